// round 1
// baseline (speedup 1.0000x reference)
#include <cuda_runtime.h>
#include <math.h>

#define PI_F 3.14159265358979323846f

// ---------------- persistent scratch (static __device__, no allocation) ----
static __device__ float  g_T [256*272*128];   // [b][row<136:Tr, >=136:Ti][128]
static __device__ float  g_Yb[256*136*272];   // [b][u][col<136:Yr, >=136:Yi]
static __device__ float2 g_H [64*4*136*136];  // [c][r][kh][kw]
static __device__ float  g_Z [1024*272*136];  // [(b*4+r)][row<136:Zr,>=136:Zi][136]
static __device__ float  g_U [1024*256*136];  // [(b*4+r)][row<128:Ur,>=128:Ui][136]
static __device__ float  g_MB1[272*128];
static __device__ float  g_MB2[256*272];
static __device__ float  g_MI1[256*272];
static __device__ float  g_MI2[272*128];

__device__ __forceinline__ float2 cmulf(float2 a, float2 b){
  return make_float2(a.x*b.x - a.y*b.y, a.x*b.y + a.y*b.x);
}

// Folded DFT matrix entries: y[i] = x[(i-4) mod 128] collapses 136->128 columns.
// Returns (sum cos, sum -sin) of 2*pi*u*i/136 over contributing i.
__device__ __forceinline__ void fold_cs(int u, int ip, float &sumc, float &sumns){
  sumc = 0.f; sumns = 0.f;
  int iv[3]; int n = 0;
  iv[n++] = ip + 4;
  if (ip >= 124) iv[n++] = ip - 124;
  if (ip <= 3)   iv[n++] = ip + 132;
  for (int t = 0; t < n; t++){
    int m = (u * iv[t]) % 136;
    float s, c;
    sincosf((2.f*PI_F/136.f) * (float)m, &s, &c);
    sumc += c; sumns -= s;
  }
}

// ---------------- constant-matrix builders --------------------------------
__global__ void k_MB1(){
  int idx = blockIdx.x*blockDim.x + threadIdx.x;
  if (idx >= 272*128) return;
  int col = idx % 128, row = idx / 128;
  int u = (row < 136) ? row : row - 136;
  float sc, sn; fold_cs(u, col, sc, sn);
  g_MB1[idx] = (row < 136) ? sc : sn;          // Tr rows: cos, Ti rows: -sin
}

__global__ void k_MB2(){
  int idx = blockIdx.x*blockDim.x + threadIdx.x;
  if (idx >= 256*272) return;
  int col = idx % 272, k = idx / 272;
  int v  = (col < 136) ? col : col - 136;
  int jp = (k < 128) ? k : k - 128;
  float sc, sn; fold_cs(v, jp, sc, sn);        // sc = Ctil, sn = Stil
  float val;
  if (col < 136) val = (k < 128) ? sc : -sn;   // Yr = Tr*C^T - Ti*S^T
  else           val = (k < 128) ? sn :  sc;   // Yi = Tr*S^T + Ti*C^T
  g_MB2[idx] = val;
}

__global__ void k_MI1(){
  int idx = blockIdx.x*blockDim.x + threadIdx.x;
  if (idx >= 256*272) return;
  int k = idx % 272, row = idx / 272;
  int m   = (row & 127) + 4;                   // cropped output row m in [4,131]
  int kap = (k < 136) ? k : k - 136;
  int a = (m * kap) % 136;
  float s, c; sincosf((2.f*PI_F/136.f)*(float)a, &s, &c);
  float val;
  if (row < 128) val = (k < 136) ?  c : -s;    // Ur = Er*Zr - Ei*Zi
  else           val = (k < 136) ?  s :  c;    // Ui = Ei*Zr + Er*Zi
  g_MI1[idx] = val;
}

__global__ void k_MI2(){
  int idx = blockIdx.x*blockDim.x + threadIdx.x;
  if (idx >= 272*128) return;
  int nn = idx % 128, k = idx / 128;
  int mp  = nn + 4;
  int kap = (k < 136) ? k : k - 136;
  int a = (mp * kap) % 136;
  float s, c; sincosf((2.f*PI_F/136.f)*(float)a, &s, &c);
  g_MI2[idx] = (k < 136) ? c : -s;             // P = Ur*Er^T - Ui*Ei^T (real part)
}

// ---------------- per-channel polyphase transfer functions H_r ------------
__global__ void k_H(const float* __restrict__ w, const float* __restrict__ bias){
  int idx = blockIdx.x*blockDim.x + threadIdx.x;
  if (idx >= 64*136*136) return;
  int kw = idx % 136; int t = idx / 136; int kh = t % 136; int c = t / 136;
  float beta = 1.f/(1.f + expf(9.f - bias[c])) + 1e-5f;

  // base phasors e^{-2*pi*i*k*(a-2)/272}
  float2 bh[5], bw[5];
  #pragma unroll
  for (int a = 0; a < 5; a++){
    float s, cc;
    sincosf((2.f*PI_F/272.f)*(float)(kh*(a-2)), &s, &cc);
    bh[a] = make_float2(cc, -s);
    sincosf((2.f*PI_F/272.f)*(float)(kw*(a-2)), &s, &cc);
    bw[a] = make_float2(cc, -s);
  }
  // row sums for both column aliases q in {0,1}
  float2 S0[5], S1[5];
  #pragma unroll
  for (int a = 0; a < 5; a++){
    float2 s0 = make_float2(0.f,0.f), s1 = make_float2(0.f,0.f);
    #pragma unroll
    for (int b = 0; b < 5; b++){
      float wv = w[c*25 + a*5 + b];
      float tx = wv*bw[b].x, ty = wv*bw[b].y;
      s0.x += tx; s0.y += ty;
      if (b & 1){ s1.x -= tx; s1.y -= ty; } else { s1.x += tx; s1.y += ty; }
    }
    S0[a] = s0; S1[a] = s1;
  }
  float sph, cph; sincosf(PI_F*(float)kh/136.f, &sph, &cph);
  float2 ph = make_float2(cph, -sph);          // e^{-i*pi*kh/136}
  float spw, cpw; sincosf(PI_F*(float)kw/136.f, &spw, &cpw);
  float2 pw = make_float2(cpw, -spw);

  float2 FB[4], G[4];
  float2 Asum = make_float2(0.f,0.f);
  float  invW = 0.f;
  #pragma unroll
  for (int p = 0; p < 2; p++){
    #pragma unroll
    for (int q = 0; q < 2; q++){
      int r = p*2+q;
      float2 fb = make_float2(0.f,0.f);
      #pragma unroll
      for (int a = 0; a < 5; a++){
        float2 S = q ? S1[a] : S0[a];
        float2 term = cmulf(bh[a], S);
        if (p && (a & 1)) { term.x = -term.x; term.y = -term.y; }
        fb.x += term.x; fb.y += term.y;
      }
      FB[r] = fb;
      float2 f1 = make_float2(1.f + (p ? -ph.x : ph.x), (p ? -ph.y : ph.y));
      float2 f2 = make_float2(1.f + (q ? -pw.x : pw.x), (q ? -pw.y : pw.y));
      float2 box = cmulf(f1, f2);
      float2 g = make_float2(fb.x + beta*box.x, -fb.y + beta*box.y); // conj(FB)+beta*Box
      G[r] = g;
      float2 ag = cmulf(fb, g);
      Asum.x += ag.x; Asum.y += ag.y;
      invW += fb.x*fb.x + fb.y*fb.y;
    }
  }
  Asum.x *= 0.25f; Asum.y *= 0.25f; invW *= 0.25f;
  float dinv = 1.f/(invW + beta);
  float2 tt = make_float2(Asum.x*dinv, Asum.y*dinv);
  float invb = 1.f/beta;
  float2 Hm[4];
  #pragma unroll
  for (int r = 0; r < 4; r++){
    float2 cf = make_float2(FB[r].x, -FB[r].y);
    float2 ct = cmulf(cf, tt);
    Hm[r] = make_float2((G[r].x - ct.x)*invb, (G[r].y - ct.y)*invb);
  }
  const float scale = 1.f/73984.f;             // 1/(4*136^2): ifft272 norm folded in
  float2 twh = make_float2(ph.x, -ph.y);       // e^{+i*pi*kh/136}
  float2 tww = make_float2(pw.x, -pw.y);
  #pragma unroll
  for (int rh = 0; rh < 2; rh++){
    #pragma unroll
    for (int rw = 0; rw < 2; rw++){
      float2 s = make_float2(0.f,0.f);
      #pragma unroll
      for (int p = 0; p < 2; p++)
        #pragma unroll
        for (int q = 0; q < 2; q++){
          float sg = ((p*rh + q*rw) & 1) ? -1.f : 1.f;
          s.x += sg*Hm[p*2+q].x; s.y += sg*Hm[p*2+q].y;
        }
      float2 tw = make_float2(1.f, 0.f);
      if (rh) tw = twh;
      if (rw) tw = cmulf(tw, tww);
      float2 o = cmulf(s, tw);
      o.x *= scale; o.y *= scale;
      g_H[((c*4 + rh*2 + rw)*136 + kh)*136 + kw] = o;
    }
  }
}

// ---------------- elementwise Z_r = Y * H_r (complex) ---------------------
__global__ void k_Z(){
  int idx = blockIdx.x*blockDim.x + threadIdx.x;
  if (idx >= 256*136*136) return;
  int kw = idx % 136; int t = idx / 136; int kh = t % 136; int b = t / 136;
  int c = b & 63;
  const float* Y = g_Yb + b*(136*272) + kh*272;
  float yr = Y[kw], yi = Y[136+kw];
  #pragma unroll
  for (int r = 0; r < 4; r++){
    float2 h = g_H[((c*4+r)*136 + kh)*136 + kw];
    float zr = yr*h.x - yi*h.y;
    float zi = yr*h.y + yi*h.x;
    float* Z = g_Z + (b*4+r)*(272*136);
    Z[kh*136 + kw]       = zr;
    Z[(136+kh)*136 + kw] = zi;
  }
}

// ---------------- tiled fp32 GEMM, stage-specialized ----------------------
// STAGE 0: T = MB1(272x128) * x_b(128x128)                 z in [0,256)
// STAGE 1: Y = [Tr|Ti](136x256) * MB2(256x272)             z in [0,256)
// STAGE 2: U = MI1(256x272) * Z(272x136)                   z in [0,1024)
// STAGE 3: out = [Ur|Ui](128x272) * MI2(272x128) -> d_out  z in [0,1024)
template<int STAGE>
__global__ __launch_bounds__(256) void gemm_k(const float* __restrict__ xin,
                                              float* __restrict__ outp)
{
  constexpr int M = (STAGE==0)?272 : (STAGE==1)?136 : (STAGE==2)?256 : 128;
  constexpr int N = (STAGE==0)?128 : (STAGE==1)?272 : (STAGE==2)?136 : 128;
  constexpr int K = (STAGE==0)?128 : (STAGE==1)?256 : 272;

  const int z = blockIdx.z;
  const float* A;
  const float* B;
  float* C = 0;
  if constexpr (STAGE==0){ A = g_MB1;             B = xin + z*(128*128); C = g_T  + z*(272*128); }
  if constexpr (STAGE==1){ A = g_T + z*(272*128); B = g_MB2;             C = g_Yb + z*(136*272); }
  if constexpr (STAGE==2){ A = g_MI1;             B = g_Z + z*(272*136); C = g_U  + z*(256*136); }
  if constexpr (STAGE==3){ A = g_U + z*(256*136); B = g_MI2; }

  __shared__ __align__(16) float As[64*16];   // [m][k]
  __shared__ __align__(16) float Bs[16*64];   // [k][n]

  const int tid = threadIdx.x;
  const int tx = tid & 15, ty = tid >> 4;
  const int m0 = blockIdx.y*64, n0 = blockIdx.x*64;

  float acc[4][4] = {};

  for (int kk = 0; kk < K; kk += 16){
    #pragma unroll
    for (int i = 0; i < 4; i++){
      int e = tid + i*256;
      int kl = e & 15, ml = e >> 4;
      int gm = m0 + ml, gk = kk + kl;
      float v = 0.f;
      if (gm < M){
        if constexpr (STAGE==0)      v = A[gm*128 + gk];
        else if constexpr (STAGE==1) v = (gk<128) ? A[gm*128+gk] : A[(136+gm)*128 + gk-128];
        else if constexpr (STAGE==2) v = A[gm*272 + gk];
        else                         v = (gk<136) ? A[gm*136+gk] : A[(128+gm)*136 + gk-136];
      }
      As[ml*16 + kl] = v;
    }
    #pragma unroll
    for (int i = 0; i < 4; i++){
      int e = tid + i*256;
      int nl = e & 63, kl = e >> 6;
      int gn = n0 + nl, gk = kk + kl;
      float v = 0.f;
      if (gn < N){
        if constexpr (STAGE==0)      v = B[gk*128 + gn];
        else if constexpr (STAGE==1) v = B[gk*272 + gn];
        else if constexpr (STAGE==2) v = B[gk*136 + gn];
        else                         v = B[gk*128 + gn];
      }
      Bs[kl*64 + nl] = v;
    }
    __syncthreads();
    #pragma unroll
    for (int k = 0; k < 16; k++){
      float a0 = As[(ty*4+0)*16 + k];
      float a1 = As[(ty*4+1)*16 + k];
      float a2 = As[(ty*4+2)*16 + k];
      float a3 = As[(ty*4+3)*16 + k];
      float4 b = *reinterpret_cast<const float4*>(&Bs[k*64 + tx*4]);
      acc[0][0] += a0*b.x; acc[0][1] += a0*b.y; acc[0][2] += a0*b.z; acc[0][3] += a0*b.w;
      acc[1][0] += a1*b.x; acc[1][1] += a1*b.y; acc[1][2] += a1*b.z; acc[1][3] += a1*b.w;
      acc[2][0] += a2*b.x; acc[2][1] += a2*b.y; acc[2][2] += a2*b.z; acc[2][3] += a2*b.w;
      acc[3][0] += a3*b.x; acc[3][1] += a3*b.y; acc[3][2] += a3*b.z; acc[3][3] += a3*b.w;
    }
    __syncthreads();
  }

  #pragma unroll
  for (int i = 0; i < 4; i++){
    int gm = m0 + ty*4 + i;
    if (gm >= M) continue;
    #pragma unroll
    for (int j = 0; j < 4; j++){
      int gn = n0 + tx*4 + j;
      if (gn >= N) continue;
      if constexpr (STAGE==3){
        int b = z >> 2, r = z & 3;
        outp[b*65536 + (2*gm + (r>>1))*256 + 2*gn + (r&1)] = acc[i][j];
      } else {
        constexpr int ldc = (STAGE==0)?128 : (STAGE==1)?272 : 136;
        C[gm*ldc + gn] = acc[i][j];
      }
    }
  }
}

// ---------------- launch ---------------------------------------------------
extern "C" void kernel_launch(void* const* d_in, const int* in_sizes, int n_in,
                              void* d_out, int out_size)
{
  const float* x = (const float*)d_in[0];
  const float* w = (const float*)(n_in > 1 ? d_in[1] : d_in[0]);
  const float* bias = (const float*)(n_in > 2 ? d_in[2] : d_in[0]);
  for (int i = 0; i < n_in; i++){
    if (in_sizes[i] == 4*64*128*128) x = (const float*)d_in[i];
    else if (in_sizes[i] == 64*25)   w = (const float*)d_in[i];
    else if (in_sizes[i] == 64)      bias = (const float*)d_in[i];
  }
  float* out = (float*)d_out;

  k_MB1<<<(272*128+255)/256, 256>>>();
  k_MB2<<<(256*272+255)/256, 256>>>();
  k_MI1<<<(256*272+255)/256, 256>>>();
  k_MI2<<<(272*128+255)/256, 256>>>();
  k_H  <<<(64*136*136+255)/256, 256>>>(w, bias);

  gemm_k<0><<<dim3(2,5,256),  256>>>(x, out);   // T  = MB1 * x
  gemm_k<1><<<dim3(5,3,256),  256>>>(x, out);   // Y  = T * MB2
  k_Z  <<<(256*136*136+255)/256, 256>>>();      // Z  = Y .* H_r
  gemm_k<2><<<dim3(3,4,1024), 256>>>(x, out);   // U  = MI1 * Z
  gemm_k<3><<<dim3(2,2,1024), 256>>>(x, out);   // out = [Ur|Ui] * MI2 (interleaved store)
}

// round 2
// speedup vs baseline: 2.0379x; 2.0379x over previous
#include <cuda_runtime.h>
#include <math.h>

#define PI_F 3.14159265358979323846f

// ---------------- persistent scratch (static __device__, no allocation) ----
static __device__ float  g_T [256*272*128];   // [b][row<136:Tr,>=136:Ti][j 128]
static __device__ float  g_Yb[256*136*138];   // [b][u][n<69:Yr(v=n), >=69:Yi]
static __device__ float2 g_H [64*4*136*69];   // [c*4+r][kh][kw<69]
static __device__ float  g_Z [256*272*276];   // [b][row<136:Zr,>=136:Zi][r*69+kw]
static __device__ float  g_U [256*256*276];   // [b][row<128:Ur,>=128:Ui][r*69+v]
static __device__ float  g_MB1[272*128];
static __device__ float  g_MB2[256*138];
static __device__ float  g_MI1[256*272];
static __device__ float  g_MI2[144*128];
static __device__ float2 g_tw[272];           // (cos, sin) of 2*pi*i/272

__device__ __forceinline__ float2 cmulf(float2 a, float2 b){
  return make_float2(a.x*b.x - a.y*b.y, a.x*b.y + a.y*b.x);
}

// packed fp32x2 FMA (sm_103a FFMA2) and broadcast-pack helpers
__device__ __forceinline__ unsigned long long ffma2(unsigned long long a,
                                                    unsigned long long b,
                                                    unsigned long long c){
  unsigned long long d;
  asm("fma.rn.f32x2 %0, %1, %2, %3;" : "=l"(d) : "l"(a), "l"(b), "l"(c));
  return d;
}
__device__ __forceinline__ unsigned long long dup2(float v){
  unsigned long long d; unsigned int u = __float_as_uint(v);
  asm("mov.b64 %0, {%1, %1};" : "=l"(d) : "r"(u));
  return d;
}

// Folded DFT entries: wrap-pad y[i]=x[(i-4) mod 128] collapses 136->128 cols.
__device__ __forceinline__ void fold_cs(int u, int ip, float &sumc, float &sumns){
  sumc = 0.f; sumns = 0.f;
  int iv[3]; int n = 0;
  iv[n++] = ip + 4;
  if (ip >= 124) iv[n++] = ip - 124;
  if (ip <= 3)   iv[n++] = ip + 132;
  for (int t = 0; t < n; t++){
    int m = (u * iv[t]) % 136;
    float s, c;
    sincosf((2.f*PI_F/136.f) * (float)m, &s, &c);
    sumc += c; sumns -= s;
  }
}

// ---------------- builders -------------------------------------------------
__global__ void k_tw(){
  int i = threadIdx.x;
  if (i < 272){
    float s, c; sincosf((2.f*PI_F/272.f)*(float)i, &s, &c);
    g_tw[i] = make_float2(c, s);
  }
}

__global__ void k_MB1(){
  int idx = blockIdx.x*blockDim.x + threadIdx.x;
  if (idx >= 272*128) return;
  int col = idx % 128, row = idx / 128;
  int u = (row < 136) ? row : row - 136;
  float sc, sn; fold_cs(u, col, sc, sn);
  g_MB1[idx] = (row < 136) ? sc : sn;
}

__global__ void k_MB2(){
  int idx = blockIdx.x*blockDim.x + threadIdx.x;
  if (idx >= 256*138) return;
  int n = idx % 138, k = idx / 138;
  int v  = (n < 69) ? n : n - 69;
  int jp = (k < 128) ? k : k - 128;
  float sc, sn; fold_cs(v, jp, sc, sn);
  float val;
  if (n < 69) val = (k < 128) ? sc : -sn;    // Yr
  else        val = (k < 128) ? sn :  sc;    // Yi
  g_MB2[idx] = val;
}

__global__ void k_MI1(){
  int idx = blockIdx.x*blockDim.x + threadIdx.x;
  if (idx >= 256*272) return;
  int k = idx % 272, row = idx / 272;
  int m   = (row & 127) + 4;
  int kap = (k < 136) ? k : k - 136;
  int a = (m * kap) % 136;
  float s, c; sincosf((2.f*PI_F/136.f)*(float)a, &s, &c);
  float val;
  if (row < 128) val = (k < 136) ?  c : -s;  // Ur
  else           val = (k < 136) ?  s :  c;  // Ui
  g_MI1[idx] = val;
}

// Hermitian-folded column DFT: out[m,n'] = sum_{v=0..68} mult(v)*(Ur cos - Ui sin)
__global__ void k_MI2(){
  int idx = blockIdx.x*blockDim.x + threadIdx.x;
  if (idx >= 144*128) return;
  int n = idx & 127, kap = idx >> 7;
  int part = (kap >= 72);
  int v = kap - (part ? 72 : 0);
  float val = 0.f;
  if (v < 69){
    float mult = (v == 0 || v == 68) ? 1.f : 2.f;
    int a = ((n + 4) * v) % 136;
    float s, c; sincosf((2.f*PI_F/136.f)*(float)a, &s, &c);
    val = part ? (-mult * s) : (mult * c);
  }
  g_MI2[idx] = val;
}

// ---------------- per-channel polyphase transfer functions (kw<69) --------
__global__ void k_H(const float* __restrict__ w, const float* __restrict__ bias){
  int idx = blockIdx.x*blockDim.x + threadIdx.x;
  if (idx >= 64*136*69) return;
  int kw = idx % 69; int t = idx / 69; int kh = t % 136; int c = t / 136;
  float beta = 1.f/(1.f + expf(9.f - bias[c])) + 1e-5f;

  float2 bh[5], bw[5];
  #pragma unroll
  for (int a = 0; a < 5; a++){
    int mh = ((kh*(a-2)) % 272 + 272) % 272;
    float2 th = g_tw[mh]; bh[a] = make_float2(th.x, -th.y);
    int mw = ((kw*(a-2)) % 272 + 272) % 272;
    float2 tw = g_tw[mw]; bw[a] = make_float2(tw.x, -tw.y);
  }
  float2 S0[5], S1[5];
  #pragma unroll
  for (int a = 0; a < 5; a++){
    float2 s0 = make_float2(0.f,0.f), s1 = make_float2(0.f,0.f);
    #pragma unroll
    for (int b = 0; b < 5; b++){
      float wv = w[c*25 + a*5 + b];
      float tx = wv*bw[b].x, ty = wv*bw[b].y;
      s0.x += tx; s0.y += ty;
      if (b & 1){ s1.x -= tx; s1.y -= ty; } else { s1.x += tx; s1.y += ty; }
    }
    S0[a] = s0; S1[a] = s1;
  }
  float2 tph = g_tw[kh];
  float2 ph = make_float2(tph.x, -tph.y);   // e^{-i*pi*kh/136}
  float2 tpw = g_tw[kw];
  float2 pw = make_float2(tpw.x, -tpw.y);

  float2 FB[4], G[4];
  float2 Asum = make_float2(0.f,0.f);
  float  invW = 0.f;
  #pragma unroll
  for (int p = 0; p < 2; p++){
    #pragma unroll
    for (int q = 0; q < 2; q++){
      int r = p*2+q;
      float2 fb = make_float2(0.f,0.f);
      #pragma unroll
      for (int a = 0; a < 5; a++){
        float2 S = q ? S1[a] : S0[a];
        float2 term = cmulf(bh[a], S);
        if (p && (a & 1)) { term.x = -term.x; term.y = -term.y; }
        fb.x += term.x; fb.y += term.y;
      }
      FB[r] = fb;
      float2 f1 = make_float2(1.f + (p ? -ph.x : ph.x), (p ? -ph.y : ph.y));
      float2 f2 = make_float2(1.f + (q ? -pw.x : pw.x), (q ? -pw.y : pw.y));
      float2 box = cmulf(f1, f2);
      float2 g = make_float2(fb.x + beta*box.x, -fb.y + beta*box.y);
      G[r] = g;
      float2 ag = cmulf(fb, g);
      Asum.x += ag.x; Asum.y += ag.y;
      invW += fb.x*fb.x + fb.y*fb.y;
    }
  }
  Asum.x *= 0.25f; Asum.y *= 0.25f; invW *= 0.25f;
  float dinv = 1.f/(invW + beta);
  float2 tt = make_float2(Asum.x*dinv, Asum.y*dinv);
  float invb = 1.f/beta;
  float2 Hm[4];
  #pragma unroll
  for (int r = 0; r < 4; r++){
    float2 cf = make_float2(FB[r].x, -FB[r].y);
    float2 ct = cmulf(cf, tt);
    Hm[r] = make_float2((G[r].x - ct.x)*invb, (G[r].y - ct.y)*invb);
  }
  const float scale = 1.f/73984.f;
  float2 twh = make_float2(ph.x, -ph.y);
  float2 tww = make_float2(pw.x, -pw.y);
  #pragma unroll
  for (int rh = 0; rh < 2; rh++){
    #pragma unroll
    for (int rw = 0; rw < 2; rw++){
      float2 s = make_float2(0.f,0.f);
      #pragma unroll
      for (int p = 0; p < 2; p++)
        #pragma unroll
        for (int q = 0; q < 2; q++){
          float sg = ((p*rh + q*rw) & 1) ? -1.f : 1.f;
          s.x += sg*Hm[p*2+q].x; s.y += sg*Hm[p*2+q].y;
        }
      float2 tw = make_float2(1.f, 0.f);
      if (rh) tw = twh;
      if (rw) tw = cmulf(tw, tww);
      float2 o = cmulf(s, tw);
      o.x *= scale; o.y *= scale;
      g_H[((c*4 + rh*2 + rw)*136 + kh)*69 + kw] = o;
    }
  }
}

// ---------------- Z_r = Y .* H_r, packed [b][row][r*69+kw] ----------------
__global__ void k_Z(){
  int idx = blockIdx.x*blockDim.x + threadIdx.x;
  if (idx >= 256*136*69) return;
  int kw = idx % 69; int t = idx / 69; int kh = t % 136; int b = t / 136;
  int c = b & 63;
  const float* Y = g_Yb + b*18768 + kh*138;
  float yr = Y[kw], yi = Y[69+kw];
  float* Zr = g_Z + b*75072 + kh*276;
  float* Zi = g_Z + b*75072 + (136+kh)*276;
  #pragma unroll
  for (int r = 0; r < 4; r++){
    float2 h = g_H[((c*4+r)*136 + kh)*69 + kw];
    Zr[r*69+kw] = yr*h.x - yi*h.y;
    Zi[r*69+kw] = yr*h.y + yi*h.x;
  }
}

// ---------------- double-buffered f32x2 GEMM -------------------------------
// STAGE 0: T (272x128) = MB1 * x_b          z=b in [0,256)
// STAGE 1: Y (136x138) = [Tr|Ti] * MB2      z=b
// STAGE 2: U (256x276) = MI1 * Z_b          z=b
// STAGE 3: out        = [Ur|Ui](128x144pad) * MI2(144x128), z=(b,r) in [0,1024)
template<int STAGE, int BM>
__global__ __launch_bounds__(256) void gemm_k(const float* __restrict__ xin,
                                              float* __restrict__ outp)
{
  constexpr int M = (STAGE==0)?272 : (STAGE==1)?136 : (STAGE==2)?256 : 128;
  constexpr int N = (STAGE==0)?128 : (STAGE==1)?138 : (STAGE==2)?276 : 128;
  constexpr int K = (STAGE==0)?128 : (STAGE==1)?256 : (STAGE==2)?272 : 144;
  constexpr int TM = BM/16;      // 8 or 4 rows per thread
  constexpr int TP = TM/2;       // row pairs
  constexpr int AR = BM/16;      // floats per thread per A tile

  __shared__ __align__(16) float As[2][16][BM];
  __shared__ __align__(16) float Bs[2][16][64];

  const int z = blockIdx.z;
  const int tid = threadIdx.x, tx = tid & 15, ty = tid >> 4;
  const int m0 = blockIdx.y*BM, n0 = blockIdx.x*64;

  auto fetchA = [&](int gm, int gk)->float{
    if constexpr (STAGE==0){
      return (gm < 272) ? g_MB1[gm*128 + gk] : 0.f;
    } else if constexpr (STAGE==1){
      if (gm >= 136) return 0.f;
      const float* T = g_T + z*34816;
      return (gk < 128) ? T[gm*128 + gk] : T[(136+gm)*128 + (gk-128)];
    } else if constexpr (STAGE==2){
      return g_MI1[gm*272 + gk];
    } else {
      int b = z >> 2, r = z & 3;
      int part = (gk >= 72);
      int v = gk - (part ? 72 : 0);
      if (v >= 69) return 0.f;
      return g_U[b*70656 + (part ? (128+gm) : gm)*276 + r*69 + v];
    }
  };
  auto fetchB = [&](int gk, int gn)->float{
    if constexpr (STAGE==0){
      return xin[z*16384 + gk*128 + gn];
    } else if constexpr (STAGE==1){
      return (gn < 138) ? g_MB2[gk*138 + gn] : 0.f;
    } else if constexpr (STAGE==2){
      return (gn < 276) ? g_Z[z*75072 + gk*276 + gn] : 0.f;
    } else {
      return g_MI2[gk*128 + gn];
    }
  };
  auto storeC = [&](int gm, int gn, float v){
    if constexpr (STAGE==0){ if (gm < 272) g_T[z*34816 + gm*128 + gn] = v; }
    else if constexpr (STAGE==1){ if (gm < 136 && gn < 138) g_Yb[z*18768 + gm*138 + gn] = v; }
    else if constexpr (STAGE==2){ if (gn < 276) g_U[z*70656 + gm*276 + gn] = v; }
    else {
      int b = z >> 2, r = z & 3;
      outp[b*65536 + (2*gm + (r>>1))*256 + 2*gn + (r&1)] = v;
    }
  };

  float ra[AR]; float rb[4];
  auto loadAB = [&](int kk){
    #pragma unroll
    for (int i = 0; i < AR/4; i++){
      int f = tid + i*256;
      int m = f >> 2, kg = (f & 3)*4;
      int gm = m0 + m;
      #pragma unroll
      for (int d = 0; d < 4; d++) ra[i*4+d] = fetchA(gm, kk + kg + d);
    }
    int kb = tid >> 4, nx = (tid & 15)*4;
    #pragma unroll
    for (int d = 0; d < 4; d++) rb[d] = fetchB(kk + kb, n0 + nx + d);
  };
  auto storeAB = [&](int buf){
    #pragma unroll
    for (int i = 0; i < AR/4; i++){
      int f = tid + i*256;
      int m = f >> 2, kg = (f & 3)*4;
      #pragma unroll
      for (int d = 0; d < 4; d++) As[buf][kg+d][m] = ra[i*4+d];
    }
    int kb = tid >> 4, nx = (tid & 15)*4;
    #pragma unroll
    for (int d = 0; d < 4; d++) Bs[buf][kb][nx+d] = rb[d];
  };

  unsigned long long acc[TP][4] = {};

  constexpr int NT = K/16;
  loadAB(0); storeAB(0); __syncthreads();

  #pragma unroll 1
  for (int t = 0; t < NT; t++){
    int buf = t & 1;
    if (t + 1 < NT) loadAB((t+1)*16);
    #pragma unroll
    for (int k = 0; k < 16; k++){
      unsigned long long ap[TP];
      if constexpr (TP == 4){
        ulonglong2 v0 = *reinterpret_cast<const ulonglong2*>(&As[buf][k][ty*TM]);
        ulonglong2 v1 = *reinterpret_cast<const ulonglong2*>(&As[buf][k][ty*TM+4]);
        ap[0]=v0.x; ap[1]=v0.y; ap[2]=v1.x; ap[3]=v1.y;
      } else {
        ulonglong2 v0 = *reinterpret_cast<const ulonglong2*>(&As[buf][k][ty*TM]);
        ap[0]=v0.x; ap[1]=v0.y;
      }
      float4 bq = *reinterpret_cast<const float4*>(&Bs[buf][k][tx*4]);
      unsigned long long bd0 = dup2(bq.x), bd1 = dup2(bq.y);
      unsigned long long bd2 = dup2(bq.z), bd3 = dup2(bq.w);
      #pragma unroll
      for (int p = 0; p < TP; p++){
        acc[p][0] = ffma2(ap[p], bd0, acc[p][0]);
        acc[p][1] = ffma2(ap[p], bd1, acc[p][1]);
        acc[p][2] = ffma2(ap[p], bd2, acc[p][2]);
        acc[p][3] = ffma2(ap[p], bd3, acc[p][3]);
      }
    }
    if (t + 1 < NT){ storeAB(buf ^ 1); __syncthreads(); }
  }

  union { unsigned long long u; float2 f; } pun;
  #pragma unroll
  for (int p = 0; p < TP; p++){
    int gmA = m0 + ty*TM + 2*p;
    #pragma unroll
    for (int j = 0; j < 4; j++){
      int gn = n0 + tx*4 + j;
      pun.u = acc[p][j];
      storeC(gmA,     gn, pun.f.x);
      storeC(gmA + 1, gn, pun.f.y);
    }
  }
}

// ---------------- launch ----------------------------------------------------
extern "C" void kernel_launch(void* const* d_in, const int* in_sizes, int n_in,
                              void* d_out, int out_size)
{
  const float* x = (const float*)d_in[0];
  const float* w = (const float*)(n_in > 1 ? d_in[1] : d_in[0]);
  const float* bias = (const float*)(n_in > 2 ? d_in[2] : d_in[0]);
  for (int i = 0; i < n_in; i++){
    if (in_sizes[i] == 4*64*128*128) x = (const float*)d_in[i];
    else if (in_sizes[i] == 64*25)   w = (const float*)d_in[i];
    else if (in_sizes[i] == 64)      bias = (const float*)d_in[i];
  }
  float* out = (float*)d_out;

  k_tw <<<1, 272>>>();
  k_MB1<<<(272*128+255)/256, 256>>>();
  k_MB2<<<(256*138+255)/256, 256>>>();
  k_MI1<<<(256*272+255)/256, 256>>>();
  k_MI2<<<(144*128+255)/256, 256>>>();
  k_H  <<<(64*136*69+255)/256, 256>>>(w, bias);

  gemm_k<0,64> <<<dim3(2,5,256),  256>>>(x, out);  // T = MB1 * x
  gemm_k<1,64> <<<dim3(3,3,256),  256>>>(x, out);  // Y = T * MB2 (half spectrum)
  k_Z  <<<(256*136*69+255)/256, 256>>>();          // Z = Y .* H_r
  gemm_k<2,128><<<dim3(5,2,256),  256>>>(x, out);  // U = MI1 * Z
  gemm_k<3,128><<<dim3(2,1,1024), 256>>>(x, out);  // out via Hermitian-folded DFT
}

// round 4
// speedup vs baseline: 2.3269x; 1.1418x over previous
#include <cuda_runtime.h>
#include <cuda_bf16.h>
#include <math.h>
#include <cstdint>

#define PI_F 3.14159265358979323846f

// ===================== helpers ==============================================
__device__ __forceinline__ uint32_t smem_u32(const void* p){
  uint32_t a;
  asm("{ .reg .u64 t; cvta.to.shared.u64 t, %1; cvt.u32.u64 %0, t; }"
      : "=r"(a) : "l"(p));
  return a;
}
__device__ __forceinline__ void ldsm_x4(uint32_t &r0, uint32_t &r1,
                                        uint32_t &r2, uint32_t &r3, uint32_t addr){
  asm volatile("ldmatrix.sync.aligned.m8n8.x4.shared.b16 {%0,%1,%2,%3}, [%4];"
               : "=r"(r0), "=r"(r1), "=r"(r2), "=r"(r3) : "r"(addr));
}
__device__ __forceinline__ void ldsm_x2(uint32_t &r0, uint32_t &r1, uint32_t addr){
  asm volatile("ldmatrix.sync.aligned.m8n8.x2.shared.b16 {%0,%1}, [%2];"
               : "=r"(r0), "=r"(r1) : "r"(addr));
}
__device__ __forceinline__ void mma_bf16(float d[4], const uint32_t a[4],
                                         const uint32_t b[2]){
  asm volatile("mma.sync.aligned.m16n8k16.row.col.f32.bf16.bf16.f32 "
    "{%0,%1,%2,%3}, {%4,%5,%6,%7}, {%8,%9}, {%0,%1,%2,%3};"
    : "+f"(d[0]), "+f"(d[1]), "+f"(d[2]), "+f"(d[3])
    : "r"(a[0]), "r"(a[1]), "r"(a[2]), "r"(a[3]), "r"(b[0]), "r"(b[1]));
}
__device__ __forceinline__ unsigned long long ffma2(unsigned long long a,
                                                    unsigned long long b,
                                                    unsigned long long c){
  unsigned long long d;
  asm("fma.rn.f32x2 %0, %1, %2, %3;" : "=l"(d) : "l"(a), "l"(b), "l"(c));
  return d;
}
__device__ __forceinline__ unsigned long long dup2(float v){
  unsigned long long d; unsigned int u = __float_as_uint(v);
  asm("mov.b64 %0, {%1, %1};" : "=l"(d) : "r"(u));
  return d;
}
__device__ __forceinline__ float2 cmulf(float2 a, float2 b){
  return make_float2(a.x*b.x - a.y*b.y, a.x*b.y + a.y*b.x);
}
__device__ __forceinline__ void split_bf(float f, __nv_bfloat16 &h, __nv_bfloat16 &l){
  h = __float2bfloat16(f);
  l = __float2bfloat16(f - __bfloat162float(h));
}
__device__ __forceinline__ void fold_cs(int u, int ip, float &sumc, float &sumns){
  sumc = 0.f; sumns = 0.f;
  int iv[3]; int n = 0;
  iv[n++] = ip + 4;
  if (ip >= 124) iv[n++] = ip - 124;
  if (ip <= 3)   iv[n++] = ip + 132;
  for (int t = 0; t < n; t++){
    int m = (u * iv[t]) % 136;
    float s, c;
    sincosf((2.f*PI_F/136.f) * (float)m, &s, &c);
    sumc += c; sumns -= s;
  }
}

// ===================== persistent scratch ===================================
static __device__ float  g_T [256*272*128];
static __device__ float  g_Yt[256*138*136];                 // [b][n 138][u 136]
static __device__ float2 g_H [64*4*69*136];                 // [c][r][kw][kh]
static __device__ __align__(16) __nv_bfloat16 g_Zh[256*276*272];
static __device__ __align__(16) __nv_bfloat16 g_Zl[256*276*272];
static __device__ __align__(16) __nv_bfloat16 g_UAh[1024*128*144];
static __device__ __align__(16) __nv_bfloat16 g_UAl[1024*128*144];
static __device__ float  g_MB1[272*128];
static __device__ float  g_MB2[256*138];
static __device__ __align__(16) __nv_bfloat16 g_MI1h[256*272];
static __device__ __align__(16) __nv_bfloat16 g_MI1l[256*272];
static __device__ __align__(16) __nv_bfloat16 g_MI2h[128*144];
static __device__ __align__(16) __nv_bfloat16 g_MI2l[128*144];
static __device__ float2 g_tw[272];

// ===================== builders =============================================
__global__ void k_tw(){
  int i = threadIdx.x;
  if (i < 272){
    float s, c; sincosf((2.f*PI_F/272.f)*(float)i, &s, &c);
    g_tw[i] = make_float2(c, s);
  }
}
__global__ void k_MB1(){
  int idx = blockIdx.x*blockDim.x + threadIdx.x;
  if (idx >= 272*128) return;
  int col = idx % 128, row = idx / 128;
  int u = (row < 136) ? row : row - 136;
  float sc, sn; fold_cs(u, col, sc, sn);
  g_MB1[idx] = (row < 136) ? sc : sn;
}
__global__ void k_MB2(){
  int idx = blockIdx.x*blockDim.x + threadIdx.x;
  if (idx >= 256*138) return;
  int n = idx % 138, k = idx / 138;
  int v  = (n < 69) ? n : n - 69;
  int jp = (k < 128) ? k : k - 128;
  float sc, sn; fold_cs(v, jp, sc, sn);
  float val;
  if (n < 69) val = (k < 128) ? sc : -sn;
  else        val = (k < 128) ? sn :  sc;
  g_MB2[idx] = val;
}
__global__ void k_MI1b(){
  int idx = blockIdx.x*blockDim.x + threadIdx.x;
  if (idx >= 256*272) return;
  int k = idx % 272, row = idx / 272;
  int m   = (row & 127) + 4;
  int kap = (k < 136) ? k : k - 136;
  int a = (m * kap) % 136;
  float s, c; sincosf((2.f*PI_F/136.f)*(float)a, &s, &c);
  float val;
  if (row < 128) val = (k < 136) ?  c : -s;
  else           val = (k < 136) ?  s :  c;
  split_bf(val, g_MI1h[idx], g_MI1l[idx]);
}
__global__ void k_MI2b(){
  int idx = blockIdx.x*blockDim.x + threadIdx.x;
  if (idx >= 128*144) return;
  int kap = idx % 144, n = idx / 144;
  int part = (kap >= 72);
  int v = kap - (part ? 72 : 0);
  float val = 0.f;
  if (v < 69){
    float mult = (v == 0 || v == 68) ? 1.f : 2.f;
    int a = ((n + 4) * v) % 136;
    float s, c; sincosf((2.f*PI_F/136.f)*(float)a, &s, &c);
    val = part ? (-mult * s) : (mult * c);
  }
  split_bf(val, g_MI2h[idx], g_MI2l[idx]);
}

__global__ void k_H(const float* __restrict__ w, const float* __restrict__ bias){
  int idx = blockIdx.x*blockDim.x + threadIdx.x;
  if (idx >= 64*136*69) return;
  int kw = idx % 69; int t = idx / 69; int kh = t % 136; int c = t / 136;
  float beta = 1.f/(1.f + expf(9.f - bias[c])) + 1e-5f;

  float2 bh[5], bw[5];
  #pragma unroll
  for (int a = 0; a < 5; a++){
    int mh = ((kh*(a-2)) % 272 + 272) % 272;
    float2 th = g_tw[mh]; bh[a] = make_float2(th.x, -th.y);
    int mw = ((kw*(a-2)) % 272 + 272) % 272;
    float2 tw = g_tw[mw]; bw[a] = make_float2(tw.x, -tw.y);
  }
  float2 S0[5], S1[5];
  #pragma unroll
  for (int a = 0; a < 5; a++){
    float2 s0 = make_float2(0.f,0.f), s1 = make_float2(0.f,0.f);
    #pragma unroll
    for (int b = 0; b < 5; b++){
      float wv = w[c*25 + a*5 + b];
      float tx = wv*bw[b].x, ty = wv*bw[b].y;
      s0.x += tx; s0.y += ty;
      if (b & 1){ s1.x -= tx; s1.y -= ty; } else { s1.x += tx; s1.y += ty; }
    }
    S0[a] = s0; S1[a] = s1;
  }
  float2 tph = g_tw[kh];
  float2 ph = make_float2(tph.x, -tph.y);
  float2 tpw = g_tw[kw];
  float2 pw = make_float2(tpw.x, -tpw.y);

  float2 FB[4], G[4];
  float2 Asum = make_float2(0.f,0.f);
  float  invW = 0.f;
  #pragma unroll
  for (int p = 0; p < 2; p++){
    #pragma unroll
    for (int q = 0; q < 2; q++){
      int r = p*2+q;
      float2 fb = make_float2(0.f,0.f);
      #pragma unroll
      for (int a = 0; a < 5; a++){
        float2 S = q ? S1[a] : S0[a];
        float2 term = cmulf(bh[a], S);
        if (p && (a & 1)) { term.x = -term.x; term.y = -term.y; }
        fb.x += term.x; fb.y += term.y;
      }
      FB[r] = fb;
      float2 f1 = make_float2(1.f + (p ? -ph.x : ph.x), (p ? -ph.y : ph.y));
      float2 f2 = make_float2(1.f + (q ? -pw.x : pw.x), (q ? -pw.y : pw.y));
      float2 box = cmulf(f1, f2);
      float2 g = make_float2(fb.x + beta*box.x, -fb.y + beta*box.y);
      G[r] = g;
      float2 ag = cmulf(fb, g);
      Asum.x += ag.x; Asum.y += ag.y;
      invW += fb.x*fb.x + fb.y*fb.y;
    }
  }
  Asum.x *= 0.25f; Asum.y *= 0.25f; invW *= 0.25f;
  float dinv = 1.f/(invW + beta);
  float2 tt = make_float2(Asum.x*dinv, Asum.y*dinv);
  float invb = 1.f/beta;
  float2 Hm[4];
  #pragma unroll
  for (int r = 0; r < 4; r++){
    float2 cf = make_float2(FB[r].x, -FB[r].y);
    float2 ct = cmulf(cf, tt);
    Hm[r] = make_float2((G[r].x - ct.x)*invb, (G[r].y - ct.y)*invb);
  }
  const float scale = 1.f/73984.f;
  float2 twh = make_float2(ph.x, -ph.y);
  float2 tww = make_float2(pw.x, -pw.y);
  #pragma unroll
  for (int rh = 0; rh < 2; rh++){
    #pragma unroll
    for (int rw = 0; rw < 2; rw++){
      float2 s = make_float2(0.f,0.f);
      #pragma unroll
      for (int p = 0; p < 2; p++)
        #pragma unroll
        for (int q = 0; q < 2; q++){
          float sg = ((p*rh + q*rw) & 1) ? -1.f : 1.f;
          s.x += sg*Hm[p*2+q].x; s.y += sg*Hm[p*2+q].y;
        }
      float2 tw = make_float2(1.f, 0.f);
      if (rh) tw = twh;
      if (rw) tw = cmulf(tw, tww);
      float2 o = cmulf(s, tw);
      o.x *= scale; o.y *= scale;
      g_H[((c*4 + rh*2 + rw)*69 + kw)*136 + kh] = o;
    }
  }
}

// ===================== Z = Y .* H, split-bf16, K-major ======================
__global__ void k_Z(){
  int kw = blockIdx.x;             // [0,69)
  int b  = blockIdx.y;             // [0,256)
  int kh = threadIdx.x;
  if (kh >= 136) return;
  int c = b & 63;
  float yr = g_Yt[(b*138 + kw)*136 + kh];
  float yi = g_Yt[(b*138 + 69 + kw)*136 + kh];
  #pragma unroll
  for (int r = 0; r < 4; r++){
    float2 h = g_H[((c*4+r)*69 + kw)*136 + kh];
    float zr = yr*h.x - yi*h.y;
    float zi = yr*h.y + yi*h.x;
    int n = r*69 + kw;
    long base = (long)(b*276 + n)*272;
    split_bf(zr, g_Zh[base + kh],       g_Zl[base + kh]);
    split_bf(zi, g_Zh[base + 136 + kh], g_Zl[base + 136 + kh]);
  }
}

// ===================== FFMA2 GEMM (stages 0,1) ==============================
template<int STAGE>
__global__ __launch_bounds__(256) void gemm_k(const float* __restrict__ xin)
{
  constexpr int K = (STAGE==0)?128 : 256;
  constexpr int BM = 64, TM = 4, TP = 2;

  __shared__ __align__(16) float As[2][16][BM];
  __shared__ __align__(16) float Bs[2][16][64];

  const int z = blockIdx.z;
  const int tid = threadIdx.x, tx = tid & 15, ty = tid >> 4;
  const int m0 = blockIdx.y*BM, n0 = blockIdx.x*64;

  auto fetchA = [&](int gm, int gk)->float{
    if constexpr (STAGE==0){
      return (gm < 272) ? g_MB1[gm*128 + gk] : 0.f;
    } else {
      if (gm >= 136) return 0.f;
      const float* T = g_T + z*34816;
      return (gk < 128) ? T[gm*128 + gk] : T[(136+gm)*128 + (gk-128)];
    }
  };
  auto fetchB = [&](int gk, int gn)->float{
    if constexpr (STAGE==0) return xin[z*16384 + gk*128 + gn];
    else                    return (gn < 138) ? g_MB2[gk*138 + gn] : 0.f;
  };
  auto storeC = [&](int gm, int gn, float v){
    if constexpr (STAGE==0){ if (gm < 272) g_T[z*34816 + gm*128 + gn] = v; }
    else { if (gm < 136 && gn < 138) g_Yt[(z*138 + gn)*136 + gm] = v; }
  };

  float ra[4]; float rb[4];
  auto loadAB = [&](int kk){
    int m = tid >> 2, kg = (tid & 3)*4;
    int gm = m0 + m;
    #pragma unroll
    for (int d = 0; d < 4; d++) ra[d] = fetchA(gm, kk + kg + d);
    int kb = tid >> 4, nx = (tid & 15)*4;
    #pragma unroll
    for (int d = 0; d < 4; d++) rb[d] = fetchB(kk + kb, n0 + nx + d);
  };
  auto storeAB = [&](int buf){
    int m = tid >> 2, kg = (tid & 3)*4;
    #pragma unroll
    for (int d = 0; d < 4; d++) As[buf][kg+d][m] = ra[d];
    int kb = tid >> 4, nx = (tid & 15)*4;
    #pragma unroll
    for (int d = 0; d < 4; d++) Bs[buf][kb][nx+d] = rb[d];
  };

  unsigned long long acc[TP][4] = {};
  constexpr int NT = K/16;
  loadAB(0); storeAB(0); __syncthreads();

  #pragma unroll 1
  for (int t = 0; t < NT; t++){
    int buf = t & 1;
    if (t + 1 < NT) loadAB((t+1)*16);
    #pragma unroll
    for (int k = 0; k < 16; k++){
      ulonglong2 v0 = *reinterpret_cast<const ulonglong2*>(&As[buf][k][ty*TM]);
      unsigned long long ap[2] = {v0.x, v0.y};
      float4 bq = *reinterpret_cast<const float4*>(&Bs[buf][k][tx*4]);
      unsigned long long bd0 = dup2(bq.x), bd1 = dup2(bq.y);
      unsigned long long bd2 = dup2(bq.z), bd3 = dup2(bq.w);
      #pragma unroll
      for (int p = 0; p < TP; p++){
        acc[p][0] = ffma2(ap[p], bd0, acc[p][0]);
        acc[p][1] = ffma2(ap[p], bd1, acc[p][1]);
        acc[p][2] = ffma2(ap[p], bd2, acc[p][2]);
        acc[p][3] = ffma2(ap[p], bd3, acc[p][3]);
      }
    }
    if (t + 1 < NT){ storeAB(buf ^ 1); __syncthreads(); }
  }

  union { unsigned long long u; float2 f; } pun;
  #pragma unroll
  for (int p = 0; p < TP; p++){
    int gmA = m0 + ty*TM + 2*p;
    #pragma unroll
    for (int j = 0; j < 4; j++){
      int gn = n0 + tx*4 + j;
      pun.u = acc[p][j];
      storeC(gmA,     gn, pun.f.x);
      storeC(gmA + 1, gn, pun.f.y);
    }
  }
}

// ===================== HMMA split-bf16 GEMM (stages 2,3) ====================
// STAGE 2: U(256x276) = MI1(256x272) * Z_b(276x272)^T  -> g_UA split bf16
// STAGE 3: out = UA_z(128x144) * MI2(128x144)^T -> d_out interleaved
template<int STAGE>
__global__ __launch_bounds__(256) void mma_k(float* __restrict__ outp)
{
  constexpr int BN  = (STAGE==2) ? 96 : 128;
  constexpr int K   = (STAGE==2) ? 272 : 144;
  constexpr int KC  = 32, SA = 40;
  constexpr int NT4 = BN/32;            // n8 tiles per warp (3 or 4)
  constexpr int WN  = BN/4;             // warp n extent (24 or 32)

  __shared__ __align__(16) __nv_bfloat16 Ah[128*SA], Al[128*SA];
  __shared__ __align__(16) __nv_bfloat16 Bh[BN*SA],  Bl[BN*SA];

  const int tid = threadIdx.x, lane = tid & 31, wid = tid >> 5;
  const int wm = wid & 1, wn = wid >> 1;

  int b = 0, m0 = 0, n0 = 0, z = 0;
  const __nv_bfloat16 *Ahs, *Als, *Bhs, *Bls;
  if constexpr (STAGE==2){
    b = blockIdx.z; m0 = blockIdx.y*128; n0 = blockIdx.x*96;
    Ahs = g_MI1h + m0*272; Als = g_MI1l + m0*272;
    Bhs = g_Zh + (long)b*276*272; Bls = g_Zl + (long)b*276*272;
  } else {
    z = blockIdx.x;
    Ahs = g_UAh + (long)z*128*144; Als = g_UAl + (long)z*128*144;
    Bhs = g_MI2h; Bls = g_MI2l;
  }

  float acc[4][NT4][4];
  #pragma unroll
  for (int i = 0; i < 4; i++)
    #pragma unroll
    for (int j = 0; j < NT4; j++)
      #pragma unroll
      for (int q = 0; q < 4; q++) acc[i][j][q] = 0.f;

  for (int kk = 0; kk < K; kk += KC){
    // ---- load A (128 x KC), hi+lo, 8B vectors
    #pragma unroll
    for (int it = 0; it < 4; it++){
      int idx = tid + it*256;
      int row = idx >> 3, c4 = (idx & 7)*4;
      int gk = kk + c4;
      unsigned long long vh = 0ull, vl = 0ull;
      if (gk < K){
        long off = (long)row*K + gk;
        vh = *reinterpret_cast<const unsigned long long*>(Ahs + off);
        vl = *reinterpret_cast<const unsigned long long*>(Als + off);
      }
      *reinterpret_cast<unsigned long long*>(Ah + row*SA + c4) = vh;
      *reinterpret_cast<unsigned long long*>(Al + row*SA + c4) = vl;
    }
    // ---- load B (BN x KC), hi+lo
    #pragma unroll
    for (int it = 0; it < BN/32; it++){
      int idx = tid + it*256;
      int row = idx >> 3, c4 = (idx & 7)*4;
      int gk = kk + c4;
      unsigned long long vh = 0ull, vl = 0ull;
      bool ok = (gk < K);
      if constexpr (STAGE==2) ok = ok && ((n0 + row) < 276);
      if (ok){
        long off = (long)((STAGE==2) ? (n0 + row) : row)*K + gk;
        vh = *reinterpret_cast<const unsigned long long*>(Bhs + off);
        vl = *reinterpret_cast<const unsigned long long*>(Bls + off);
      }
      *reinterpret_cast<unsigned long long*>(Bh + row*SA + c4) = vh;
      *reinterpret_cast<unsigned long long*>(Bl + row*SA + c4) = vl;
    }
    __syncthreads();

    const int ks = (K - kk >= KC) ? (KC/16) : ((K - kk)/16);
    for (int s = 0; s < ks; s++){
      const int tk = s*16;
      uint32_t afh[4][4], afl[4][4];
      #pragma unroll
      for (int i = 0; i < 4; i++){
        int row = wm*64 + i*16 + (lane & 15);
        int col = tk + (lane >> 4)*8;
        ldsm_x4(afh[i][0], afh[i][1], afh[i][2], afh[i][3],
                smem_u32(&Ah[row*SA + col]));
        ldsm_x4(afl[i][0], afl[i][1], afl[i][2], afl[i][3],
                smem_u32(&Al[row*SA + col]));
      }
      uint32_t bfh[NT4][2], bfl[NT4][2];
      #pragma unroll
      for (int j = 0; j < NT4; j++){
        int l15 = lane & 15;
        int row = wn*WN + j*8 + (l15 & 7);
        int col = tk + (l15 >> 3)*8;
        ldsm_x2(bfh[j][0], bfh[j][1], smem_u32(&Bh[row*SA + col]));
        ldsm_x2(bfl[j][0], bfl[j][1], smem_u32(&Bl[row*SA + col]));
      }
      #pragma unroll
      for (int i = 0; i < 4; i++)
        #pragma unroll
        for (int j = 0; j < NT4; j++){
          mma_bf16(acc[i][j], afh[i], bfh[j]);
          mma_bf16(acc[i][j], afh[i], bfl[j]);
          mma_bf16(acc[i][j], afl[i], bfh[j]);
        }
    }
    __syncthreads();
  }

  // ---- epilogue
  const int g = lane >> 2, tig = lane & 3;
  #pragma unroll
  for (int i = 0; i < 4; i++){
    #pragma unroll
    for (int j = 0; j < NT4; j++){
      int gr0 = m0 + wm*64 + i*16 + g;
      int gc0 = n0 + wn*WN + j*8 + tig*2;
      #pragma unroll
      for (int h = 0; h < 2; h++){       // row halves (+0 / +8)
        int gr = gr0 + h*8;
        #pragma unroll
        for (int e = 0; e < 2; e++){     // col pair
          int gc = gc0 + e;
          float val = acc[i][j][h*2 + e];
          if constexpr (STAGE==2){
            if (gc < 276){
              int r = gc/69, v = gc - r*69;
              long dst = (long)((b*4 + r)*128 + (gr & 127))*144 + (gr >> 7)*72 + v;
              split_bf(val, g_UAh[dst], g_UAl[dst]);
            }
          } else {
            int rr = z & 3, bb = z >> 2;
            outp[(long)bb*65536 + (2*gr + (rr >> 1))*256 + 2*gc + (rr & 1)] = val;
          }
        }
      }
    }
  }
}

// ===================== launch ===============================================
extern "C" void kernel_launch(void* const* d_in, const int* in_sizes, int n_in,
                              void* d_out, int out_size)
{
  const float* x = (const float*)d_in[0];
  const float* w = (const float*)(n_in > 1 ? d_in[1] : d_in[0]);
  const float* bias = (const float*)(n_in > 2 ? d_in[2] : d_in[0]);
  for (int i = 0; i < n_in; i++){
    if (in_sizes[i] == 4*64*128*128) x = (const float*)d_in[i];
    else if (in_sizes[i] == 64*25)   w = (const float*)d_in[i];
    else if (in_sizes[i] == 64)      bias = (const float*)d_in[i];
  }
  float* out = (float*)d_out;

  k_tw  <<<1, 272>>>();
  k_MB1 <<<(272*128+255)/256, 256>>>();
  k_MB2 <<<(256*138+255)/256, 256>>>();
  k_MI1b<<<(256*272+255)/256, 256>>>();
  k_MI2b<<<(128*144+255)/256, 256>>>();
  k_H   <<<(64*136*69+255)/256, 256>>>(w, bias);

  gemm_k<0><<<dim3(2,5,256), 256>>>(x);     // T  = MB1 * x
  gemm_k<1><<<dim3(3,3,256), 256>>>(x);     // Yt = (T * MB2)^T
  k_Z   <<<dim3(69,256), 160>>>();          // Z  = Y .* H (split bf16, K-major)

  mma_k<2><<<dim3(3,2,256), 256>>>(out);    // U  -> g_UA (split bf16)
  mma_k<3><<<dim3(1024,1,1), 256>>>(out);   // out via Hermitian-folded DFT
}

// round 5
// speedup vs baseline: 3.1575x; 1.3569x over previous
#include <cuda_runtime.h>
#include <cuda_bf16.h>
#include <math.h>
#include <cstdint>

#define PI_F 3.14159265358979323846f

// ===================== helpers ==============================================
__device__ __forceinline__ uint32_t smem_u32(const void* p){
  uint32_t a;
  asm("{ .reg .u64 t; cvta.to.shared.u64 t, %1; cvt.u32.u64 %0, t; }"
      : "=r"(a) : "l"(p));
  return a;
}
__device__ __forceinline__ void ldsm_x4(uint32_t &r0, uint32_t &r1,
                                        uint32_t &r2, uint32_t &r3, uint32_t addr){
  asm volatile("ldmatrix.sync.aligned.m8n8.x4.shared.b16 {%0,%1,%2,%3}, [%4];"
               : "=r"(r0), "=r"(r1), "=r"(r2), "=r"(r3) : "r"(addr));
}
__device__ __forceinline__ void ldsm_x2(uint32_t &r0, uint32_t &r1, uint32_t addr){
  asm volatile("ldmatrix.sync.aligned.m8n8.x2.shared.b16 {%0,%1}, [%2];"
               : "=r"(r0), "=r"(r1) : "r"(addr));
}
__device__ __forceinline__ void mma_bf16(float d[4], const uint32_t a[4],
                                         const uint32_t b[2]){
  asm volatile("mma.sync.aligned.m16n8k16.row.col.f32.bf16.bf16.f32 "
    "{%0,%1,%2,%3}, {%4,%5,%6,%7}, {%8,%9}, {%0,%1,%2,%3};"
    : "+f"(d[0]), "+f"(d[1]), "+f"(d[2]), "+f"(d[3])
    : "r"(a[0]), "r"(a[1]), "r"(a[2]), "r"(a[3]), "r"(b[0]), "r"(b[1]));
}
__device__ __forceinline__ unsigned long long ffma2(unsigned long long a,
                                                    unsigned long long b,
                                                    unsigned long long c){
  unsigned long long d;
  asm("fma.rn.f32x2 %0, %1, %2, %3;" : "=l"(d) : "l"(a), "l"(b), "l"(c));
  return d;
}
__device__ __forceinline__ unsigned long long dup2(float v){
  unsigned long long d; unsigned int u = __float_as_uint(v);
  asm("mov.b64 %0, {%1, %1};" : "=l"(d) : "r"(u));
  return d;
}
__device__ __forceinline__ float2 cmulf(float2 a, float2 b){
  return make_float2(a.x*b.x - a.y*b.y, a.x*b.y + a.y*b.x);
}
__device__ __forceinline__ void split_bf(float f, __nv_bfloat16 &h, __nv_bfloat16 &l){
  h = __float2bfloat16(f);
  l = __float2bfloat16(f - __bfloat162float(h));
}
__device__ __forceinline__ void fold_cs(int u, int ip, float &sumc, float &sumns){
  sumc = 0.f; sumns = 0.f;
  int iv[3]; int n = 0;
  iv[n++] = ip + 4;
  if (ip >= 124) iv[n++] = ip - 124;
  if (ip <= 3)   iv[n++] = ip + 132;
  for (int t = 0; t < n; t++){
    int m = (u * iv[t]) % 136;
    float s, c;
    sincosf((2.f*PI_F/136.f) * (float)m, &s, &c);
    sumc += c; sumns -= s;
  }
}

// ===================== persistent scratch ===================================
static __device__ float  g_T [256*272*128];
static __device__ float  g_Yt[256*138*136];                 // [b][n 138][u 136]
static __device__ float2 g_H [64*4*69*136];                 // [c][r][kw][kh]
static __device__ __align__(16) __nv_bfloat16 g_Zh[256*276*272];
static __device__ __align__(16) __nv_bfloat16 g_Zl[256*276*272];
static __device__ __align__(16) __nv_bfloat16 g_UAh[1024*128*144];
static __device__ __align__(16) __nv_bfloat16 g_UAl[1024*128*144];
static __device__ float  g_MB1[272*128];
static __device__ float  g_MB2[256*138];
static __device__ __align__(16) __nv_bfloat16 g_MI1h[256*272];
static __device__ __align__(16) __nv_bfloat16 g_MI1l[256*272];
static __device__ __align__(16) __nv_bfloat16 g_MI2h[128*144];
static __device__ __align__(16) __nv_bfloat16 g_MI2l[128*144];
static __device__ float2 g_tw[272];

// ===================== builders =============================================
__global__ void k_tw(){
  int i = threadIdx.x;
  if (i < 272){
    float s, c; sincosf((2.f*PI_F/272.f)*(float)i, &s, &c);
    g_tw[i] = make_float2(c, s);
  }
}
__global__ void k_MB1(){
  int idx = blockIdx.x*blockDim.x + threadIdx.x;
  if (idx >= 272*128) return;
  int col = idx % 128, row = idx / 128;
  int u = (row < 136) ? row : row - 136;
  float sc, sn; fold_cs(u, col, sc, sn);
  g_MB1[idx] = (row < 136) ? sc : sn;
}
__global__ void k_MB2(){
  int idx = blockIdx.x*blockDim.x + threadIdx.x;
  if (idx >= 256*138) return;
  int n = idx % 138, k = idx / 138;
  int v  = (n < 69) ? n : n - 69;
  int jp = (k < 128) ? k : k - 128;
  float sc, sn; fold_cs(v, jp, sc, sn);
  float val;
  if (n < 69) val = (k < 128) ? sc : -sn;
  else        val = (k < 128) ? sn :  sc;
  g_MB2[idx] = val;
}
__global__ void k_MI1b(){
  int idx = blockIdx.x*blockDim.x + threadIdx.x;
  if (idx >= 256*272) return;
  int k = idx % 272, row = idx / 272;
  int m   = (row & 127) + 4;
  int kap = (k < 136) ? k : k - 136;
  int a = (m * kap) % 136;
  float s, c; sincosf((2.f*PI_F/136.f)*(float)a, &s, &c);
  float val;
  if (row < 128) val = (k < 136) ?  c : -s;
  else           val = (k < 136) ?  s :  c;
  split_bf(val, g_MI1h[idx], g_MI1l[idx]);
}
__global__ void k_MI2b(){
  int idx = blockIdx.x*blockDim.x + threadIdx.x;
  if (idx >= 128*144) return;
  int kap = idx % 144, n = idx / 144;
  int part = (kap >= 72);
  int v = kap - (part ? 72 : 0);
  float val = 0.f;
  if (v < 69){
    float mult = (v == 0 || v == 68) ? 1.f : 2.f;
    int a = ((n + 4) * v) % 136;
    float s, c; sincosf((2.f*PI_F/136.f)*(float)a, &s, &c);
    val = part ? (-mult * s) : (mult * c);
  }
  split_bf(val, g_MI2h[idx], g_MI2l[idx]);
}

__global__ void k_H(const float* __restrict__ w, const float* __restrict__ bias){
  int idx = blockIdx.x*blockDim.x + threadIdx.x;
  if (idx >= 64*136*69) return;
  int kw = idx % 69; int t = idx / 69; int kh = t % 136; int c = t / 136;
  float beta = 1.f/(1.f + expf(9.f - bias[c])) + 1e-5f;

  float2 bh[5], bw[5];
  #pragma unroll
  for (int a = 0; a < 5; a++){
    int mh = ((kh*(a-2)) % 272 + 272) % 272;
    float2 th = g_tw[mh]; bh[a] = make_float2(th.x, -th.y);
    int mw = ((kw*(a-2)) % 272 + 272) % 272;
    float2 tw = g_tw[mw]; bw[a] = make_float2(tw.x, -tw.y);
  }
  float2 S0[5], S1[5];
  #pragma unroll
  for (int a = 0; a < 5; a++){
    float2 s0 = make_float2(0.f,0.f), s1 = make_float2(0.f,0.f);
    #pragma unroll
    for (int b = 0; b < 5; b++){
      float wv = w[c*25 + a*5 + b];
      float tx = wv*bw[b].x, ty = wv*bw[b].y;
      s0.x += tx; s0.y += ty;
      if (b & 1){ s1.x -= tx; s1.y -= ty; } else { s1.x += tx; s1.y += ty; }
    }
    S0[a] = s0; S1[a] = s1;
  }
  float2 tph = g_tw[kh];
  float2 ph = make_float2(tph.x, -tph.y);
  float2 tpw = g_tw[kw];
  float2 pw = make_float2(tpw.x, -tpw.y);

  float2 FB[4], G[4];
  float2 Asum = make_float2(0.f,0.f);
  float  invW = 0.f;
  #pragma unroll
  for (int p = 0; p < 2; p++){
    #pragma unroll
    for (int q = 0; q < 2; q++){
      int r = p*2+q;
      float2 fb = make_float2(0.f,0.f);
      #pragma unroll
      for (int a = 0; a < 5; a++){
        float2 S = q ? S1[a] : S0[a];
        float2 term = cmulf(bh[a], S);
        if (p && (a & 1)) { term.x = -term.x; term.y = -term.y; }
        fb.x += term.x; fb.y += term.y;
      }
      FB[r] = fb;
      float2 f1 = make_float2(1.f + (p ? -ph.x : ph.x), (p ? -ph.y : ph.y));
      float2 f2 = make_float2(1.f + (q ? -pw.x : pw.x), (q ? -pw.y : pw.y));
      float2 box = cmulf(f1, f2);
      float2 g = make_float2(fb.x + beta*box.x, -fb.y + beta*box.y);
      G[r] = g;
      float2 ag = cmulf(fb, g);
      Asum.x += ag.x; Asum.y += ag.y;
      invW += fb.x*fb.x + fb.y*fb.y;
    }
  }
  Asum.x *= 0.25f; Asum.y *= 0.25f; invW *= 0.25f;
  float dinv = 1.f/(invW + beta);
  float2 tt = make_float2(Asum.x*dinv, Asum.y*dinv);
  float invb = 1.f/beta;
  float2 Hm[4];
  #pragma unroll
  for (int r = 0; r < 4; r++){
    float2 cf = make_float2(FB[r].x, -FB[r].y);
    float2 ct = cmulf(cf, tt);
    Hm[r] = make_float2((G[r].x - ct.x)*invb, (G[r].y - ct.y)*invb);
  }
  const float scale = 1.f/73984.f;
  float2 twh = make_float2(ph.x, -ph.y);
  float2 tww = make_float2(pw.x, -pw.y);
  #pragma unroll
  for (int rh = 0; rh < 2; rh++){
    #pragma unroll
    for (int rw = 0; rw < 2; rw++){
      float2 s = make_float2(0.f,0.f);
      #pragma unroll
      for (int p = 0; p < 2; p++)
        #pragma unroll
        for (int q = 0; q < 2; q++){
          float sg = ((p*rh + q*rw) & 1) ? -1.f : 1.f;
          s.x += sg*Hm[p*2+q].x; s.y += sg*Hm[p*2+q].y;
        }
      float2 tw = make_float2(1.f, 0.f);
      if (rh) tw = twh;
      if (rw) tw = cmulf(tw, tww);
      float2 o = cmulf(s, tw);
      o.x *= scale; o.y *= scale;
      g_H[((c*4 + rh*2 + rw)*69 + kw)*136 + kh] = o;
    }
  }
}

// ===================== Z = Y .* H, split-bf16, K-major ======================
__global__ void k_Z(){
  int kw = blockIdx.x;             // [0,69)
  int b  = blockIdx.y;             // [0,256)
  int kh = threadIdx.x;
  if (kh >= 136) return;
  int c = b & 63;
  float yr = g_Yt[(b*138 + kw)*136 + kh];
  float yi = g_Yt[(b*138 + 69 + kw)*136 + kh];
  #pragma unroll
  for (int r = 0; r < 4; r++){
    float2 h = g_H[((c*4+r)*69 + kw)*136 + kh];
    float zr = yr*h.x - yi*h.y;
    float zi = yr*h.y + yi*h.x;
    int n = r*69 + kw;
    long base = (long)(b*276 + n)*272;
    split_bf(zr, g_Zh[base + kh],       g_Zl[base + kh]);
    split_bf(zi, g_Zh[base + 136 + kh], g_Zl[base + 136 + kh]);
  }
}

// ===================== FFMA2 GEMM (stages 0,1) ==============================
template<int STAGE>
__global__ __launch_bounds__(256) void gemm_k(const float* __restrict__ xin)
{
  constexpr int K = (STAGE==0)?128 : 256;
  constexpr int BM = 64, TM = 4, TP = 2;

  __shared__ __align__(16) float As[2][16][BM];
  __shared__ __align__(16) float Bs[2][16][64];

  const int z = blockIdx.z;
  const int tid = threadIdx.x, tx = tid & 15, ty = tid >> 4;
  const int m0 = blockIdx.y*BM, n0 = blockIdx.x*64;

  auto fetchA = [&](int gm, int gk)->float{
    if constexpr (STAGE==0){
      return (gm < 272) ? g_MB1[gm*128 + gk] : 0.f;
    } else {
      if (gm >= 136) return 0.f;
      const float* T = g_T + z*34816;
      return (gk < 128) ? T[gm*128 + gk] : T[(136+gm)*128 + (gk-128)];
    }
  };
  auto fetchB = [&](int gk, int gn)->float{
    if constexpr (STAGE==0) return xin[z*16384 + gk*128 + gn];
    else                    return (gn < 138) ? g_MB2[gk*138 + gn] : 0.f;
  };
  auto storeC = [&](int gm, int gn, float v){
    if constexpr (STAGE==0){ if (gm < 272) g_T[z*34816 + gm*128 + gn] = v; }
    else { if (gm < 136 && gn < 138) g_Yt[(z*138 + gn)*136 + gm] = v; }
  };

  float ra[4]; float rb[4];
  auto loadAB = [&](int kk){
    int m = tid >> 2, kg = (tid & 3)*4;
    int gm = m0 + m;
    #pragma unroll
    for (int d = 0; d < 4; d++) ra[d] = fetchA(gm, kk + kg + d);
    int kb = tid >> 4, nx = (tid & 15)*4;
    #pragma unroll
    for (int d = 0; d < 4; d++) rb[d] = fetchB(kk + kb, n0 + nx + d);
  };
  auto storeAB = [&](int buf){
    int m = tid >> 2, kg = (tid & 3)*4;
    #pragma unroll
    for (int d = 0; d < 4; d++) As[buf][kg+d][m] = ra[d];
    int kb = tid >> 4, nx = (tid & 15)*4;
    #pragma unroll
    for (int d = 0; d < 4; d++) Bs[buf][kb][nx+d] = rb[d];
  };

  unsigned long long acc[TP][4] = {};
  constexpr int NT = K/16;
  loadAB(0); storeAB(0); __syncthreads();

  #pragma unroll 1
  for (int t = 0; t < NT; t++){
    int buf = t & 1;
    if (t + 1 < NT) loadAB((t+1)*16);
    #pragma unroll
    for (int k = 0; k < 16; k++){
      ulonglong2 v0 = *reinterpret_cast<const ulonglong2*>(&As[buf][k][ty*TM]);
      unsigned long long ap[2] = {v0.x, v0.y};
      float4 bq = *reinterpret_cast<const float4*>(&Bs[buf][k][tx*4]);
      unsigned long long bd0 = dup2(bq.x), bd1 = dup2(bq.y);
      unsigned long long bd2 = dup2(bq.z), bd3 = dup2(bq.w);
      #pragma unroll
      for (int p = 0; p < TP; p++){
        acc[p][0] = ffma2(ap[p], bd0, acc[p][0]);
        acc[p][1] = ffma2(ap[p], bd1, acc[p][1]);
        acc[p][2] = ffma2(ap[p], bd2, acc[p][2]);
        acc[p][3] = ffma2(ap[p], bd3, acc[p][3]);
      }
    }
    if (t + 1 < NT){ storeAB(buf ^ 1); __syncthreads(); }
  }

  union { unsigned long long u; float2 f; } pun;
  #pragma unroll
  for (int p = 0; p < TP; p++){
    int gmA = m0 + ty*TM + 2*p;
    #pragma unroll
    for (int j = 0; j < 4; j++){
      int gn = n0 + tx*4 + j;
      pun.u = acc[p][j];
      storeC(gmA,     gn, pun.f.x);
      storeC(gmA + 1, gn, pun.f.y);
    }
  }
}

// ===================== HMMA split-bf16 GEMM, cp.async pipelined =============
// STAGE 2: U(256x276) = MI1(256x272) * Z_b(276x272)^T  -> g_UA split bf16
// STAGE 3: out = UA_z(128x144) * MI2(128x144)^T -> d_out interleaved
template<int STAGE>
__global__ __launch_bounds__(256) void mma_k(float* __restrict__ outp)
{
  constexpr int BN  = (STAGE==2) ? 96 : 128;
  constexpr int K   = (STAGE==2) ? 272 : 144;
  constexpr int NCH = K/16;            // 17 or 9 chunks of 16
  constexpr int SA  = 24;              // smem row stride (elements) = 48B
  constexpr int NT4 = BN/32;           // 3 or 4
  constexpr int WN  = BN/4;            // 24 or 32
  constexpr int ABYTES = 128*SA*2;
  constexpr int BBYTES = BN*SA*2;
  constexpr int BUFB = 2*ABYTES + 2*BBYTES;
  constexpr int OAH = 0, OAL = ABYTES, OBH = 2*ABYTES, OBL = 2*ABYTES + BBYTES;

  __shared__ __align__(16) char smraw[2*BUFB];

  const int tid = threadIdx.x, lane = tid & 31, wid = tid >> 5;
  const int wm = wid & 1, wn = wid >> 1;

  int b = 0, n0 = 0, z = 0, mt = 0;
  const __nv_bfloat16 *Ahs, *Als, *Bhs, *Bls;
  if constexpr (STAGE==2){
    b = blockIdx.z; mt = blockIdx.y; n0 = blockIdx.x*96;
    Ahs = g_MI1h + mt*128*272; Als = g_MI1l + mt*128*272;
    Bhs = g_Zh + (long)b*276*272; Bls = g_Zl + (long)b*276*272;
  } else {
    z = blockIdx.x;
    Ahs = g_UAh + (long)z*128*144; Als = g_UAl + (long)z*128*144;
    Bhs = g_MI2h; Bls = g_MI2l;
  }

  auto issue = [&](int t, int buf){
    const int kk = t*16;
    char* base = smraw + buf*BUFB;
    // A: 128 rows x 2 c16 x 2 (h,l) = 512 chunks of 16B
    #pragma unroll
    for (int it = 0; it < 2; it++){
      int cid = tid + it*256;
      int hl = cid >> 8, rem = cid & 255;
      int row = rem >> 1, c16 = rem & 1;
      const __nv_bfloat16* src = (hl ? Als : Ahs) + (long)row*K + kk + c16*8;
      uint32_t dst = smem_u32(base + (hl ? OAL : OAH) + row*(SA*2) + c16*16);
      asm volatile("cp.async.ca.shared.global [%0], [%1], 16;"
                   :: "r"(dst), "l"(src));
    }
    // B: BN rows x 2 x 2
    constexpr int BCH = BN*4;
    #pragma unroll
    for (int it = 0; it < (BCH + 255)/256; it++){
      int cid = tid + it*256;
      if (cid < BCH){
        int hl = (cid >= BCH/2), rem = cid % (BCH/2);
        int row = rem >> 1, c16 = rem & 1;
        int grow = row, sz = 16;
        if constexpr (STAGE==2){
          grow = n0 + row;
          if (grow >= 276){ grow = 275; sz = 0; }
        }
        const __nv_bfloat16* src = (hl ? Bls : Bhs) + (long)grow*K + kk + c16*8;
        uint32_t dst = smem_u32(base + (hl ? OBL : OBH) + row*(SA*2) + c16*16);
        asm volatile("cp.async.ca.shared.global [%0], [%1], 16, %2;"
                     :: "r"(dst), "l"(src), "r"(sz));
      }
    }
    asm volatile("cp.async.commit_group;" ::: "memory");
  };

  float acc[4][NT4][4];
  #pragma unroll
  for (int i = 0; i < 4; i++)
    #pragma unroll
    for (int j = 0; j < NT4; j++)
      #pragma unroll
      for (int q = 0; q < 4; q++) acc[i][j][q] = 0.f;

  issue(0, 0);

  #pragma unroll 1
  for (int t = 0; t < NCH; t++){
    const int buf = t & 1;
    if (t + 1 < NCH){
      issue(t + 1, buf ^ 1);
      asm volatile("cp.async.wait_group 1;" ::: "memory");
    } else {
      asm volatile("cp.async.wait_group 0;" ::: "memory");
    }
    __syncthreads();

    char* base = smraw + buf*BUFB;
    uint32_t afh[4][4], afl[4][4];
    #pragma unroll
    for (int i = 0; i < 4; i++){
      int row = wm*64 + i*16 + (lane & 15);
      int col = (lane >> 4)*8;
      ldsm_x4(afh[i][0], afh[i][1], afh[i][2], afh[i][3],
              smem_u32(base + OAH + row*(SA*2) + col*2));
      ldsm_x4(afl[i][0], afl[i][1], afl[i][2], afl[i][3],
              smem_u32(base + OAL + row*(SA*2) + col*2));
    }
    uint32_t bfh[NT4][2], bfl[NT4][2];
    #pragma unroll
    for (int j = 0; j < NT4; j++){
      int l15 = lane & 15;
      int row = wn*WN + j*8 + (l15 & 7);
      int col = (l15 >> 3)*8;
      ldsm_x2(bfh[j][0], bfh[j][1], smem_u32(base + OBH + row*(SA*2) + col*2));
      ldsm_x2(bfl[j][0], bfl[j][1], smem_u32(base + OBL + row*(SA*2) + col*2));
    }
    #pragma unroll
    for (int i = 0; i < 4; i++)
      #pragma unroll
      for (int j = 0; j < NT4; j++){
        mma_bf16(acc[i][j], afh[i], bfh[j]);
        mma_bf16(acc[i][j], afh[i], bfl[j]);
        mma_bf16(acc[i][j], afl[i], bfh[j]);
      }
    __syncthreads();
  }

  // ---- coalesced epilogue via SMEM staging
  float* S = reinterpret_cast<float*>(smraw);
  const int g = lane >> 2, tig = lane & 3;
  constexpr int CG = (STAGE==2) ? 48 : 64;   // columns per pass
  constexpr int NP = BN / CG;                // 2 passes

  #pragma unroll 1
  for (int p = 0; p < NP; p++){
    if ((wn >> 1) == p){
      #pragma unroll
      for (int i = 0; i < 4; i++)
        #pragma unroll
        for (int j = 0; j < NT4; j++)
          #pragma unroll
          for (int h = 0; h < 2; h++)
            #pragma unroll
            for (int e = 0; e < 2; e++){
              int row = wm*64 + i*16 + g + h*8;
              int lc  = (wn & 1)*WN + j*8 + tig*2 + e;
              S[lc*129 + row] = acc[i][j][h*2 + e];
            }
    }
    __syncthreads();
    for (int idx = tid; idx < CG*128; idx += 256){
      int m = idx / CG, cc = idx % CG;
      float val = S[cc*129 + m];
      if constexpr (STAGE==2){
        int gc = n0 + p*CG + cc;
        if (gc < 276){
          int r = gc/69, v = gc - r*69;
          long dst = (long)((b*4 + r)*128 + m)*144 + mt*72 + v;
          split_bf(val, g_UAh[dst], g_UAl[dst]);
        }
      } else {
        int rr = z & 3, bb = z >> 2;
        int gc = p*CG + cc;
        outp[(long)bb*65536 + (2*m + (rr >> 1))*256 + 2*gc + (rr & 1)] = val;
      }
    }
    __syncthreads();
  }
}

// ===================== launch ===============================================
extern "C" void kernel_launch(void* const* d_in, const int* in_sizes, int n_in,
                              void* d_out, int out_size)
{
  const float* x = (const float*)d_in[0];
  const float* w = (const float*)(n_in > 1 ? d_in[1] : d_in[0]);
  const float* bias = (const float*)(n_in > 2 ? d_in[2] : d_in[0]);
  for (int i = 0; i < n_in; i++){
    if (in_sizes[i] == 4*64*128*128) x = (const float*)d_in[i];
    else if (in_sizes[i] == 64*25)   w = (const float*)d_in[i];
    else if (in_sizes[i] == 64)      bias = (const float*)d_in[i];
  }
  float* out = (float*)d_out;

  k_tw  <<<1, 272>>>();
  k_MB1 <<<(272*128+255)/256, 256>>>();
  k_MB2 <<<(256*138+255)/256, 256>>>();
  k_MI1b<<<(256*272+255)/256, 256>>>();
  k_MI2b<<<(128*144+255)/256, 256>>>();
  k_H   <<<(64*136*69+255)/256, 256>>>(w, bias);

  gemm_k<0><<<dim3(2,5,256), 256>>>(x);     // T  = MB1 * x
  gemm_k<1><<<dim3(3,3,256), 256>>>(x);     // Yt = (T * MB2)^T
  k_Z   <<<dim3(69,256), 160>>>();          // Z  = Y .* H (split bf16, K-major)

  mma_k<2><<<dim3(3,2,256), 256>>>(out);    // U  -> g_UA (split bf16)
  mma_k<3><<<dim3(1024,1,1), 256>>>(out);   // out via Hermitian-folded DFT
}

// round 6
// speedup vs baseline: 3.1700x; 1.0040x over previous
#include <cuda_runtime.h>
#include <cuda_bf16.h>
#include <math.h>
#include <cstdint>

#define PI_F 3.14159265358979323846f

// ===================== helpers ==============================================
__device__ __forceinline__ uint32_t smem_u32(const void* p){
  uint32_t a;
  asm("{ .reg .u64 t; cvta.to.shared.u64 t, %1; cvt.u32.u64 %0, t; }"
      : "=r"(a) : "l"(p));
  return a;
}
__device__ __forceinline__ void ldsm_x4(uint32_t &r0, uint32_t &r1,
                                        uint32_t &r2, uint32_t &r3, uint32_t addr){
  asm volatile("ldmatrix.sync.aligned.m8n8.x4.shared.b16 {%0,%1,%2,%3}, [%4];"
               : "=r"(r0), "=r"(r1), "=r"(r2), "=r"(r3) : "r"(addr));
}
__device__ __forceinline__ void ldsm_x2(uint32_t &r0, uint32_t &r1, uint32_t addr){
  asm volatile("ldmatrix.sync.aligned.m8n8.x2.shared.b16 {%0,%1}, [%2];"
               : "=r"(r0), "=r"(r1) : "r"(addr));
}
__device__ __forceinline__ void mma_bf16(float d[4], const uint32_t a[4],
                                         const uint32_t b[2]){
  asm volatile("mma.sync.aligned.m16n8k16.row.col.f32.bf16.bf16.f32 "
    "{%0,%1,%2,%3}, {%4,%5,%6,%7}, {%8,%9}, {%0,%1,%2,%3};"
    : "+f"(d[0]), "+f"(d[1]), "+f"(d[2]), "+f"(d[3])
    : "r"(a[0]), "r"(a[1]), "r"(a[2]), "r"(a[3]), "r"(b[0]), "r"(b[1]));
}
__device__ __forceinline__ unsigned long long ffma2(unsigned long long a,
                                                    unsigned long long b,
                                                    unsigned long long c){
  unsigned long long d;
  asm("fma.rn.f32x2 %0, %1, %2, %3;" : "=l"(d) : "l"(a), "l"(b), "l"(c));
  return d;
}
__device__ __forceinline__ unsigned long long dup2(float v){
  unsigned long long d; unsigned int u = __float_as_uint(v);
  asm("mov.b64 %0, {%1, %1};" : "=l"(d) : "r"(u));
  return d;
}
__device__ __forceinline__ float2 cmulf(float2 a, float2 b){
  return make_float2(a.x*b.x - a.y*b.y, a.x*b.y + a.y*b.x);
}
__device__ __forceinline__ void split_bf(float f, __nv_bfloat16 &h, __nv_bfloat16 &l){
  h = __float2bfloat16(f);
  l = __float2bfloat16(f - __bfloat162float(h));
}
__device__ __forceinline__ void fold_cs(int u, int ip, float &sumc, float &sumns){
  sumc = 0.f; sumns = 0.f;
  int iv[3]; int n = 0;
  iv[n++] = ip + 4;
  if (ip >= 124) iv[n++] = ip - 124;
  if (ip <= 3)   iv[n++] = ip + 132;
  for (int t = 0; t < n; t++){
    int m = (u * iv[t]) % 136;
    float s, c;
    sincosf((2.f*PI_F/136.f) * (float)m, &s, &c);
    sumc += c; sumns -= s;
  }
}

// ===================== persistent scratch ===================================
static __device__ float  g_T [256*272*128];
static __device__ float  g_Yt[256*138*136];                 // [b][n 138][u 136]
static __device__ float2 g_H [64*4*69*136];                 // [c][r][kw][kh]
static __device__ __align__(16) __nv_bfloat16 g_Zh[256*276*272];
static __device__ __align__(16) __nv_bfloat16 g_Zl[256*276*272];
static __device__ __align__(16) __nv_bfloat16 g_UAh[1024*128*144];
static __device__ __align__(16) __nv_bfloat16 g_UAl[1024*128*144];
static __device__ float  g_MB1[272*128];
static __device__ float  g_MB2[256*138];
static __device__ __align__(16) __nv_bfloat16 g_MI1h[256*272];
static __device__ __align__(16) __nv_bfloat16 g_MI1l[256*272];
static __device__ __align__(16) __nv_bfloat16 g_MI2h[128*144];
static __device__ __align__(16) __nv_bfloat16 g_MI2l[128*144];
static __device__ float2 g_tw[272];

// ===================== builders =============================================
__global__ void k_tw(){
  int i = threadIdx.x;
  if (i < 272){
    float s, c; sincosf((2.f*PI_F/272.f)*(float)i, &s, &c);
    g_tw[i] = make_float2(c, s);
  }
}
__global__ void k_MB1(){
  int idx = blockIdx.x*blockDim.x + threadIdx.x;
  if (idx >= 272*128) return;
  int col = idx % 128, row = idx / 128;
  int u = (row < 136) ? row : row - 136;
  float sc, sn; fold_cs(u, col, sc, sn);
  g_MB1[idx] = (row < 136) ? sc : sn;
}
__global__ void k_MB2(){
  int idx = blockIdx.x*blockDim.x + threadIdx.x;
  if (idx >= 256*138) return;
  int n = idx % 138, k = idx / 138;
  int v  = (n < 69) ? n : n - 69;
  int jp = (k < 128) ? k : k - 128;
  float sc, sn; fold_cs(v, jp, sc, sn);
  float val;
  if (n < 69) val = (k < 128) ? sc : -sn;
  else        val = (k < 128) ? sn :  sc;
  g_MB2[idx] = val;
}
__global__ void k_MI1b(){
  int idx = blockIdx.x*blockDim.x + threadIdx.x;
  if (idx >= 256*272) return;
  int k = idx % 272, row = idx / 272;
  int m   = (row & 127) + 4;
  int kap = (k < 136) ? k : k - 136;
  int a = (m * kap) % 136;
  float s, c; sincosf((2.f*PI_F/136.f)*(float)a, &s, &c);
  float val;
  if (row < 128) val = (k < 136) ?  c : -s;
  else           val = (k < 136) ?  s :  c;
  split_bf(val, g_MI1h[idx], g_MI1l[idx]);
}
__global__ void k_MI2b(){
  int idx = blockIdx.x*blockDim.x + threadIdx.x;
  if (idx >= 128*144) return;
  int kap = idx % 144, n = idx / 144;
  int part = (kap >= 72);
  int v = kap - (part ? 72 : 0);
  float val = 0.f;
  if (v < 69){
    float mult = (v == 0 || v == 68) ? 1.f : 2.f;
    int a = ((n + 4) * v) % 136;
    float s, c; sincosf((2.f*PI_F/136.f)*(float)a, &s, &c);
    val = part ? (-mult * s) : (mult * c);
  }
  split_bf(val, g_MI2h[idx], g_MI2l[idx]);
}

__global__ void k_H(const float* __restrict__ w, const float* __restrict__ bias){
  int idx = blockIdx.x*blockDim.x + threadIdx.x;
  if (idx >= 64*136*69) return;
  int kw = idx % 69; int t = idx / 69; int kh = t % 136; int c = t / 136;
  float beta = 1.f/(1.f + expf(9.f - bias[c])) + 1e-5f;

  float2 bh[5], bw[5];
  #pragma unroll
  for (int a = 0; a < 5; a++){
    int mh = ((kh*(a-2)) % 272 + 272) % 272;
    float2 th = g_tw[mh]; bh[a] = make_float2(th.x, -th.y);
    int mw = ((kw*(a-2)) % 272 + 272) % 272;
    float2 tw = g_tw[mw]; bw[a] = make_float2(tw.x, -tw.y);
  }
  float2 S0[5], S1[5];
  #pragma unroll
  for (int a = 0; a < 5; a++){
    float2 s0 = make_float2(0.f,0.f), s1 = make_float2(0.f,0.f);
    #pragma unroll
    for (int b = 0; b < 5; b++){
      float wv = w[c*25 + a*5 + b];
      float tx = wv*bw[b].x, ty = wv*bw[b].y;
      s0.x += tx; s0.y += ty;
      if (b & 1){ s1.x -= tx; s1.y -= ty; } else { s1.x += tx; s1.y += ty; }
    }
    S0[a] = s0; S1[a] = s1;
  }
  float2 tph = g_tw[kh];
  float2 ph = make_float2(tph.x, -tph.y);
  float2 tpw = g_tw[kw];
  float2 pw = make_float2(tpw.x, -tpw.y);

  float2 FB[4], G[4];
  float2 Asum = make_float2(0.f,0.f);
  float  invW = 0.f;
  #pragma unroll
  for (int p = 0; p < 2; p++){
    #pragma unroll
    for (int q = 0; q < 2; q++){
      int r = p*2+q;
      float2 fb = make_float2(0.f,0.f);
      #pragma unroll
      for (int a = 0; a < 5; a++){
        float2 S = q ? S1[a] : S0[a];
        float2 term = cmulf(bh[a], S);
        if (p && (a & 1)) { term.x = -term.x; term.y = -term.y; }
        fb.x += term.x; fb.y += term.y;
      }
      FB[r] = fb;
      float2 f1 = make_float2(1.f + (p ? -ph.x : ph.x), (p ? -ph.y : ph.y));
      float2 f2 = make_float2(1.f + (q ? -pw.x : pw.x), (q ? -pw.y : pw.y));
      float2 box = cmulf(f1, f2);
      float2 g = make_float2(fb.x + beta*box.x, -fb.y + beta*box.y);
      G[r] = g;
      float2 ag = cmulf(fb, g);
      Asum.x += ag.x; Asum.y += ag.y;
      invW += fb.x*fb.x + fb.y*fb.y;
    }
  }
  Asum.x *= 0.25f; Asum.y *= 0.25f; invW *= 0.25f;
  float dinv = 1.f/(invW + beta);
  float2 tt = make_float2(Asum.x*dinv, Asum.y*dinv);
  float invb = 1.f/beta;
  float2 Hm[4];
  #pragma unroll
  for (int r = 0; r < 4; r++){
    float2 cf = make_float2(FB[r].x, -FB[r].y);
    float2 ct = cmulf(cf, tt);
    Hm[r] = make_float2((G[r].x - ct.x)*invb, (G[r].y - ct.y)*invb);
  }
  const float scale = 1.f/73984.f;
  float2 twh = make_float2(ph.x, -ph.y);
  float2 tww = make_float2(pw.x, -pw.y);
  #pragma unroll
  for (int rh = 0; rh < 2; rh++){
    #pragma unroll
    for (int rw = 0; rw < 2; rw++){
      float2 s = make_float2(0.f,0.f);
      #pragma unroll
      for (int p = 0; p < 2; p++)
        #pragma unroll
        for (int q = 0; q < 2; q++){
          float sg = ((p*rh + q*rw) & 1) ? -1.f : 1.f;
          s.x += sg*Hm[p*2+q].x; s.y += sg*Hm[p*2+q].y;
        }
      float2 tw = make_float2(1.f, 0.f);
      if (rh) tw = twh;
      if (rw) tw = cmulf(tw, tww);
      float2 o = cmulf(s, tw);
      o.x *= scale; o.y *= scale;
      g_H[((c*4 + rh*2 + rw)*69 + kw)*136 + kh] = o;
    }
  }
}

// ===================== Z = Y .* H, split-bf16, K-major ======================
__global__ void k_Z(){
  int kw = blockIdx.x;             // [0,69)
  int b  = blockIdx.y;             // [0,256)
  int kh = threadIdx.x;
  if (kh >= 136) return;
  int c = b & 63;
  float yr = g_Yt[(b*138 + kw)*136 + kh];
  float yi = g_Yt[(b*138 + 69 + kw)*136 + kh];
  #pragma unroll
  for (int r = 0; r < 4; r++){
    float2 h = g_H[((c*4+r)*69 + kw)*136 + kh];
    float zr = yr*h.x - yi*h.y;
    float zi = yr*h.y + yi*h.x;
    int n = r*69 + kw;
    long base = (long)(b*276 + n)*272;
    split_bf(zr, g_Zh[base + kh],       g_Zl[base + kh]);
    split_bf(zi, g_Zh[base + 136 + kh], g_Zl[base + 136 + kh]);
  }
}

// ===================== FFMA2 GEMM (stages 0,1) ==============================
template<int STAGE>
__global__ __launch_bounds__(256) void gemm_k(const float* __restrict__ xin)
{
  constexpr int K = (STAGE==0)?128 : 256;
  constexpr int BM = 64, TM = 4, TP = 2;

  __shared__ __align__(16) float As[2][16][BM];
  __shared__ __align__(16) float Bs[2][16][64];

  const int z = blockIdx.z;
  const int tid = threadIdx.x, tx = tid & 15, ty = tid >> 4;
  const int m0 = blockIdx.y*BM, n0 = blockIdx.x*64;

  auto fetchA = [&](int gm, int gk)->float{
    if constexpr (STAGE==0){
      return (gm < 272) ? g_MB1[gm*128 + gk] : 0.f;
    } else {
      if (gm >= 136) return 0.f;
      const float* T = g_T + z*34816;
      return (gk < 128) ? T[gm*128 + gk] : T[(136+gm)*128 + (gk-128)];
    }
  };
  auto fetchB = [&](int gk, int gn)->float{
    if constexpr (STAGE==0) return xin[z*16384 + gk*128 + gn];
    else                    return (gn < 138) ? g_MB2[gk*138 + gn] : 0.f;
  };
  auto storeC = [&](int gm, int gn, float v){
    if constexpr (STAGE==0){ if (gm < 272) g_T[z*34816 + gm*128 + gn] = v; }
    else { if (gm < 136 && gn < 138) g_Yt[(z*138 + gn)*136 + gm] = v; }
  };

  float ra[4]; float rb[4];
  auto loadAB = [&](int kk){
    int m = tid >> 2, kg = (tid & 3)*4;
    int gm = m0 + m;
    #pragma unroll
    for (int d = 0; d < 4; d++) ra[d] = fetchA(gm, kk + kg + d);
    int kb = tid >> 4, nx = (tid & 15)*4;
    #pragma unroll
    for (int d = 0; d < 4; d++) rb[d] = fetchB(kk + kb, n0 + nx + d);
  };
  auto storeAB = [&](int buf){
    int m = tid >> 2, kg = (tid & 3)*4;
    #pragma unroll
    for (int d = 0; d < 4; d++) As[buf][kg+d][m] = ra[d];
    int kb = tid >> 4, nx = (tid & 15)*4;
    #pragma unroll
    for (int d = 0; d < 4; d++) Bs[buf][kb][nx+d] = rb[d];
  };

  unsigned long long acc[TP][4] = {};
  constexpr int NT = K/16;
  loadAB(0); storeAB(0); __syncthreads();

  #pragma unroll 1
  for (int t = 0; t < NT; t++){
    int buf = t & 1;
    if (t + 1 < NT) loadAB((t+1)*16);
    #pragma unroll
    for (int k = 0; k < 16; k++){
      ulonglong2 v0 = *reinterpret_cast<const ulonglong2*>(&As[buf][k][ty*TM]);
      unsigned long long ap[2] = {v0.x, v0.y};
      float4 bq = *reinterpret_cast<const float4*>(&Bs[buf][k][tx*4]);
      unsigned long long bd0 = dup2(bq.x), bd1 = dup2(bq.y);
      unsigned long long bd2 = dup2(bq.z), bd3 = dup2(bq.w);
      #pragma unroll
      for (int p = 0; p < TP; p++){
        acc[p][0] = ffma2(ap[p], bd0, acc[p][0]);
        acc[p][1] = ffma2(ap[p], bd1, acc[p][1]);
        acc[p][2] = ffma2(ap[p], bd2, acc[p][2]);
        acc[p][3] = ffma2(ap[p], bd3, acc[p][3]);
      }
    }
    if (t + 1 < NT){ storeAB(buf ^ 1); __syncthreads(); }
  }

  union { unsigned long long u; float2 f; } pun;
  #pragma unroll
  for (int p = 0; p < TP; p++){
    int gmA = m0 + ty*TM + 2*p;
    #pragma unroll
    for (int j = 0; j < 4; j++){
      int gn = n0 + tx*4 + j;
      pun.u = acc[p][j];
      storeC(gmA,     gn, pun.f.x);
      storeC(gmA + 1, gn, pun.f.y);
    }
  }
}

// ===================== HMMA split-bf16 GEMM, cp.async KC=32 pipeline ========
// STAGE 2: U(256x276) = MI1(256x272) * Z_b(276x272)^T  -> g_UA split bf16
// STAGE 3: out = UA_z(128x144) * MI2(128x144)^T -> d_out interleaved
template<int STAGE>
__global__ __launch_bounds__(256) void mma_k(float* __restrict__ outp)
{
  constexpr int BN  = (STAGE==2) ? 96 : 128;
  constexpr int K   = (STAGE==2) ? 272 : 144;
  constexpr int KC  = 32;
  constexpr int NCH = (K + KC - 1)/KC;       // 9 or 5
  constexpr int SAB = 80;                    // smem row stride bytes (40 elems)
  constexpr int NT4 = BN/32;                 // 3 or 4
  constexpr int WN  = BN/4;                  // 24 or 32
  constexpr int ABY = 128*SAB;               // per hl matrix
  constexpr int BBY = BN*SAB;
  constexpr int OAH = 0, OAL = ABY, OBH = 2*ABY, OBL = 2*ABY + BBY;
  constexpr int BUFB = 2*ABY + 2*BBY;

  extern __shared__ __align__(16) char smraw[];

  const int tid = threadIdx.x, lane = tid & 31, wid = tid >> 5;
  const int wm = wid & 1, wn = wid >> 1;

  int b = 0, n0 = 0, z = 0, mt = 0;
  const __nv_bfloat16 *Ahs, *Als, *Bhs, *Bls;
  if constexpr (STAGE==2){
    b = blockIdx.z; mt = blockIdx.y; n0 = blockIdx.x*96;
    Ahs = g_MI1h + mt*128*272; Als = g_MI1l + mt*128*272;
    Bhs = g_Zh + (long)b*276*272; Bls = g_Zl + (long)b*276*272;
  } else {
    z = blockIdx.x;
    Ahs = g_UAh + (long)z*128*144; Als = g_UAl + (long)z*128*144;
    Bhs = g_MI2h; Bls = g_MI2l;
  }

  auto issue = [&](int t, int buf){
    const int kk = t*KC;
    char* base = smraw + buf*BUFB;
    // A: 128 rows x 4 c16 x 2 hl = 1024 chunks of 16B -> 4 per thread
    #pragma unroll
    for (int it = 0; it < 4; it++){
      int cid = tid + it*256;
      int hl = cid >> 9, rem = cid & 511;
      int row = rem >> 2, c16 = rem & 3;
      int gk = kk + c16*8;
      int sz = (gk + 8 <= K) ? 16 : 0;
      const __nv_bfloat16* src = (hl ? Als : Ahs) + (long)row*K + (sz ? gk : 0);
      uint32_t dst = smem_u32(base + (hl ? OAL : OAH) + row*SAB + c16*16);
      asm volatile("cp.async.ca.shared.global [%0], [%1], 16, %2;"
                   :: "r"(dst), "l"(src), "r"(sz));
    }
    // B: BN rows x 4 c16 x 2 hl
    constexpr int BCH = BN*8;
    #pragma unroll
    for (int it = 0; it < BCH/256; it++){
      int cid = tid + it*256;
      int hl = (cid >= BCH/2), rem = cid % (BCH/2);
      int row = rem >> 2, c16 = rem & 3;
      int gk = kk + c16*8;
      int grow = row;
      int sz = (gk + 8 <= K) ? 16 : 0;
      if constexpr (STAGE==2){
        grow = n0 + row;
        if (grow >= 276){ grow = 275; sz = 0; }
      }
      const __nv_bfloat16* src = (hl ? Bls : Bhs) + (long)grow*K + (sz ? gk : 0);
      uint32_t dst = smem_u32(base + (hl ? OBL : OBH) + row*SAB + c16*16);
      asm volatile("cp.async.ca.shared.global [%0], [%1], 16, %2;"
                   :: "r"(dst), "l"(src), "r"(sz));
    }
    asm volatile("cp.async.commit_group;" ::: "memory");
  };

  float acc[4][NT4][4];
  #pragma unroll
  for (int i = 0; i < 4; i++)
    #pragma unroll
    for (int j = 0; j < NT4; j++)
      #pragma unroll
      for (int q = 0; q < 4; q++) acc[i][j][q] = 0.f;

  issue(0, 0);

  #pragma unroll 1
  for (int t = 0; t < NCH; t++){
    const int buf = t & 1;
    if (t + 1 < NCH){
      issue(t + 1, buf ^ 1);
      asm volatile("cp.async.wait_group 1;" ::: "memory");
    } else {
      asm volatile("cp.async.wait_group 0;" ::: "memory");
    }
    __syncthreads();

    char* base = smraw + buf*BUFB;
    const int nsub = (K - t*KC >= KC) ? 2 : 1;
    #pragma unroll
    for (int sub = 0; sub < 2; sub++){
      if (sub >= nsub) break;
      const int tk = sub*16;
      uint32_t afh[4][4], afl[4][4];
      #pragma unroll
      for (int i = 0; i < 4; i++){
        int row = wm*64 + i*16 + (lane & 15);
        int col = tk + (lane >> 4)*8;
        ldsm_x4(afh[i][0], afh[i][1], afh[i][2], afh[i][3],
                smem_u32(base + OAH + row*SAB + col*2));
        ldsm_x4(afl[i][0], afl[i][1], afl[i][2], afl[i][3],
                smem_u32(base + OAL + row*SAB + col*2));
      }
      uint32_t bfh[NT4][2], bfl[NT4][2];
      #pragma unroll
      for (int j = 0; j < NT4; j++){
        int l15 = lane & 15;
        int row = wn*WN + j*8 + (l15 & 7);
        int col = tk + (l15 >> 3)*8;
        ldsm_x2(bfh[j][0], bfh[j][1], smem_u32(base + OBH + row*SAB + col*2));
        ldsm_x2(bfl[j][0], bfl[j][1], smem_u32(base + OBL + row*SAB + col*2));
      }
      #pragma unroll
      for (int i = 0; i < 4; i++)
        #pragma unroll
        for (int j = 0; j < NT4; j++){
          mma_bf16(acc[i][j], afh[i], bfh[j]);
          mma_bf16(acc[i][j], afh[i], bfl[j]);
          mma_bf16(acc[i][j], afl[i], bfh[j]);
        }
    }
    __syncthreads();
  }

  // ---- coalesced epilogue via SMEM staging
  float* S = reinterpret_cast<float*>(smraw);
  const int g = lane >> 2, tig = lane & 3;
  constexpr int CG = (STAGE==2) ? 48 : 64;   // columns per pass
  constexpr int NP = BN / CG;                // 2 passes

  #pragma unroll 1
  for (int p = 0; p < NP; p++){
    if ((wn >> 1) == p){
      #pragma unroll
      for (int i = 0; i < 4; i++)
        #pragma unroll
        for (int j = 0; j < NT4; j++)
          #pragma unroll
          for (int h = 0; h < 2; h++)
            #pragma unroll
            for (int e = 0; e < 2; e++){
              int row = wm*64 + i*16 + g + h*8;
              int lc  = (wn & 1)*WN + j*8 + tig*2 + e;
              S[lc*129 + row] = acc[i][j][h*2 + e];
            }
    }
    __syncthreads();
    for (int idx = tid; idx < CG*128; idx += 256){
      int m = idx / CG, cc = idx % CG;
      float val = S[cc*129 + m];
      if constexpr (STAGE==2){
        int gc = n0 + p*CG + cc;
        if (gc < 276){
          int r = gc/69, v = gc - r*69;
          long dst = (long)((b*4 + r)*128 + m)*144 + mt*72 + v;
          split_bf(val, g_UAh[dst], g_UAl[dst]);
        }
      } else {
        int rr = z & 3, bb = z >> 2;
        int gc = p*CG + cc;
        outp[(long)bb*65536 + (2*m + (rr >> 1))*256 + 2*gc + (rr & 1)] = val;
      }
    }
    __syncthreads();
  }
}

// ===================== launch ===============================================
extern "C" void kernel_launch(void* const* d_in, const int* in_sizes, int n_in,
                              void* d_out, int out_size)
{
  const float* x = (const float*)d_in[0];
  const float* w = (const float*)(n_in > 1 ? d_in[1] : d_in[0]);
  const float* bias = (const float*)(n_in > 2 ? d_in[2] : d_in[0]);
  for (int i = 0; i < n_in; i++){
    if (in_sizes[i] == 4*64*128*128) x = (const float*)d_in[i];
    else if (in_sizes[i] == 64*25)   w = (const float*)d_in[i];
    else if (in_sizes[i] == 64)      bias = (const float*)d_in[i];
  }
  float* out = (float*)d_out;

  // dynamic-smem opt-in (non-stream call; legal during graph capture)
  constexpr int SM2 = 2*(2*128*80 + 2*96*80);    // 71680
  constexpr int SM3 = 2*(2*128*80 + 2*128*80);   // 81920
  cudaFuncSetAttribute(mma_k<2>, cudaFuncAttributeMaxDynamicSharedMemorySize, SM2);
  cudaFuncSetAttribute(mma_k<3>, cudaFuncAttributeMaxDynamicSharedMemorySize, SM3);

  k_tw  <<<1, 272>>>();
  k_MB1 <<<(272*128+255)/256, 256>>>();
  k_MB2 <<<(256*138+255)/256, 256>>>();
  k_MI1b<<<(256*272+255)/256, 256>>>();
  k_MI2b<<<(128*144+255)/256, 256>>>();
  k_H   <<<(64*136*69+255)/256, 256>>>(w, bias);

  gemm_k<0><<<dim3(2,5,256), 256>>>(x);     // T  = MB1 * x
  gemm_k<1><<<dim3(3,3,256), 256>>>(x);     // Yt = (T * MB2)^T
  k_Z   <<<dim3(69,256), 160>>>();          // Z  = Y .* H (split bf16, K-major)

  mma_k<2><<<dim3(3,2,256), 256, SM2>>>(out);   // U  -> g_UA (split bf16)
  mma_k<3><<<dim3(1024,1,1), 256, SM3>>>(out);  // out via Hermitian-folded DFT
}

// round 7
// speedup vs baseline: 3.2201x; 1.0158x over previous
#include <cuda_runtime.h>
#include <cuda_bf16.h>
#include <math.h>
#include <cstdint>

#define PI_F 3.14159265358979323846f

// ===================== helpers ==============================================
__device__ __forceinline__ uint32_t smem_u32(const void* p){
  uint32_t a;
  asm("{ .reg .u64 t; cvta.to.shared.u64 t, %1; cvt.u32.u64 %0, t; }"
      : "=r"(a) : "l"(p));
  return a;
}
__device__ __forceinline__ void ldsm_x4(uint32_t &r0, uint32_t &r1,
                                        uint32_t &r2, uint32_t &r3, uint32_t addr){
  asm volatile("ldmatrix.sync.aligned.m8n8.x4.shared.b16 {%0,%1,%2,%3}, [%4];"
               : "=r"(r0), "=r"(r1), "=r"(r2), "=r"(r3) : "r"(addr));
}
__device__ __forceinline__ void ldsm_x2(uint32_t &r0, uint32_t &r1, uint32_t addr){
  asm volatile("ldmatrix.sync.aligned.m8n8.x2.shared.b16 {%0,%1}, [%2];"
               : "=r"(r0), "=r"(r1) : "r"(addr));
}
__device__ __forceinline__ void mma_bf16(float d[4], const uint32_t a[4],
                                         const uint32_t b[2]){
  asm volatile("mma.sync.aligned.m16n8k16.row.col.f32.bf16.bf16.f32 "
    "{%0,%1,%2,%3}, {%4,%5,%6,%7}, {%8,%9}, {%0,%1,%2,%3};"
    : "+f"(d[0]), "+f"(d[1]), "+f"(d[2]), "+f"(d[3])
    : "r"(a[0]), "r"(a[1]), "r"(a[2]), "r"(a[3]), "r"(b[0]), "r"(b[1]));
}
__device__ __forceinline__ unsigned long long ffma2(unsigned long long a,
                                                    unsigned long long b,
                                                    unsigned long long c){
  unsigned long long d;
  asm("fma.rn.f32x2 %0, %1, %2, %3;" : "=l"(d) : "l"(a), "l"(b), "l"(c));
  return d;
}
__device__ __forceinline__ unsigned long long dup2(float v){
  unsigned long long d; unsigned int u = __float_as_uint(v);
  asm("mov.b64 %0, {%1, %1};" : "=l"(d) : "r"(u));
  return d;
}
__device__ __forceinline__ float2 cmulf(float2 a, float2 b){
  return make_float2(a.x*b.x - a.y*b.y, a.x*b.y + a.y*b.x);
}
__device__ __forceinline__ void split_bf(float f, __nv_bfloat16 &h, __nv_bfloat16 &l){
  h = __float2bfloat16(f);
  l = __float2bfloat16(f - __bfloat162float(h));
}
__device__ __forceinline__ void fold_cs(int u, int ip, float &sumc, float &sumns){
  sumc = 0.f; sumns = 0.f;
  int iv[3]; int n = 0;
  iv[n++] = ip + 4;
  if (ip >= 124) iv[n++] = ip - 124;
  if (ip <= 3)   iv[n++] = ip + 132;
  for (int t = 0; t < n; t++){
    int m = (u * iv[t]) % 136;
    float s, c;
    sincosf((2.f*PI_F/136.f) * (float)m, &s, &c);
    sumc += c; sumns -= s;
  }
}

// ===================== persistent scratch ===================================
static __device__ float  g_T [256*272*128];
static __device__ float  g_Yt[256*138*136];                 // [b][n 138][u 136]
static __device__ float2 g_H [64*4*69*136];                 // [c][r][kw][kh]
static __device__ __align__(16) __nv_bfloat16 g_Zh[256*276*272];
static __device__ __align__(16) __nv_bfloat16 g_Zl[256*276*272];
static __device__ __align__(16) __nv_bfloat16 g_UAh[1024*128*144];
static __device__ __align__(16) __nv_bfloat16 g_UAl[1024*128*144];
static __device__ float  g_MB1[272*128];
static __device__ float  g_MB2[256*138];
static __device__ __align__(16) __nv_bfloat16 g_MI1h[256*272];
static __device__ __align__(16) __nv_bfloat16 g_MI1l[256*272];
static __device__ __align__(16) __nv_bfloat16 g_MI2h[128*144];
static __device__ __align__(16) __nv_bfloat16 g_MI2l[128*144];
static __device__ float2 g_tw[272];

// ===================== merged builder =======================================
// ranges: [0,272) tw | MB1 34816 | MB2 35328 | MI1 69632 | MI2 18432
__global__ void k_build(){
  int idx = blockIdx.x*blockDim.x + threadIdx.x;
  if (idx < 272){
    float s, c; sincosf((2.f*PI_F/272.f)*(float)idx, &s, &c);
    g_tw[idx] = make_float2(c, s);
    return;
  }
  int i1 = idx - 272;
  if (i1 < 272*128){
    int col = i1 % 128, row = i1 / 128;
    int u = (row < 136) ? row : row - 136;
    float sc, sn; fold_cs(u, col, sc, sn);
    g_MB1[i1] = (row < 136) ? sc : sn;
    return;
  }
  int i2 = i1 - 272*128;
  if (i2 < 256*138){
    int n = i2 % 138, k = i2 / 138;
    int v  = (n < 69) ? n : n - 69;
    int jp = (k < 128) ? k : k - 128;
    float sc, sn; fold_cs(v, jp, sc, sn);
    float val;
    if (n < 69) val = (k < 128) ? sc : -sn;
    else        val = (k < 128) ? sn :  sc;
    g_MB2[i2] = val;
    return;
  }
  int i3 = i2 - 256*138;
  if (i3 < 256*272){
    int k = i3 % 272, row = i3 / 272;
    int m   = (row & 127) + 4;
    int kap = (k < 136) ? k : k - 136;
    int a = (m * kap) % 136;
    float s, c; sincosf((2.f*PI_F/136.f)*(float)a, &s, &c);
    float val;
    if (row < 128) val = (k < 136) ?  c : -s;
    else           val = (k < 136) ?  s :  c;
    split_bf(val, g_MI1h[i3], g_MI1l[i3]);
    return;
  }
  int i4 = i3 - 256*272;
  if (i4 < 128*144){
    int kap = i4 % 144, n = i4 / 144;
    int part = (kap >= 72);
    int v = kap - (part ? 72 : 0);
    float val = 0.f;
    if (v < 69){
      float mult = (v == 0 || v == 68) ? 1.f : 2.f;
      int a = ((n + 4) * v) % 136;
      float s, c; sincosf((2.f*PI_F/136.f)*(float)a, &s, &c);
      val = part ? (-mult * s) : (mult * c);
    }
    split_bf(val, g_MI2h[i4], g_MI2l[i4]);
  }
}

__global__ void k_H(const float* __restrict__ w, const float* __restrict__ bias){
  int idx = blockIdx.x*blockDim.x + threadIdx.x;
  if (idx >= 64*136*69) return;
  int kw = idx % 69; int t = idx / 69; int kh = t % 136; int c = t / 136;
  float beta = 1.f/(1.f + expf(9.f - bias[c])) + 1e-5f;

  float2 bh[5], bw[5];
  #pragma unroll
  for (int a = 0; a < 5; a++){
    int mh = ((kh*(a-2)) % 272 + 272) % 272;
    float2 th = g_tw[mh]; bh[a] = make_float2(th.x, -th.y);
    int mw = ((kw*(a-2)) % 272 + 272) % 272;
    float2 tw = g_tw[mw]; bw[a] = make_float2(tw.x, -tw.y);
  }
  float2 S0[5], S1[5];
  #pragma unroll
  for (int a = 0; a < 5; a++){
    float2 s0 = make_float2(0.f,0.f), s1 = make_float2(0.f,0.f);
    #pragma unroll
    for (int b = 0; b < 5; b++){
      float wv = w[c*25 + a*5 + b];
      float tx = wv*bw[b].x, ty = wv*bw[b].y;
      s0.x += tx; s0.y += ty;
      if (b & 1){ s1.x -= tx; s1.y -= ty; } else { s1.x += tx; s1.y += ty; }
    }
    S0[a] = s0; S1[a] = s1;
  }
  float2 tph = g_tw[kh];
  float2 ph = make_float2(tph.x, -tph.y);
  float2 tpw = g_tw[kw];
  float2 pw = make_float2(tpw.x, -tpw.y);

  float2 FB[4], G[4];
  float2 Asum = make_float2(0.f,0.f);
  float  invW = 0.f;
  #pragma unroll
  for (int p = 0; p < 2; p++){
    #pragma unroll
    for (int q = 0; q < 2; q++){
      int r = p*2+q;
      float2 fb = make_float2(0.f,0.f);
      #pragma unroll
      for (int a = 0; a < 5; a++){
        float2 S = q ? S1[a] : S0[a];
        float2 term = cmulf(bh[a], S);
        if (p && (a & 1)) { term.x = -term.x; term.y = -term.y; }
        fb.x += term.x; fb.y += term.y;
      }
      FB[r] = fb;
      float2 f1 = make_float2(1.f + (p ? -ph.x : ph.x), (p ? -ph.y : ph.y));
      float2 f2 = make_float2(1.f + (q ? -pw.x : pw.x), (q ? -pw.y : pw.y));
      float2 box = cmulf(f1, f2);
      float2 g = make_float2(fb.x + beta*box.x, -fb.y + beta*box.y);
      G[r] = g;
      float2 ag = cmulf(fb, g);
      Asum.x += ag.x; Asum.y += ag.y;
      invW += fb.x*fb.x + fb.y*fb.y;
    }
  }
  Asum.x *= 0.25f; Asum.y *= 0.25f; invW *= 0.25f;
  float dinv = 1.f/(invW + beta);
  float2 tt = make_float2(Asum.x*dinv, Asum.y*dinv);
  float invb = 1.f/beta;
  float2 Hm[4];
  #pragma unroll
  for (int r = 0; r < 4; r++){
    float2 cf = make_float2(FB[r].x, -FB[r].y);
    float2 ct = cmulf(cf, tt);
    Hm[r] = make_float2((G[r].x - ct.x)*invb, (G[r].y - ct.y)*invb);
  }
  const float scale = 1.f/73984.f;
  float2 twh = make_float2(ph.x, -ph.y);
  float2 tww = make_float2(pw.x, -pw.y);
  #pragma unroll
  for (int rh = 0; rh < 2; rh++){
    #pragma unroll
    for (int rw = 0; rw < 2; rw++){
      float2 s = make_float2(0.f,0.f);
      #pragma unroll
      for (int p = 0; p < 2; p++)
        #pragma unroll
        for (int q = 0; q < 2; q++){
          float sg = ((p*rh + q*rw) & 1) ? -1.f : 1.f;
          s.x += sg*Hm[p*2+q].x; s.y += sg*Hm[p*2+q].y;
        }
      float2 tw = make_float2(1.f, 0.f);
      if (rh) tw = twh;
      if (rw) tw = cmulf(tw, tww);
      float2 o = cmulf(s, tw);
      o.x *= scale; o.y *= scale;
      g_H[((c*4 + rh*2 + rw)*69 + kw)*136 + kh] = o;
    }
  }
}

// ===================== Z = Y .* H, split-bf16, K-major ======================
__global__ void k_Z(){
  int kw = blockIdx.x;             // [0,69)
  int b  = blockIdx.y;             // [0,256)
  int kh = threadIdx.x;
  if (kh >= 136) return;
  int c = b & 63;
  float yr = g_Yt[(b*138 + kw)*136 + kh];
  float yi = g_Yt[(b*138 + 69 + kw)*136 + kh];
  #pragma unroll
  for (int r = 0; r < 4; r++){
    float2 h = g_H[((c*4+r)*69 + kw)*136 + kh];
    float zr = yr*h.x - yi*h.y;
    float zi = yr*h.y + yi*h.x;
    int n = r*69 + kw;
    long base = (long)(b*276 + n)*272;
    split_bf(zr, g_Zh[base + kh],       g_Zl[base + kh]);
    split_bf(zi, g_Zh[base + 136 + kh], g_Zl[base + 136 + kh]);
  }
}

// ===================== FFMA2 GEMM (stages 0,1) ==============================
template<int STAGE>
__global__ __launch_bounds__(256) void gemm_k(const float* __restrict__ xin)
{
  constexpr int K = (STAGE==0)?128 : 256;
  constexpr int BM = 64, TM = 4, TP = 2;

  __shared__ __align__(16) float As[2][16][BM];
  __shared__ __align__(16) float Bs[2][16][64];

  const int z = blockIdx.z;
  const int tid = threadIdx.x, tx = tid & 15, ty = tid >> 4;
  const int m0 = blockIdx.y*BM, n0 = blockIdx.x*64;

  auto fetchA = [&](int gm, int gk)->float{
    if constexpr (STAGE==0){
      return (gm < 272) ? g_MB1[gm*128 + gk] : 0.f;
    } else {
      if (gm >= 136) return 0.f;
      const float* T = g_T + z*34816;
      return (gk < 128) ? T[gm*128 + gk] : T[(136+gm)*128 + (gk-128)];
    }
  };
  auto fetchB = [&](int gk, int gn)->float{
    if constexpr (STAGE==0) return xin[z*16384 + gk*128 + gn];
    else                    return (gn < 138) ? g_MB2[gk*138 + gn] : 0.f;
  };
  auto storeC = [&](int gm, int gn, float v){
    if constexpr (STAGE==0){ if (gm < 272) g_T[z*34816 + gm*128 + gn] = v; }
    else { if (gm < 136 && gn < 138) g_Yt[(z*138 + gn)*136 + gm] = v; }
  };

  float ra[4]; float rb[4];
  auto loadAB = [&](int kk){
    int m = tid >> 2, kg = (tid & 3)*4;
    int gm = m0 + m;
    #pragma unroll
    for (int d = 0; d < 4; d++) ra[d] = fetchA(gm, kk + kg + d);
    int kb = tid >> 4, nx = (tid & 15)*4;
    #pragma unroll
    for (int d = 0; d < 4; d++) rb[d] = fetchB(kk + kb, n0 + nx + d);
  };
  auto storeAB = [&](int buf){
    int m = tid >> 2, kg = (tid & 3)*4;
    #pragma unroll
    for (int d = 0; d < 4; d++) As[buf][kg+d][m] = ra[d];
    int kb = tid >> 4, nx = (tid & 15)*4;
    #pragma unroll
    for (int d = 0; d < 4; d++) Bs[buf][kb][nx+d] = rb[d];
  };

  unsigned long long acc[TP][4] = {};
  constexpr int NT = K/16;
  loadAB(0); storeAB(0); __syncthreads();

  #pragma unroll 1
  for (int t = 0; t < NT; t++){
    int buf = t & 1;
    if (t + 1 < NT) loadAB((t+1)*16);
    #pragma unroll
    for (int k = 0; k < 16; k++){
      ulonglong2 v0 = *reinterpret_cast<const ulonglong2*>(&As[buf][k][ty*TM]);
      unsigned long long ap[2] = {v0.x, v0.y};
      float4 bq = *reinterpret_cast<const float4*>(&Bs[buf][k][tx*4]);
      unsigned long long bd0 = dup2(bq.x), bd1 = dup2(bq.y);
      unsigned long long bd2 = dup2(bq.z), bd3 = dup2(bq.w);
      #pragma unroll
      for (int p = 0; p < TP; p++){
        acc[p][0] = ffma2(ap[p], bd0, acc[p][0]);
        acc[p][1] = ffma2(ap[p], bd1, acc[p][1]);
        acc[p][2] = ffma2(ap[p], bd2, acc[p][2]);
        acc[p][3] = ffma2(ap[p], bd3, acc[p][3]);
      }
    }
    if (t + 1 < NT){ storeAB(buf ^ 1); __syncthreads(); }
  }

  union { unsigned long long u; float2 f; } pun;
  #pragma unroll
  for (int p = 0; p < TP; p++){
    int gmA = m0 + ty*TM + 2*p;
    #pragma unroll
    for (int j = 0; j < 4; j++){
      int gn = n0 + tx*4 + j;
      pun.u = acc[p][j];
      storeC(gmA,     gn, pun.f.x);
      storeC(gmA + 1, gn, pun.f.y);
    }
  }
}

// ===================== HMMA split-bf16 GEMM, cp.async KC=32 pipeline ========
// STAGE 2: U(256x276) = MI1(256x272) * Z_b(276x272)^T  -> g_UA split bf16
// STAGE 3: out = UA_z(128x144) * MI2(128x144)^T -> d_out interleaved
template<int STAGE>
__global__ __launch_bounds__(256) void mma_k(float* __restrict__ outp)
{
  constexpr int BN  = (STAGE==2) ? 96 : 128;
  constexpr int K   = (STAGE==2) ? 272 : 144;
  constexpr int KC  = 32;
  constexpr int NCH = (K + KC - 1)/KC;       // 9 or 5
  constexpr int SAB = 80;                    // smem row stride bytes (40 elems)
  constexpr int NT4 = BN/32;                 // 3 or 4
  constexpr int WN  = BN/4;                  // 24 or 32
  constexpr int ABY = 128*SAB;               // per hl matrix
  constexpr int BBY = BN*SAB;
  constexpr int OAH = 0, OAL = ABY, OBH = 2*ABY, OBL = 2*ABY + BBY;
  constexpr int BUFB = 2*ABY + 2*BBY;

  extern __shared__ __align__(16) char smraw[];

  const int tid = threadIdx.x, lane = tid & 31, wid = tid >> 5;
  const int wm = wid & 1, wn = wid >> 1;

  int b = 0, n0 = 0, z = 0, mt = 0;
  const __nv_bfloat16 *Ahs, *Als, *Bhs, *Bls;
  if constexpr (STAGE==2){
    b = blockIdx.z; mt = blockIdx.y; n0 = blockIdx.x*96;
    Ahs = g_MI1h + mt*128*272; Als = g_MI1l + mt*128*272;
    Bhs = g_Zh + (long)b*276*272; Bls = g_Zl + (long)b*276*272;
  } else {
    z = blockIdx.x;
    Ahs = g_UAh + (long)z*128*144; Als = g_UAl + (long)z*128*144;
    Bhs = g_MI2h; Bls = g_MI2l;
  }

  auto issue = [&](int t, int buf){
    const int kk = t*KC;
    char* base = smraw + buf*BUFB;
    #pragma unroll
    for (int it = 0; it < 4; it++){
      int cid = tid + it*256;
      int hl = cid >> 9, rem = cid & 511;
      int row = rem >> 2, c16 = rem & 3;
      int gk = kk + c16*8;
      int sz = (gk + 8 <= K) ? 16 : 0;
      const __nv_bfloat16* src = (hl ? Als : Ahs) + (long)row*K + (sz ? gk : 0);
      uint32_t dst = smem_u32(base + (hl ? OAL : OAH) + row*SAB + c16*16);
      asm volatile("cp.async.ca.shared.global [%0], [%1], 16, %2;"
                   :: "r"(dst), "l"(src), "r"(sz));
    }
    constexpr int BCH = BN*8;
    #pragma unroll
    for (int it = 0; it < BCH/256; it++){
      int cid = tid + it*256;
      int hl = (cid >= BCH/2), rem = cid % (BCH/2);
      int row = rem >> 2, c16 = rem & 3;
      int gk = kk + c16*8;
      int grow = row;
      int sz = (gk + 8 <= K) ? 16 : 0;
      if constexpr (STAGE==2){
        grow = n0 + row;
        if (grow >= 276){ grow = 275; sz = 0; }
      }
      const __nv_bfloat16* src = (hl ? Bls : Bhs) + (long)grow*K + (sz ? gk : 0);
      uint32_t dst = smem_u32(base + (hl ? OBL : OBH) + row*SAB + c16*16);
      asm volatile("cp.async.ca.shared.global [%0], [%1], 16, %2;"
                   :: "r"(dst), "l"(src), "r"(sz));
    }
    asm volatile("cp.async.commit_group;" ::: "memory");
  };

  float acc[4][NT4][4];
  #pragma unroll
  for (int i = 0; i < 4; i++)
    #pragma unroll
    for (int j = 0; j < NT4; j++)
      #pragma unroll
      for (int q = 0; q < 4; q++) acc[i][j][q] = 0.f;

  issue(0, 0);

  #pragma unroll 1
  for (int t = 0; t < NCH; t++){
    const int buf = t & 1;
    if (t + 1 < NCH){
      issue(t + 1, buf ^ 1);
      asm volatile("cp.async.wait_group 1;" ::: "memory");
    } else {
      asm volatile("cp.async.wait_group 0;" ::: "memory");
    }
    __syncthreads();

    char* base = smraw + buf*BUFB;
    const int nsub = (K - t*KC >= KC) ? 2 : 1;
    #pragma unroll
    for (int sub = 0; sub < 2; sub++){
      if (sub >= nsub) break;
      const int tk = sub*16;
      uint32_t afh[4][4], afl[4][4];
      #pragma unroll
      for (int i = 0; i < 4; i++){
        int row = wm*64 + i*16 + (lane & 15);
        int col = tk + (lane >> 4)*8;
        ldsm_x4(afh[i][0], afh[i][1], afh[i][2], afh[i][3],
                smem_u32(base + OAH + row*SAB + col*2));
        ldsm_x4(afl[i][0], afl[i][1], afl[i][2], afl[i][3],
                smem_u32(base + OAL + row*SAB + col*2));
      }
      // B fragments: paired x4 loads (two n8 tiles per ldmatrix.x4)
      uint32_t bfh[NT4][2], bfl[NT4][2];
      if constexpr (NT4 == 4){
        #pragma unroll
        for (int j0 = 0; j0 < 4; j0 += 2){
          int q = lane >> 3;
          int row = wn*WN + (j0 + (q >> 1))*8 + (lane & 7);
          int col = tk + (q & 1)*8;
          ldsm_x4(bfh[j0][0], bfh[j0][1], bfh[j0+1][0], bfh[j0+1][1],
                  smem_u32(base + OBH + row*SAB + col*2));
          ldsm_x4(bfl[j0][0], bfl[j0][1], bfl[j0+1][0], bfl[j0+1][1],
                  smem_u32(base + OBL + row*SAB + col*2));
        }
      } else {
        {
          int q = lane >> 3;
          int row = wn*WN + (q >> 1)*8 + (lane & 7);
          int col = tk + (q & 1)*8;
          ldsm_x4(bfh[0][0], bfh[0][1], bfh[1][0], bfh[1][1],
                  smem_u32(base + OBH + row*SAB + col*2));
          ldsm_x4(bfl[0][0], bfl[0][1], bfl[1][0], bfl[1][1],
                  smem_u32(base + OBL + row*SAB + col*2));
        }
        {
          int l15 = lane & 15;
          int row = wn*WN + 16 + (l15 & 7);
          int col = tk + (l15 >> 3)*8;
          ldsm_x2(bfh[2][0], bfh[2][1], smem_u32(base + OBH + row*SAB + col*2));
          ldsm_x2(bfl[2][0], bfl[2][1], smem_u32(base + OBL + row*SAB + col*2));
        }
      }
      #pragma unroll
      for (int i = 0; i < 4; i++)
        #pragma unroll
        for (int j = 0; j < NT4; j++){
          mma_bf16(acc[i][j], afh[i], bfh[j]);
          mma_bf16(acc[i][j], afh[i], bfl[j]);
          mma_bf16(acc[i][j], afl[i], bfh[j]);
        }
    }
    __syncthreads();
  }

  // ---- coalesced epilogue via SMEM staging
  float* S = reinterpret_cast<float*>(smraw);
  const int g = lane >> 2, tig = lane & 3;
  constexpr int CG = (STAGE==2) ? 48 : 64;   // columns per pass
  constexpr int NP = BN / CG;                // 2 passes

  #pragma unroll 1
  for (int p = 0; p < NP; p++){
    if ((wn >> 1) == p){
      #pragma unroll
      for (int i = 0; i < 4; i++)
        #pragma unroll
        for (int j = 0; j < NT4; j++)
          #pragma unroll
          for (int h = 0; h < 2; h++)
            #pragma unroll
            for (int e = 0; e < 2; e++){
              int row = wm*64 + i*16 + g + h*8;
              int lc  = (wn & 1)*WN + j*8 + tig*2 + e;
              S[lc*129 + row] = acc[i][j][h*2 + e];
            }
    }
    __syncthreads();
    for (int idx = tid; idx < CG*128; idx += 256){
      int m = idx / CG, cc = idx % CG;
      float val = S[cc*129 + m];
      if constexpr (STAGE==2){
        int gc = n0 + p*CG + cc;
        if (gc < 276){
          int r = gc/69, v = gc - r*69;
          long dst = (long)((b*4 + r)*128 + m)*144 + mt*72 + v;
          split_bf(val, g_UAh[dst], g_UAl[dst]);
        }
      } else {
        int rr = z & 3, bb = z >> 2;
        int gc = p*CG + cc;
        outp[(long)bb*65536 + (2*m + (rr >> 1))*256 + 2*gc + (rr & 1)] = val;
      }
    }
    __syncthreads();
  }
}

// ===================== launch ===============================================
extern "C" void kernel_launch(void* const* d_in, const int* in_sizes, int n_in,
                              void* d_out, int out_size)
{
  const float* x = (const float*)d_in[0];
  const float* w = (const float*)(n_in > 1 ? d_in[1] : d_in[0]);
  const float* bias = (const float*)(n_in > 2 ? d_in[2] : d_in[0]);
  for (int i = 0; i < n_in; i++){
    if (in_sizes[i] == 4*64*128*128) x = (const float*)d_in[i];
    else if (in_sizes[i] == 64*25)   w = (const float*)d_in[i];
    else if (in_sizes[i] == 64)      bias = (const float*)d_in[i];
  }
  float* out = (float*)d_out;

  constexpr int SM2 = 2*(2*128*80 + 2*96*80);    // 71680
  constexpr int SM3 = 2*(2*128*80 + 2*128*80);   // 81920
  cudaFuncSetAttribute(mma_k<2>, cudaFuncAttributeMaxDynamicSharedMemorySize, SM2);
  cudaFuncSetAttribute(mma_k<3>, cudaFuncAttributeMaxDynamicSharedMemorySize, SM3);

  // launch order matters for ncu (-s 5 -c 1 captures launch #6 = mma_k<2>)
  k_build<<<(158480+255)/256, 256>>>();         // #1: all constant tables
  k_H   <<<(64*136*69+255)/256, 256>>>(w, bias);// #2
  gemm_k<0><<<dim3(2,5,256), 256>>>(x);         // #3: T  = MB1 * x
  gemm_k<1><<<dim3(3,3,256), 256>>>(x);         // #4: Yt = (T * MB2)^T
  k_Z   <<<dim3(69,256), 160>>>();              // #5: Z  = Y .* H
  mma_k<2><<<dim3(3,2,256), 256, SM2>>>(out);   // #6: U  -> g_UA
  mma_k<3><<<dim3(1024,1,1), 256, SM3>>>(out);  // #7: out
}

// round 8
// speedup vs baseline: 3.5789x; 1.1114x over previous
#include <cuda_runtime.h>
#include <cuda_bf16.h>
#include <math.h>
#include <cstdint>

#define PI_F 3.14159265358979323846f

// ===================== helpers ==============================================
__device__ __forceinline__ uint32_t smem_u32(const void* p){
  uint32_t a;
  asm("{ .reg .u64 t; cvta.to.shared.u64 t, %1; cvt.u32.u64 %0, t; }"
      : "=r"(a) : "l"(p));
  return a;
}
__device__ __forceinline__ void ldsm_x4(uint32_t &r0, uint32_t &r1,
                                        uint32_t &r2, uint32_t &r3, uint32_t addr){
  asm volatile("ldmatrix.sync.aligned.m8n8.x4.shared.b16 {%0,%1,%2,%3}, [%4];"
               : "=r"(r0), "=r"(r1), "=r"(r2), "=r"(r3) : "r"(addr));
}
__device__ __forceinline__ void ldsm_x2(uint32_t &r0, uint32_t &r1, uint32_t addr){
  asm volatile("ldmatrix.sync.aligned.m8n8.x2.shared.b16 {%0,%1}, [%2];"
               : "=r"(r0), "=r"(r1) : "r"(addr));
}
__device__ __forceinline__ void mma_bf16(float d[4], const uint32_t a[4],
                                         const uint32_t b[2]){
  asm volatile("mma.sync.aligned.m16n8k16.row.col.f32.bf16.bf16.f32 "
    "{%0,%1,%2,%3}, {%4,%5,%6,%7}, {%8,%9}, {%0,%1,%2,%3};"
    : "+f"(d[0]), "+f"(d[1]), "+f"(d[2]), "+f"(d[3])
    : "r"(a[0]), "r"(a[1]), "r"(a[2]), "r"(a[3]), "r"(b[0]), "r"(b[1]));
}
__device__ __forceinline__ unsigned long long ffma2(unsigned long long a,
                                                    unsigned long long b,
                                                    unsigned long long c){
  unsigned long long d;
  asm("fma.rn.f32x2 %0, %1, %2, %3;" : "=l"(d) : "l"(a), "l"(b), "l"(c));
  return d;
}
__device__ __forceinline__ unsigned long long dup2(float v){
  unsigned long long d; unsigned int u = __float_as_uint(v);
  asm("mov.b64 %0, {%1, %1};" : "=l"(d) : "r"(u));
  return d;
}
__device__ __forceinline__ float2 cmulf(float2 a, float2 b){
  return make_float2(a.x*b.x - a.y*b.y, a.x*b.y + a.y*b.x);
}
__device__ __forceinline__ void split_bf(float f, __nv_bfloat16 &h, __nv_bfloat16 &l){
  h = __float2bfloat16(f);
  l = __float2bfloat16(f - __bfloat162float(h));
}
__device__ __forceinline__ void fold_cs(int u, int ip, float &sumc, float &sumns){
  sumc = 0.f; sumns = 0.f;
  int iv[3]; int n = 0;
  iv[n++] = ip + 4;
  if (ip >= 124) iv[n++] = ip - 124;
  if (ip <= 3)   iv[n++] = ip + 132;
  for (int t = 0; t < n; t++){
    int m = (u * iv[t]) % 136;
    float s, c;
    sincosf((2.f*PI_F/136.f) * (float)m, &s, &c);
    sumc += c; sumns -= s;
  }
}

// ===================== persistent scratch ===================================
static __device__ float  g_T [256*136*256];                 // Tsp[(b*136+u)][256]
static __device__ float  g_Yt[256*138*136];                 // [b][n 138][u 136]
static __device__ float2 g_H [64*4*69*136];                 // [c][r][kw][kh]
static __device__ __align__(16) __nv_bfloat16 g_Zh[256*276*272];
static __device__ __align__(16) __nv_bfloat16 g_Zl[256*276*272];
static __device__ __align__(16) __nv_bfloat16 g_UAh[1024*128*144];
static __device__ __align__(16) __nv_bfloat16 g_UAl[1024*128*144];
static __device__ float  g_MB1[272*128];
static __device__ float  g_MB2[256*138];
static __device__ __align__(16) __nv_bfloat16 g_MI1h[256*272];
static __device__ __align__(16) __nv_bfloat16 g_MI1l[256*272];
static __device__ __align__(16) __nv_bfloat16 g_MI2h[128*144];
static __device__ __align__(16) __nv_bfloat16 g_MI2l[128*144];
static __device__ float2 g_tw[272];

// ===================== merged builder =======================================
__global__ void k_build(){
  int idx = blockIdx.x*blockDim.x + threadIdx.x;
  if (idx < 272){
    float s, c; sincosf((2.f*PI_F/272.f)*(float)idx, &s, &c);
    g_tw[idx] = make_float2(c, s);
    return;
  }
  int i1 = idx - 272;
  if (i1 < 272*128){
    int col = i1 % 128, row = i1 / 128;
    int u = (row < 136) ? row : row - 136;
    float sc, sn; fold_cs(u, col, sc, sn);
    g_MB1[i1] = (row < 136) ? sc : sn;
    return;
  }
  int i2 = i1 - 272*128;
  if (i2 < 256*138){
    int n = i2 % 138, k = i2 / 138;
    int v  = (n < 69) ? n : n - 69;
    int jp = (k < 128) ? k : k - 128;
    float sc, sn; fold_cs(v, jp, sc, sn);
    float val;
    if (n < 69) val = (k < 128) ? sc : -sn;
    else        val = (k < 128) ? sn :  sc;
    g_MB2[i2] = val;
    return;
  }
  int i3 = i2 - 256*138;
  if (i3 < 256*272){
    int k = i3 % 272, row = i3 / 272;
    int m   = (row & 127) + 4;
    int kap = (k < 136) ? k : k - 136;
    int a = (m * kap) % 136;
    float s, c; sincosf((2.f*PI_F/136.f)*(float)a, &s, &c);
    float val;
    if (row < 128) val = (k < 136) ?  c : -s;
    else           val = (k < 136) ?  s :  c;
    split_bf(val, g_MI1h[i3], g_MI1l[i3]);
    return;
  }
  int i4 = i3 - 256*272;
  if (i4 < 128*144){
    int kap = i4 % 144, n = i4 / 144;
    int part = (kap >= 72);
    int v = kap - (part ? 72 : 0);
    float val = 0.f;
    if (v < 69){
      float mult = (v == 0 || v == 68) ? 1.f : 2.f;
      int a = ((n + 4) * v) % 136;
      float s, c; sincosf((2.f*PI_F/136.f)*(float)a, &s, &c);
      val = part ? (-mult * s) : (mult * c);
    }
    split_bf(val, g_MI2h[i4], g_MI2l[i4]);
  }
}

__global__ void k_H(const float* __restrict__ w, const float* __restrict__ bias){
  int idx = blockIdx.x*blockDim.x + threadIdx.x;
  if (idx >= 64*136*69) return;
  int kw = idx % 69; int t = idx / 69; int kh = t % 136; int c = t / 136;
  float beta = 1.f/(1.f + expf(9.f - bias[c])) + 1e-5f;

  float2 bh[5], bw[5];
  #pragma unroll
  for (int a = 0; a < 5; a++){
    int mh = ((kh*(a-2)) % 272 + 272) % 272;
    float2 th = g_tw[mh]; bh[a] = make_float2(th.x, -th.y);
    int mw = ((kw*(a-2)) % 272 + 272) % 272;
    float2 tw = g_tw[mw]; bw[a] = make_float2(tw.x, -tw.y);
  }
  float2 S0[5], S1[5];
  #pragma unroll
  for (int a = 0; a < 5; a++){
    float2 s0 = make_float2(0.f,0.f), s1 = make_float2(0.f,0.f);
    #pragma unroll
    for (int b = 0; b < 5; b++){
      float wv = w[c*25 + a*5 + b];
      float tx = wv*bw[b].x, ty = wv*bw[b].y;
      s0.x += tx; s0.y += ty;
      if (b & 1){ s1.x -= tx; s1.y -= ty; } else { s1.x += tx; s1.y += ty; }
    }
    S0[a] = s0; S1[a] = s1;
  }
  float2 tph = g_tw[kh];
  float2 ph = make_float2(tph.x, -tph.y);
  float2 tpw = g_tw[kw];
  float2 pw = make_float2(tpw.x, -tpw.y);

  float2 FB[4], G[4];
  float2 Asum = make_float2(0.f,0.f);
  float  invW = 0.f;
  #pragma unroll
  for (int p = 0; p < 2; p++){
    #pragma unroll
    for (int q = 0; q < 2; q++){
      int r = p*2+q;
      float2 fb = make_float2(0.f,0.f);
      #pragma unroll
      for (int a = 0; a < 5; a++){
        float2 S = q ? S1[a] : S0[a];
        float2 term = cmulf(bh[a], S);
        if (p && (a & 1)) { term.x = -term.x; term.y = -term.y; }
        fb.x += term.x; fb.y += term.y;
      }
      FB[r] = fb;
      float2 f1 = make_float2(1.f + (p ? -ph.x : ph.x), (p ? -ph.y : ph.y));
      float2 f2 = make_float2(1.f + (q ? -pw.x : pw.x), (q ? -pw.y : pw.y));
      float2 box = cmulf(f1, f2);
      float2 g = make_float2(fb.x + beta*box.x, -fb.y + beta*box.y);
      G[r] = g;
      float2 ag = cmulf(fb, g);
      Asum.x += ag.x; Asum.y += ag.y;
      invW += fb.x*fb.x + fb.y*fb.y;
    }
  }
  Asum.x *= 0.25f; Asum.y *= 0.25f; invW *= 0.25f;
  float dinv = 1.f/(invW + beta);
  float2 tt = make_float2(Asum.x*dinv, Asum.y*dinv);
  float invb = 1.f/beta;
  float2 Hm[4];
  #pragma unroll
  for (int r = 0; r < 4; r++){
    float2 cf = make_float2(FB[r].x, -FB[r].y);
    float2 ct = cmulf(cf, tt);
    Hm[r] = make_float2((G[r].x - ct.x)*invb, (G[r].y - ct.y)*invb);
  }
  const float scale = 1.f/73984.f;
  float2 twh = make_float2(ph.x, -ph.y);
  float2 tww = make_float2(pw.x, -pw.y);
  #pragma unroll
  for (int rh = 0; rh < 2; rh++){
    #pragma unroll
    for (int rw = 0; rw < 2; rw++){
      float2 s = make_float2(0.f,0.f);
      #pragma unroll
      for (int p = 0; p < 2; p++)
        #pragma unroll
        for (int q = 0; q < 2; q++){
          float sg = ((p*rh + q*rw) & 1) ? -1.f : 1.f;
          s.x += sg*Hm[p*2+q].x; s.y += sg*Hm[p*2+q].y;
        }
      float2 tw = make_float2(1.f, 0.f);
      if (rh) tw = twh;
      if (rw) tw = cmulf(tw, tww);
      float2 o = cmulf(s, tw);
      o.x *= scale; o.y *= scale;
      g_H[((c*4 + rh*2 + rw)*69 + kw)*136 + kh] = o;
    }
  }
}

// ===================== Z = Y .* H, split-bf16, K-major ======================
__global__ void k_Z(){
  int kw = blockIdx.x;             // [0,69)
  int b  = blockIdx.y;             // [0,256)
  int kh = threadIdx.x;
  if (kh >= 136) return;
  int c = b & 63;
  float yr = g_Yt[(b*138 + kw)*136 + kh];
  float yi = g_Yt[(b*138 + 69 + kw)*136 + kh];
  #pragma unroll
  for (int r = 0; r < 4; r++){
    float2 h = g_H[((c*4+r)*69 + kw)*136 + kh];
    float zr = yr*h.x - yi*h.y;
    float zi = yr*h.y + yi*h.x;
    int n = r*69 + kw;
    long base = (long)(b*276 + n)*272;
    split_bf(zr, g_Zh[base + kh],       g_Zl[base + kh]);
    split_bf(zi, g_Zh[base + 136 + kh], g_Zl[base + 136 + kh]);
  }
}

// ===================== FFMA2 GEMM (stages 0,1) ==============================
// STAGE 0: Tsp[(b*136+u)][half*128+j] = MB1 * xT     (z=b, M=272, N=128, K=128)
// STAGE 1: Yt = Tsp(34816x256) * MB2(256x138), dense M, staged epilogue
template<int STAGE>
__global__ __launch_bounds__(256) void gemm_k(const float* __restrict__ xin)
{
  constexpr int K = (STAGE==0)?128 : 256;
  constexpr int BM = 64, TM = 4, TP = 2;

  __shared__ __align__(16) float As[2][16][BM];
  __shared__ __align__(16) float Bs[2][16][64];
  __shared__ __align__(16) float S[64*65];

  const int z = blockIdx.z;
  const int tid = threadIdx.x, tx = tid & 15, ty = tid >> 4;
  const int m0 = blockIdx.y*BM, n0 = blockIdx.x*64;

  auto fetchA = [&](int gm, int gk)->float{
    if constexpr (STAGE==0){
      return (gm < 272) ? g_MB1[gm*128 + gk] : 0.f;
    } else {
      return g_T[(long)gm*256 + gk];
    }
  };
  auto fetchB = [&](int gk, int gn)->float{
    if constexpr (STAGE==0) return xin[z*16384 + gk*128 + gn];
    else                    return (gn < 138) ? g_MB2[gk*138 + gn] : 0.f;
  };

  float ra[4]; float rb[4];
  auto loadAB = [&](int kk){
    int m = tid >> 2, kg = (tid & 3)*4;
    int gm = m0 + m;
    #pragma unroll
    for (int d = 0; d < 4; d++) ra[d] = fetchA(gm, kk + kg + d);
    int kb = tid >> 4, nx = (tid & 15)*4;
    #pragma unroll
    for (int d = 0; d < 4; d++) rb[d] = fetchB(kk + kb, n0 + nx + d);
  };
  auto storeAB = [&](int buf){
    int m = tid >> 2, kg = (tid & 3)*4;
    #pragma unroll
    for (int d = 0; d < 4; d++) As[buf][kg+d][m] = ra[d];
    int kb = tid >> 4, nx = (tid & 15)*4;
    #pragma unroll
    for (int d = 0; d < 4; d++) Bs[buf][kb][nx+d] = rb[d];
  };

  unsigned long long acc[TP][4] = {};
  constexpr int NT = K/16;
  loadAB(0); storeAB(0); __syncthreads();

  #pragma unroll 1
  for (int t = 0; t < NT; t++){
    int buf = t & 1;
    if (t + 1 < NT) loadAB((t+1)*16);
    #pragma unroll
    for (int k = 0; k < 16; k++){
      ulonglong2 v0 = *reinterpret_cast<const ulonglong2*>(&As[buf][k][ty*TM]);
      unsigned long long ap[2] = {v0.x, v0.y};
      float4 bq = *reinterpret_cast<const float4*>(&Bs[buf][k][tx*4]);
      unsigned long long bd0 = dup2(bq.x), bd1 = dup2(bq.y);
      unsigned long long bd2 = dup2(bq.z), bd3 = dup2(bq.w);
      #pragma unroll
      for (int p = 0; p < TP; p++){
        acc[p][0] = ffma2(ap[p], bd0, acc[p][0]);
        acc[p][1] = ffma2(ap[p], bd1, acc[p][1]);
        acc[p][2] = ffma2(ap[p], bd2, acc[p][2]);
        acc[p][3] = ffma2(ap[p], bd3, acc[p][3]);
      }
    }
    if (t + 1 < NT){ storeAB(buf ^ 1); __syncthreads(); }
  }

  union { unsigned long long u; float2 f; } pun;
  if constexpr (STAGE==0){
    #pragma unroll
    for (int p = 0; p < TP; p++){
      int gmA = m0 + ty*TM + 2*p;
      #pragma unroll
      for (int j = 0; j < 4; j++){
        int gn = n0 + tx*4 + j;
        pun.u = acc[p][j];
        #pragma unroll
        for (int e = 0; e < 2; e++){
          int gm = gmA + e;
          if (gm < 272){
            int u = (gm < 136) ? gm : gm - 136;
            int half = (gm < 136) ? 0 : 128;
            g_T[(long)(z*136 + u)*256 + half + gn] = (e ? pun.f.y : pun.f.x);
          }
        }
      }
    }
  } else {
    // staged transpose epilogue: S[n_local][m_local], then contiguous-u stores
    __syncthreads();
    #pragma unroll
    for (int p = 0; p < TP; p++){
      int mlA = ty*TM + 2*p;
      #pragma unroll
      for (int j = 0; j < 4; j++){
        int nl = tx*4 + j;
        pun.u = acc[p][j];
        S[nl*65 + mlA]     = pun.f.x;
        S[nl*65 + mlA + 1] = pun.f.y;
      }
    }
    __syncthreads();
    for (int idx = tid; idx < 64*64; idx += 256){
      int nl = idx >> 6, ml = idx & 63;
      int gn = n0 + nl;
      if (gn >= 138) continue;
      int g = m0 + ml;
      int bb = g / 136, uu = g - bb*136;
      g_Yt[((long)bb*138 + gn)*136 + uu] = S[nl*65 + ml];
    }
  }
}

// ===================== HMMA split-bf16 GEMM, cp.async KC=32 pipeline ========
template<int STAGE>
__global__ __launch_bounds__(256) void mma_k(float* __restrict__ outp)
{
  constexpr int BN  = (STAGE==2) ? 96 : 128;
  constexpr int K   = (STAGE==2) ? 272 : 144;
  constexpr int KC  = 32;
  constexpr int NCH = (K + KC - 1)/KC;
  constexpr int SAB = 80;
  constexpr int NT4 = BN/32;
  constexpr int WN  = BN/4;
  constexpr int ABY = 128*SAB;
  constexpr int BBY = BN*SAB;
  constexpr int OAH = 0, OAL = ABY, OBH = 2*ABY, OBL = 2*ABY + BBY;
  constexpr int BUFB = 2*ABY + 2*BBY;

  extern __shared__ __align__(16) char smraw[];

  const int tid = threadIdx.x, lane = tid & 31, wid = tid >> 5;
  const int wm = wid & 1, wn = wid >> 1;

  int b = 0, n0 = 0, z = 0, mt = 0;
  const __nv_bfloat16 *Ahs, *Als, *Bhs, *Bls;
  if constexpr (STAGE==2){
    b = blockIdx.z; mt = blockIdx.y; n0 = blockIdx.x*96;
    Ahs = g_MI1h + mt*128*272; Als = g_MI1l + mt*128*272;
    Bhs = g_Zh + (long)b*276*272; Bls = g_Zl + (long)b*276*272;
  } else {
    z = blockIdx.x;
    Ahs = g_UAh + (long)z*128*144; Als = g_UAl + (long)z*128*144;
    Bhs = g_MI2h; Bls = g_MI2l;
  }

  auto issue = [&](int t, int buf){
    const int kk = t*KC;
    char* base = smraw + buf*BUFB;
    #pragma unroll
    for (int it = 0; it < 4; it++){
      int cid = tid + it*256;
      int hl = cid >> 9, rem = cid & 511;
      int row = rem >> 2, c16 = rem & 3;
      int gk = kk + c16*8;
      int sz = (gk + 8 <= K) ? 16 : 0;
      const __nv_bfloat16* src = (hl ? Als : Ahs) + (long)row*K + (sz ? gk : 0);
      uint32_t dst = smem_u32(base + (hl ? OAL : OAH) + row*SAB + c16*16);
      asm volatile("cp.async.ca.shared.global [%0], [%1], 16, %2;"
                   :: "r"(dst), "l"(src), "r"(sz));
    }
    constexpr int BCH = BN*8;
    #pragma unroll
    for (int it = 0; it < BCH/256; it++){
      int cid = tid + it*256;
      int hl = (cid >= BCH/2), rem = cid % (BCH/2);
      int row = rem >> 2, c16 = rem & 3;
      int gk = kk + c16*8;
      int grow = row;
      int sz = (gk + 8 <= K) ? 16 : 0;
      if constexpr (STAGE==2){
        grow = n0 + row;
        if (grow >= 276){ grow = 275; sz = 0; }
      }
      const __nv_bfloat16* src = (hl ? Bls : Bhs) + (long)grow*K + (sz ? gk : 0);
      uint32_t dst = smem_u32(base + (hl ? OBL : OBH) + row*SAB + c16*16);
      asm volatile("cp.async.ca.shared.global [%0], [%1], 16, %2;"
                   :: "r"(dst), "l"(src), "r"(sz));
    }
    asm volatile("cp.async.commit_group;" ::: "memory");
  };

  float acc[4][NT4][4];
  #pragma unroll
  for (int i = 0; i < 4; i++)
    #pragma unroll
    for (int j = 0; j < NT4; j++)
      #pragma unroll
      for (int q = 0; q < 4; q++) acc[i][j][q] = 0.f;

  issue(0, 0);

  #pragma unroll 1
  for (int t = 0; t < NCH; t++){
    const int buf = t & 1;
    if (t + 1 < NCH){
      issue(t + 1, buf ^ 1);
      asm volatile("cp.async.wait_group 1;" ::: "memory");
    } else {
      asm volatile("cp.async.wait_group 0;" ::: "memory");
    }
    __syncthreads();

    char* base = smraw + buf*BUFB;
    const int nsub = (K - t*KC >= KC) ? 2 : 1;
    #pragma unroll
    for (int sub = 0; sub < 2; sub++){
      if (sub >= nsub) break;
      const int tk = sub*16;
      uint32_t afh[4][4], afl[4][4];
      #pragma unroll
      for (int i = 0; i < 4; i++){
        int row = wm*64 + i*16 + (lane & 15);
        int col = tk + (lane >> 4)*8;
        ldsm_x4(afh[i][0], afh[i][1], afh[i][2], afh[i][3],
                smem_u32(base + OAH + row*SAB + col*2));
        ldsm_x4(afl[i][0], afl[i][1], afl[i][2], afl[i][3],
                smem_u32(base + OAL + row*SAB + col*2));
      }
      uint32_t bfh[NT4][2], bfl[NT4][2];
      if constexpr (NT4 == 4){
        #pragma unroll
        for (int j0 = 0; j0 < 4; j0 += 2){
          int q = lane >> 3;
          int row = wn*WN + (j0 + (q >> 1))*8 + (lane & 7);
          int col = tk + (q & 1)*8;
          ldsm_x4(bfh[j0][0], bfh[j0][1], bfh[j0+1][0], bfh[j0+1][1],
                  smem_u32(base + OBH + row*SAB + col*2));
          ldsm_x4(bfl[j0][0], bfl[j0][1], bfl[j0+1][0], bfl[j0+1][1],
                  smem_u32(base + OBL + row*SAB + col*2));
        }
      } else {
        {
          int q = lane >> 3;
          int row = wn*WN + (q >> 1)*8 + (lane & 7);
          int col = tk + (q & 1)*8;
          ldsm_x4(bfh[0][0], bfh[0][1], bfh[1][0], bfh[1][1],
                  smem_u32(base + OBH + row*SAB + col*2));
          ldsm_x4(bfl[0][0], bfl[0][1], bfl[1][0], bfl[1][1],
                  smem_u32(base + OBL + row*SAB + col*2));
        }
        {
          int l15 = lane & 15;
          int row = wn*WN + 16 + (l15 & 7);
          int col = tk + (l15 >> 3)*8;
          ldsm_x2(bfh[2][0], bfh[2][1], smem_u32(base + OBH + row*SAB + col*2));
          ldsm_x2(bfl[2][0], bfl[2][1], smem_u32(base + OBL + row*SAB + col*2));
        }
      }
      #pragma unroll
      for (int i = 0; i < 4; i++)
        #pragma unroll
        for (int j = 0; j < NT4; j++){
          mma_bf16(acc[i][j], afh[i], bfh[j]);
          mma_bf16(acc[i][j], afh[i], bfl[j]);
          mma_bf16(acc[i][j], afl[i], bfh[j]);
        }
    }
    __syncthreads();
  }

  // ---- coalesced epilogue via SMEM staging
  float* S = reinterpret_cast<float*>(smraw);
  const int g = lane >> 2, tig = lane & 3;
  constexpr int CG = (STAGE==2) ? 48 : 64;
  constexpr int NP = BN / CG;

  #pragma unroll 1
  for (int p = 0; p < NP; p++){
    if ((wn >> 1) == p){
      #pragma unroll
      for (int i = 0; i < 4; i++)
        #pragma unroll
        for (int j = 0; j < NT4; j++)
          #pragma unroll
          for (int h = 0; h < 2; h++)
            #pragma unroll
            for (int e = 0; e < 2; e++){
              int row = wm*64 + i*16 + g + h*8;
              int lc  = (wn & 1)*WN + j*8 + tig*2 + e;
              S[lc*129 + row] = acc[i][j][h*2 + e];
            }
    }
    __syncthreads();
    for (int idx = tid; idx < CG*128; idx += 256){
      int m = idx / CG, cc = idx % CG;
      float val = S[cc*129 + m];
      if constexpr (STAGE==2){
        int gc = n0 + p*CG + cc;
        if (gc < 276){
          int r = gc/69, v = gc - r*69;
          long dst = (long)((b*4 + r)*128 + m)*144 + mt*72 + v;
          split_bf(val, g_UAh[dst], g_UAl[dst]);
        }
      } else {
        int rr = z & 3, bb = z >> 2;
        int gc = p*CG + cc;
        outp[(long)bb*65536 + (2*m + (rr >> 1))*256 + 2*gc + (rr & 1)] = val;
      }
    }
    __syncthreads();
  }
}

// ===================== launch ===============================================
extern "C" void kernel_launch(void* const* d_in, const int* in_sizes, int n_in,
                              void* d_out, int out_size)
{
  const float* x = (const float*)d_in[0];
  const float* w = (const float*)(n_in > 1 ? d_in[1] : d_in[0]);
  const float* bias = (const float*)(n_in > 2 ? d_in[2] : d_in[0]);
  for (int i = 0; i < n_in; i++){
    if (in_sizes[i] == 4*64*128*128) x = (const float*)d_in[i];
    else if (in_sizes[i] == 64*25)   w = (const float*)d_in[i];
    else if (in_sizes[i] == 64)      bias = (const float*)d_in[i];
  }
  float* out = (float*)d_out;

  constexpr int SM2 = 2*(2*128*80 + 2*96*80);    // 71680
  constexpr int SM3 = 2*(2*128*80 + 2*128*80);   // 81920
  cudaFuncSetAttribute(mma_k<2>, cudaFuncAttributeMaxDynamicSharedMemorySize, SM2);
  cudaFuncSetAttribute(mma_k<3>, cudaFuncAttributeMaxDynamicSharedMemorySize, SM3);

  k_build<<<(158480+255)/256, 256>>>();
  k_H   <<<(64*136*69+255)/256, 256>>>(w, bias);
  gemm_k<0><<<dim3(2,5,256), 256>>>(x);          // Tsp = MB1 * x
  gemm_k<1><<<dim3(3,544,1), 256>>>(x);          // Yt  = Tsp * MB2 (dense M)
  k_Z   <<<dim3(69,256), 160>>>();               // Z   = Y .* H
  mma_k<2><<<dim3(3,2,256), 256, SM2>>>(out);    // U   -> g_UA
  mma_k<3><<<dim3(1024,1,1), 256, SM3>>>(out);   // out
}

// round 9
// speedup vs baseline: 3.8564x; 1.0775x over previous
#include <cuda_runtime.h>
#include <cuda_bf16.h>
#include <math.h>
#include <cstdint>

#define PI_F 3.14159265358979323846f

// ===================== helpers ==============================================
__device__ __forceinline__ uint32_t smem_u32(const void* p){
  uint32_t a;
  asm("{ .reg .u64 t; cvta.to.shared.u64 t, %1; cvt.u32.u64 %0, t; }"
      : "=r"(a) : "l"(p));
  return a;
}
__device__ __forceinline__ void ldsm_x4(uint32_t &r0, uint32_t &r1,
                                        uint32_t &r2, uint32_t &r3, uint32_t addr){
  asm volatile("ldmatrix.sync.aligned.m8n8.x4.shared.b16 {%0,%1,%2,%3}, [%4];"
               : "=r"(r0), "=r"(r1), "=r"(r2), "=r"(r3) : "r"(addr));
}
__device__ __forceinline__ void ldsm_x2(uint32_t &r0, uint32_t &r1, uint32_t addr){
  asm volatile("ldmatrix.sync.aligned.m8n8.x2.shared.b16 {%0,%1}, [%2];"
               : "=r"(r0), "=r"(r1) : "r"(addr));
}
__device__ __forceinline__ void mma_bf16(float d[4], const uint32_t a[4],
                                         const uint32_t b[2]){
  asm volatile("mma.sync.aligned.m16n8k16.row.col.f32.bf16.bf16.f32 "
    "{%0,%1,%2,%3}, {%4,%5,%6,%7}, {%8,%9}, {%0,%1,%2,%3};"
    : "+f"(d[0]), "+f"(d[1]), "+f"(d[2]), "+f"(d[3])
    : "r"(a[0]), "r"(a[1]), "r"(a[2]), "r"(a[3]), "r"(b[0]), "r"(b[1]));
}
__device__ __forceinline__ unsigned long long ffma2(unsigned long long a,
                                                    unsigned long long b,
                                                    unsigned long long c){
  unsigned long long d;
  asm("fma.rn.f32x2 %0, %1, %2, %3;" : "=l"(d) : "l"(a), "l"(b), "l"(c));
  return d;
}
__device__ __forceinline__ unsigned long long dup2(float v){
  unsigned long long d; unsigned int u = __float_as_uint(v);
  asm("mov.b64 %0, {%1, %1};" : "=l"(d) : "r"(u));
  return d;
}
__device__ __forceinline__ float2 cmulf(float2 a, float2 b){
  return make_float2(a.x*b.x - a.y*b.y, a.x*b.y + a.y*b.x);
}
__device__ __forceinline__ void split_bf(float f, __nv_bfloat16 &h, __nv_bfloat16 &l){
  h = __float2bfloat16(f);
  l = __float2bfloat16(f - __bfloat162float(h));
}
__device__ __forceinline__ void fold_cs(int u, int ip, float &sumc, float &sumns){
  sumc = 0.f; sumns = 0.f;
  int iv[3]; int n = 0;
  iv[n++] = ip + 4;
  if (ip >= 124) iv[n++] = ip - 124;
  if (ip <= 3)   iv[n++] = ip + 132;
  for (int t = 0; t < n; t++){
    int m = (u * iv[t]) % 136;
    float s, c;
    sincosf((2.f*PI_F/136.f) * (float)m, &s, &c);
    sumc += c; sumns -= s;
  }
}

// ===================== persistent scratch ===================================
static __device__ float  g_T [256*136*256];                 // Tsp[(b*136+u)][256]
static __device__ float  g_Yt[256*138*136];                 // [b][n 138][u 136]
static __device__ float2 g_H [64*4*69*136];                 // [c][r][kw][kh]
static __device__ __align__(16) __nv_bfloat16 g_Zh[256*276*272];
static __device__ __align__(16) __nv_bfloat16 g_Zl[256*276*272];
static __device__ __align__(16) __nv_bfloat16 g_UAh[1024*128*144];
static __device__ __align__(16) __nv_bfloat16 g_UAl[1024*128*144];
static __device__ float  g_MB1[272*128];
static __device__ float  g_MB2[256*144];                    // padded to 144 cols
static __device__ __align__(16) __nv_bfloat16 g_MI1h[256*272];
static __device__ __align__(16) __nv_bfloat16 g_MI1l[256*272];
static __device__ __align__(16) __nv_bfloat16 g_MI2h[128*144];
static __device__ __align__(16) __nv_bfloat16 g_MI2l[128*144];
static __device__ float2 g_tw[272];

// ===================== merged builder =======================================
__global__ void k_build(){
  int idx = blockIdx.x*blockDim.x + threadIdx.x;
  if (idx < 272){
    float s, c; sincosf((2.f*PI_F/272.f)*(float)idx, &s, &c);
    g_tw[idx] = make_float2(c, s);
    return;
  }
  int i1 = idx - 272;
  if (i1 < 272*128){
    int col = i1 % 128, row = i1 / 128;
    int u = (row < 136) ? row : row - 136;
    float sc, sn; fold_cs(u, col, sc, sn);
    g_MB1[i1] = (row < 136) ? sc : sn;
    return;
  }
  int i2 = i1 - 272*128;
  if (i2 < 256*144){
    int n = i2 % 144, k = i2 / 144;
    float val = 0.f;
    if (n < 138){
      int v  = (n < 69) ? n : n - 69;
      int jp = (k < 128) ? k : k - 128;
      float sc, sn; fold_cs(v, jp, sc, sn);
      if (n < 69) val = (k < 128) ? sc : -sn;
      else        val = (k < 128) ? sn :  sc;
    }
    g_MB2[i2] = val;
    return;
  }
  int i3 = i2 - 256*144;
  if (i3 < 256*272){
    int k = i3 % 272, row = i3 / 272;
    int m   = (row & 127) + 4;
    int kap = (k < 136) ? k : k - 136;
    int a = (m * kap) % 136;
    float s, c; sincosf((2.f*PI_F/136.f)*(float)a, &s, &c);
    float val;
    if (row < 128) val = (k < 136) ?  c : -s;
    else           val = (k < 136) ?  s :  c;
    split_bf(val, g_MI1h[i3], g_MI1l[i3]);
    return;
  }
  int i4 = i3 - 256*272;
  if (i4 < 128*144){
    int kap = i4 % 144, n = i4 / 144;
    int part = (kap >= 72);
    int v = kap - (part ? 72 : 0);
    float val = 0.f;
    if (v < 69){
      float mult = (v == 0 || v == 68) ? 1.f : 2.f;
      int a = ((n + 4) * v) % 136;
      float s, c; sincosf((2.f*PI_F/136.f)*(float)a, &s, &c);
      val = part ? (-mult * s) : (mult * c);
    }
    split_bf(val, g_MI2h[i4], g_MI2l[i4]);
  }
}

__global__ void k_H(const float* __restrict__ w, const float* __restrict__ bias){
  int idx = blockIdx.x*blockDim.x + threadIdx.x;
  if (idx >= 64*136*69) return;
  int kw = idx % 69; int t = idx / 69; int kh = t % 136; int c = t / 136;
  float beta = 1.f/(1.f + expf(9.f - bias[c])) + 1e-5f;

  float2 bh[5], bw[5];
  #pragma unroll
  for (int a = 0; a < 5; a++){
    int mh = ((kh*(a-2)) % 272 + 272) % 272;
    float2 th = g_tw[mh]; bh[a] = make_float2(th.x, -th.y);
    int mw = ((kw*(a-2)) % 272 + 272) % 272;
    float2 tw = g_tw[mw]; bw[a] = make_float2(tw.x, -tw.y);
  }
  float2 S0[5], S1[5];
  #pragma unroll
  for (int a = 0; a < 5; a++){
    float2 s0 = make_float2(0.f,0.f), s1 = make_float2(0.f,0.f);
    #pragma unroll
    for (int b = 0; b < 5; b++){
      float wv = w[c*25 + a*5 + b];
      float tx = wv*bw[b].x, ty = wv*bw[b].y;
      s0.x += tx; s0.y += ty;
      if (b & 1){ s1.x -= tx; s1.y -= ty; } else { s1.x += tx; s1.y += ty; }
    }
    S0[a] = s0; S1[a] = s1;
  }
  float2 tph = g_tw[kh];
  float2 ph = make_float2(tph.x, -tph.y);
  float2 tpw = g_tw[kw];
  float2 pw = make_float2(tpw.x, -tpw.y);

  float2 FB[4], G[4];
  float2 Asum = make_float2(0.f,0.f);
  float  invW = 0.f;
  #pragma unroll
  for (int p = 0; p < 2; p++){
    #pragma unroll
    for (int q = 0; q < 2; q++){
      int r = p*2+q;
      float2 fb = make_float2(0.f,0.f);
      #pragma unroll
      for (int a = 0; a < 5; a++){
        float2 S = q ? S1[a] : S0[a];
        float2 term = cmulf(bh[a], S);
        if (p && (a & 1)) { term.x = -term.x; term.y = -term.y; }
        fb.x += term.x; fb.y += term.y;
      }
      FB[r] = fb;
      float2 f1 = make_float2(1.f + (p ? -ph.x : ph.x), (p ? -ph.y : ph.y));
      float2 f2 = make_float2(1.f + (q ? -pw.x : pw.x), (q ? -pw.y : pw.y));
      float2 box = cmulf(f1, f2);
      float2 g = make_float2(fb.x + beta*box.x, -fb.y + beta*box.y);
      G[r] = g;
      float2 ag = cmulf(fb, g);
      Asum.x += ag.x; Asum.y += ag.y;
      invW += fb.x*fb.x + fb.y*fb.y;
    }
  }
  Asum.x *= 0.25f; Asum.y *= 0.25f; invW *= 0.25f;
  float dinv = 1.f/(invW + beta);
  float2 tt = make_float2(Asum.x*dinv, Asum.y*dinv);
  float invb = 1.f/beta;
  float2 Hm[4];
  #pragma unroll
  for (int r = 0; r < 4; r++){
    float2 cf = make_float2(FB[r].x, -FB[r].y);
    float2 ct = cmulf(cf, tt);
    Hm[r] = make_float2((G[r].x - ct.x)*invb, (G[r].y - ct.y)*invb);
  }
  const float scale = 1.f/73984.f;
  float2 twh = make_float2(ph.x, -ph.y);
  float2 tww = make_float2(pw.x, -pw.y);
  #pragma unroll
  for (int rh = 0; rh < 2; rh++){
    #pragma unroll
    for (int rw = 0; rw < 2; rw++){
      float2 s = make_float2(0.f,0.f);
      #pragma unroll
      for (int p = 0; p < 2; p++)
        #pragma unroll
        for (int q = 0; q < 2; q++){
          float sg = ((p*rh + q*rw) & 1) ? -1.f : 1.f;
          s.x += sg*Hm[p*2+q].x; s.y += sg*Hm[p*2+q].y;
        }
      float2 tw = make_float2(1.f, 0.f);
      if (rh) tw = twh;
      if (rw) tw = cmulf(tw, tww);
      float2 o = cmulf(s, tw);
      o.x *= scale; o.y *= scale;
      g_H[((c*4 + rh*2 + rw)*69 + kw)*136 + kh] = o;
    }
  }
}

// ===================== Z = Y .* H, split-bf16, K-major ======================
__global__ void k_Z(){
  int kw = blockIdx.x;             // [0,69)
  int b  = blockIdx.y;             // [0,256)
  int kh = threadIdx.x;
  if (kh >= 136) return;
  int c = b & 63;
  float yr = g_Yt[(b*138 + kw)*136 + kh];
  float yi = g_Yt[(b*138 + 69 + kw)*136 + kh];
  #pragma unroll
  for (int r = 0; r < 4; r++){
    float2 h = g_H[((c*4+r)*69 + kw)*136 + kh];
    float zr = yr*h.x - yi*h.y;
    float zi = yr*h.y + yi*h.x;
    int n = r*69 + kw;
    long base = (long)(b*276 + n)*272;
    split_bf(zr, g_Zh[base + kh],       g_Zl[base + kh]);
    split_bf(zi, g_Zh[base + 136 + kh], g_Zl[base + 136 + kh]);
  }
}

// ===================== FFMA2 GEMM, 8x8 microtiles (stages 0,1) ==============
// STAGE 0: Tsp[(b*136+u)][half*128+j] = MB1 * x_b   (M=272pad384, N=128, K=128)
// STAGE 1: Yt = Tsp(34816x256) * MB2(256x144pad)     (BM=256, BN=64, grid 3x136)
template<int STAGE>
__global__ __launch_bounds__(256, 2) void gemm_k(const float* __restrict__ xin)
{
  constexpr int K   = (STAGE==0)?128:256;
  constexpr int TC  = (STAGE==0)?16:8;
  constexpr int BM  = (STAGE==0)?128:256;
  constexpr int BN  = (STAGE==0)?128:64;
  constexpr int NT  = K/16;
  constexpr int NAQ = BM/64;      // A float4s per thread per tile
  constexpr int NBQ = BN/64;      // B float4s per thread per tile (>=1)

  __shared__ __align__(16) float As[2][16][BM];
  __shared__ __align__(16) float Bs[2][16][BN];

  const int z = blockIdx.z;
  const int tid = threadIdx.x;
  const int tc = tid % TC, tr = tid / TC;
  const int m0 = blockIdx.y*BM, n0 = blockIdx.x*BN;

  auto fetchAq = [&](int gm, int gk)->float4{
    if constexpr (STAGE==0){
      if (gm < 272) return *reinterpret_cast<const float4*>(g_MB1 + gm*128 + gk);
      return make_float4(0.f,0.f,0.f,0.f);
    } else {
      return *reinterpret_cast<const float4*>(g_T + (long)gm*256 + gk);
    }
  };
  auto fetchBq = [&](int gk, int gn)->float4{
    if constexpr (STAGE==0){
      return *reinterpret_cast<const float4*>(xin + z*16384 + gk*128 + gn);
    } else {
      if (gn < 144) return *reinterpret_cast<const float4*>(g_MB2 + gk*144 + gn);
      return make_float4(0.f,0.f,0.f,0.f);
    }
  };

  float4 raq[NAQ], rbq[NBQ];
  auto loadAB = [&](int kk){
    #pragma unroll
    for (int i = 0; i < NAQ; i++){
      int e = tid + i*256;
      int m = e >> 2, kq = e & 3;
      raq[i] = fetchAq(m0 + m, kk + kq*4);
    }
    #pragma unroll
    for (int i = 0; i < NBQ; i++){
      int e = tid + i*256;
      int kb = e / (BN/4), nq = e % (BN/4);
      rbq[i] = fetchBq(kk + kb, n0 + nq*4);
    }
  };
  auto storeAB = [&](int buf){
    #pragma unroll
    for (int i = 0; i < NAQ; i++){
      int e = tid + i*256;
      int m = e >> 2, kq = e & 3;
      As[buf][kq*4+0][m] = raq[i].x;
      As[buf][kq*4+1][m] = raq[i].y;
      As[buf][kq*4+2][m] = raq[i].z;
      As[buf][kq*4+3][m] = raq[i].w;
    }
    #pragma unroll
    for (int i = 0; i < NBQ; i++){
      int e = tid + i*256;
      int kb = e / (BN/4), nq = e % (BN/4);
      *reinterpret_cast<float4*>(&Bs[buf][kb][nq*4]) = rbq[i];
    }
  };

  unsigned long long acc[4][8] = {};
  loadAB(0); storeAB(0); __syncthreads();

  #pragma unroll 1
  for (int t = 0; t < NT; t++){
    int buf = t & 1;
    if (t + 1 < NT) loadAB((t+1)*16);
    #pragma unroll
    for (int k = 0; k < 16; k++){
      ulonglong2 a01 = *reinterpret_cast<const ulonglong2*>(&As[buf][k][tr*8]);
      ulonglong2 a23 = *reinterpret_cast<const ulonglong2*>(&As[buf][k][tr*8+4]);
      unsigned long long ap[4] = {a01.x, a01.y, a23.x, a23.y};
      float4 b0 = *reinterpret_cast<const float4*>(&Bs[buf][k][tc*8]);
      float4 b1 = *reinterpret_cast<const float4*>(&Bs[buf][k][tc*8+4]);
      unsigned long long bd[8] = {dup2(b0.x),dup2(b0.y),dup2(b0.z),dup2(b0.w),
                                  dup2(b1.x),dup2(b1.y),dup2(b1.z),dup2(b1.w)};
      #pragma unroll
      for (int p = 0; p < 4; p++)
        #pragma unroll
        for (int j = 0; j < 8; j++)
          acc[p][j] = ffma2(ap[p], bd[j], acc[p][j]);
    }
    if (t + 1 < NT){ storeAB(buf ^ 1); __syncthreads(); }
  }

  union { unsigned long long u; float2 f; } pun;
  if constexpr (STAGE==0){
    #pragma unroll
    for (int p = 0; p < 4; p++){
      #pragma unroll
      for (int e = 0; e < 2; e++){
        int gm = m0 + tr*8 + 2*p + e;
        if (gm >= 272) continue;
        int u = (gm < 136) ? gm : gm - 136;
        int half = (gm < 136) ? 0 : 128;
        float v[8];
        #pragma unroll
        for (int j = 0; j < 8; j++){
          pun.u = acc[p][j]; v[j] = e ? pun.f.y : pun.f.x;
        }
        float* dst = g_T + (long)(z*136 + u)*256 + half + tc*8;
        *reinterpret_cast<float4*>(dst)     = make_float4(v[0],v[1],v[2],v[3]);
        *reinterpret_cast<float4*>(dst + 4) = make_float4(v[4],v[5],v[6],v[7]);
      }
    }
  } else {
    // staged transpose epilogue: 4 passes of 64 m-rows
    float* S = &As[0][0][0];    // 64*65 floats, aliases double buffers
    __syncthreads();
    const int pmine = tr >> 3;
    const int mlb = (tr & 7)*8;
    #pragma unroll 1
    for (int p = 0; p < 4; p++){
      if (p == pmine){
        #pragma unroll
        for (int pp = 0; pp < 4; pp++)
          #pragma unroll
          for (int e = 0; e < 2; e++){
            int ml = mlb + 2*pp + e;
            #pragma unroll
            for (int j = 0; j < 8; j++){
              pun.u = acc[pp][j];
              S[(tc*8 + j)*65 + ml] = e ? pun.f.y : pun.f.x;
            }
          }
      }
      __syncthreads();
      for (int idx = tid; idx < 64*64; idx += 256){
        int nl = idx >> 6, ml = idx & 63;
        int gn = n0 + nl;
        if (gn < 138){
          int g = m0 + p*64 + ml;
          int bb = g / 136, uu = g - bb*136;
          g_Yt[((long)bb*138 + gn)*136 + uu] = S[nl*65 + ml];
        }
      }
      __syncthreads();
    }
  }
}

// ===================== HMMA split-bf16 GEMM, cp.async KC=32 pipeline ========
template<int STAGE>
__global__ __launch_bounds__(256) void mma_k(float* __restrict__ outp)
{
  constexpr int BN  = (STAGE==2) ? 96 : 128;
  constexpr int K   = (STAGE==2) ? 272 : 144;
  constexpr int KC  = 32;
  constexpr int NCH = (K + KC - 1)/KC;
  constexpr int SAB = 80;
  constexpr int NT4 = BN/32;
  constexpr int WN  = BN/4;
  constexpr int ABY = 128*SAB;
  constexpr int BBY = BN*SAB;
  constexpr int OAH = 0, OAL = ABY, OBH = 2*ABY, OBL = 2*ABY + BBY;
  constexpr int BUFB = 2*ABY + 2*BBY;

  extern __shared__ __align__(16) char smraw[];

  const int tid = threadIdx.x, lane = tid & 31, wid = tid >> 5;
  const int wm = wid & 1, wn = wid >> 1;

  int b = 0, n0 = 0, z = 0, mt = 0;
  const __nv_bfloat16 *Ahs, *Als, *Bhs, *Bls;
  if constexpr (STAGE==2){
    b = blockIdx.z; mt = blockIdx.y; n0 = blockIdx.x*96;
    Ahs = g_MI1h + mt*128*272; Als = g_MI1l + mt*128*272;
    Bhs = g_Zh + (long)b*276*272; Bls = g_Zl + (long)b*276*272;
  } else {
    z = blockIdx.x;
    Ahs = g_UAh + (long)z*128*144; Als = g_UAl + (long)z*128*144;
    Bhs = g_MI2h; Bls = g_MI2l;
  }

  auto issue = [&](int t, int buf){
    const int kk = t*KC;
    char* base = smraw + buf*BUFB;
    #pragma unroll
    for (int it = 0; it < 4; it++){
      int cid = tid + it*256;
      int hl = cid >> 9, rem = cid & 511;
      int row = rem >> 2, c16 = rem & 3;
      int gk = kk + c16*8;
      int sz = (gk + 8 <= K) ? 16 : 0;
      const __nv_bfloat16* src = (hl ? Als : Ahs) + (long)row*K + (sz ? gk : 0);
      uint32_t dst = smem_u32(base + (hl ? OAL : OAH) + row*SAB + c16*16);
      asm volatile("cp.async.ca.shared.global [%0], [%1], 16, %2;"
                   :: "r"(dst), "l"(src), "r"(sz));
    }
    constexpr int BCH = BN*8;
    #pragma unroll
    for (int it = 0; it < BCH/256; it++){
      int cid = tid + it*256;
      int hl = (cid >= BCH/2), rem = cid % (BCH/2);
      int row = rem >> 2, c16 = rem & 3;
      int gk = kk + c16*8;
      int grow = row;
      int sz = (gk + 8 <= K) ? 16 : 0;
      if constexpr (STAGE==2){
        grow = n0 + row;
        if (grow >= 276){ grow = 275; sz = 0; }
      }
      const __nv_bfloat16* src = (hl ? Bls : Bhs) + (long)grow*K + (sz ? gk : 0);
      uint32_t dst = smem_u32(base + (hl ? OBL : OBH) + row*SAB + c16*16);
      asm volatile("cp.async.ca.shared.global [%0], [%1], 16, %2;"
                   :: "r"(dst), "l"(src), "r"(sz));
    }
    asm volatile("cp.async.commit_group;" ::: "memory");
  };

  float acc[4][NT4][4];
  #pragma unroll
  for (int i = 0; i < 4; i++)
    #pragma unroll
    for (int j = 0; j < NT4; j++)
      #pragma unroll
      for (int q = 0; q < 4; q++) acc[i][j][q] = 0.f;

  issue(0, 0);

  #pragma unroll 1
  for (int t = 0; t < NCH; t++){
    const int buf = t & 1;
    if (t + 1 < NCH){
      issue(t + 1, buf ^ 1);
      asm volatile("cp.async.wait_group 1;" ::: "memory");
    } else {
      asm volatile("cp.async.wait_group 0;" ::: "memory");
    }
    __syncthreads();

    char* base = smraw + buf*BUFB;
    const int nsub = (K - t*KC >= KC) ? 2 : 1;
    #pragma unroll
    for (int sub = 0; sub < 2; sub++){
      if (sub >= nsub) break;
      const int tk = sub*16;
      uint32_t afh[4][4], afl[4][4];
      #pragma unroll
      for (int i = 0; i < 4; i++){
        int row = wm*64 + i*16 + (lane & 15);
        int col = tk + (lane >> 4)*8;
        ldsm_x4(afh[i][0], afh[i][1], afh[i][2], afh[i][3],
                smem_u32(base + OAH + row*SAB + col*2));
        ldsm_x4(afl[i][0], afl[i][1], afl[i][2], afl[i][3],
                smem_u32(base + OAL + row*SAB + col*2));
      }
      uint32_t bfh[NT4][2], bfl[NT4][2];
      if constexpr (NT4 == 4){
        #pragma unroll
        for (int j0 = 0; j0 < 4; j0 += 2){
          int q = lane >> 3;
          int row = wn*WN + (j0 + (q >> 1))*8 + (lane & 7);
          int col = tk + (q & 1)*8;
          ldsm_x4(bfh[j0][0], bfh[j0][1], bfh[j0+1][0], bfh[j0+1][1],
                  smem_u32(base + OBH + row*SAB + col*2));
          ldsm_x4(bfl[j0][0], bfl[j0][1], bfl[j0+1][0], bfl[j0+1][1],
                  smem_u32(base + OBL + row*SAB + col*2));
        }
      } else {
        {
          int q = lane >> 3;
          int row = wn*WN + (q >> 1)*8 + (lane & 7);
          int col = tk + (q & 1)*8;
          ldsm_x4(bfh[0][0], bfh[0][1], bfh[1][0], bfh[1][1],
                  smem_u32(base + OBH + row*SAB + col*2));
          ldsm_x4(bfl[0][0], bfl[0][1], bfl[1][0], bfl[1][1],
                  smem_u32(base + OBL + row*SAB + col*2));
        }
        {
          int l15 = lane & 15;
          int row = wn*WN + 16 + (l15 & 7);
          int col = tk + (l15 >> 3)*8;
          ldsm_x2(bfh[2][0], bfh[2][1], smem_u32(base + OBH + row*SAB + col*2));
          ldsm_x2(bfl[2][0], bfl[2][1], smem_u32(base + OBL + row*SAB + col*2));
        }
      }
      #pragma unroll
      for (int i = 0; i < 4; i++)
        #pragma unroll
        for (int j = 0; j < NT4; j++){
          mma_bf16(acc[i][j], afh[i], bfh[j]);
          mma_bf16(acc[i][j], afh[i], bfl[j]);
          mma_bf16(acc[i][j], afl[i], bfh[j]);
        }
    }
    __syncthreads();
  }

  // ---- coalesced epilogue via SMEM staging
  float* S = reinterpret_cast<float*>(smraw);
  const int g = lane >> 2, tig = lane & 3;
  constexpr int CG = (STAGE==2) ? 48 : 64;
  constexpr int NP = BN / CG;

  #pragma unroll 1
  for (int p = 0; p < NP; p++){
    if ((wn >> 1) == p){
      #pragma unroll
      for (int i = 0; i < 4; i++)
        #pragma unroll
        for (int j = 0; j < NT4; j++)
          #pragma unroll
          for (int h = 0; h < 2; h++)
            #pragma unroll
            for (int e = 0; e < 2; e++){
              int row = wm*64 + i*16 + g + h*8;
              int lc  = (wn & 1)*WN + j*8 + tig*2 + e;
              S[lc*129 + row] = acc[i][j][h*2 + e];
            }
    }
    __syncthreads();
    for (int idx = tid; idx < CG*128; idx += 256){
      int m = idx / CG, cc = idx % CG;
      float val = S[cc*129 + m];
      if constexpr (STAGE==2){
        int gc = n0 + p*CG + cc;
        if (gc < 276){
          int r = gc/69, v = gc - r*69;
          long dst = (long)((b*4 + r)*128 + m)*144 + mt*72 + v;
          split_bf(val, g_UAh[dst], g_UAl[dst]);
        }
      } else {
        int rr = z & 3, bb = z >> 2;
        int gc = p*CG + cc;
        outp[(long)bb*65536 + (2*m + (rr >> 1))*256 + 2*gc + (rr & 1)] = val;
      }
    }
    __syncthreads();
  }
}

// ===================== launch ===============================================
extern "C" void kernel_launch(void* const* d_in, const int* in_sizes, int n_in,
                              void* d_out, int out_size)
{
  const float* x = (const float*)d_in[0];
  const float* w = (const float*)(n_in > 1 ? d_in[1] : d_in[0]);
  const float* bias = (const float*)(n_in > 2 ? d_in[2] : d_in[0]);
  for (int i = 0; i < n_in; i++){
    if (in_sizes[i] == 4*64*128*128) x = (const float*)d_in[i];
    else if (in_sizes[i] == 64*25)   w = (const float*)d_in[i];
    else if (in_sizes[i] == 64)      bias = (const float*)d_in[i];
  }
  float* out = (float*)d_out;

  constexpr int SM2 = 2*(2*128*80 + 2*96*80);    // 71680
  constexpr int SM3 = 2*(2*128*80 + 2*128*80);   // 81920
  cudaFuncSetAttribute(mma_k<2>, cudaFuncAttributeMaxDynamicSharedMemorySize, SM2);
  cudaFuncSetAttribute(mma_k<3>, cudaFuncAttributeMaxDynamicSharedMemorySize, SM3);

  k_build<<<(160016+255)/256, 256>>>();
  k_H   <<<(64*136*69+255)/256, 256>>>(w, bias);
  gemm_k<0><<<dim3(1,3,256), 256>>>(x);          // Tsp = MB1 * x   (128x128 tiles)
  gemm_k<1><<<dim3(3,136,1), 256>>>(x);          // Yt  = Tsp * MB2 (256x64 tiles)
  k_Z   <<<dim3(69,256), 160>>>();               // Z   = Y .* H
  mma_k<2><<<dim3(3,2,256), 256, SM2>>>(out);    // U   -> g_UA
  mma_k<3><<<dim3(1024,1,1), 256, SM3>>>(out);   // out
}

// round 10
// speedup vs baseline: 4.5330x; 1.1754x over previous
#include <cuda_runtime.h>
#include <cuda_bf16.h>
#include <math.h>
#include <cstdint>

#define PI_F 3.14159265358979323846f

// ===================== helpers ==============================================
__device__ __forceinline__ uint32_t smem_u32(const void* p){
  uint32_t a;
  asm("{ .reg .u64 t; cvta.to.shared.u64 t, %1; cvt.u32.u64 %0, t; }"
      : "=r"(a) : "l"(p));
  return a;
}
__device__ __forceinline__ void ldsm_x4(uint32_t &r0, uint32_t &r1,
                                        uint32_t &r2, uint32_t &r3, uint32_t addr){
  asm volatile("ldmatrix.sync.aligned.m8n8.x4.shared.b16 {%0,%1,%2,%3}, [%4];"
               : "=r"(r0), "=r"(r1), "=r"(r2), "=r"(r3) : "r"(addr));
}
__device__ __forceinline__ void ldsm_x2(uint32_t &r0, uint32_t &r1, uint32_t addr){
  asm volatile("ldmatrix.sync.aligned.m8n8.x2.shared.b16 {%0,%1}, [%2];"
               : "=r"(r0), "=r"(r1) : "r"(addr));
}
__device__ __forceinline__ void mma_bf16(float d[4], const uint32_t a[4],
                                         const uint32_t b[2]){
  asm volatile("mma.sync.aligned.m16n8k16.row.col.f32.bf16.bf16.f32 "
    "{%0,%1,%2,%3}, {%4,%5,%6,%7}, {%8,%9}, {%0,%1,%2,%3};"
    : "+f"(d[0]), "+f"(d[1]), "+f"(d[2]), "+f"(d[3])
    : "r"(a[0]), "r"(a[1]), "r"(a[2]), "r"(a[3]), "r"(b[0]), "r"(b[1]));
}
__device__ __forceinline__ unsigned long long ffma2(unsigned long long a,
                                                    unsigned long long b,
                                                    unsigned long long c){
  unsigned long long d;
  asm("fma.rn.f32x2 %0, %1, %2, %3;" : "=l"(d) : "l"(a), "l"(b), "l"(c));
  return d;
}
__device__ __forceinline__ unsigned long long dup2(float v){
  unsigned long long d; unsigned int u = __float_as_uint(v);
  asm("mov.b64 %0, {%1, %1};" : "=l"(d) : "r"(u));
  return d;
}
__device__ __forceinline__ float2 cmulf(float2 a, float2 b){
  return make_float2(a.x*b.x - a.y*b.y, a.x*b.y + a.y*b.x);
}
__device__ __forceinline__ void split_bf(float f, __nv_bfloat16 &h, __nv_bfloat16 &l){
  h = __float2bfloat16(f);
  l = __float2bfloat16(f - __bfloat162float(h));
}
__device__ __forceinline__ void fold_cs(int u, int ip, float &sumc, float &sumns){
  sumc = 0.f; sumns = 0.f;
  int iv[3]; int n = 0;
  iv[n++] = ip + 4;
  if (ip >= 124) iv[n++] = ip - 124;
  if (ip <= 3)   iv[n++] = ip + 132;
  for (int t = 0; t < n; t++){
    int m = (u * iv[t]) % 136;
    float s, c;
    sincosf((2.f*PI_F/136.f) * (float)m, &s, &c);
    sumc += c; sumns -= s;
  }
}

// ===================== persistent scratch ===================================
static __device__ __align__(16) __nv_bfloat16 g_Tbh[256*136*256]; // Tsp hi
static __device__ __align__(16) __nv_bfloat16 g_Tbl[256*136*256]; // Tsp lo
static __device__ float  g_Yt[256*138*136];                 // [b][n 138][u 136]
static __device__ float2 g_H [64*4*69*136];                 // [c][r][kw][kh]
static __device__ __align__(16) __nv_bfloat16 g_Zh[256*276*272];
static __device__ __align__(16) __nv_bfloat16 g_Zl[256*276*272];
static __device__ __align__(16) __nv_bfloat16 g_UAh[1024*128*144];
static __device__ __align__(16) __nv_bfloat16 g_UAl[1024*128*144];
static __device__ float  g_MB1[272*128];
static __device__ __align__(16) __nv_bfloat16 g_MB2th[144*256];  // MB2^T split
static __device__ __align__(16) __nv_bfloat16 g_MB2tl[144*256];
static __device__ __align__(16) __nv_bfloat16 g_MI1h[256*272];
static __device__ __align__(16) __nv_bfloat16 g_MI1l[256*272];
static __device__ __align__(16) __nv_bfloat16 g_MI2h[128*144];
static __device__ __align__(16) __nv_bfloat16 g_MI2l[128*144];
static __device__ float2 g_tw[272];

// ===================== merged builder =======================================
__global__ void k_build(){
  int idx = blockIdx.x*blockDim.x + threadIdx.x;
  if (idx < 272){
    float s, c; sincosf((2.f*PI_F/272.f)*(float)idx, &s, &c);
    g_tw[idx] = make_float2(c, s);
    return;
  }
  int i1 = idx - 272;
  if (i1 < 272*128){
    int col = i1 % 128, row = i1 / 128;
    int u = (row < 136) ? row : row - 136;
    float sc, sn; fold_cs(u, col, sc, sn);
    g_MB1[i1] = (row < 136) ? sc : sn;
    return;
  }
  int i2 = i1 - 272*128;
  if (i2 < 144*256){                       // MB2^T split: [n][k]
    int k = i2 % 256, n = i2 / 256;
    float val = 0.f;
    if (n < 138){
      int v  = (n < 69) ? n : n - 69;
      int jp = (k < 128) ? k : k - 128;
      float sc, sn; fold_cs(v, jp, sc, sn);
      if (n < 69) val = (k < 128) ? sc : -sn;
      else        val = (k < 128) ? sn :  sc;
    }
    split_bf(val, g_MB2th[i2], g_MB2tl[i2]);
    return;
  }
  int i3 = i2 - 144*256;
  if (i3 < 256*272){
    int k = i3 % 272, row = i3 / 272;
    int m   = (row & 127) + 4;
    int kap = (k < 136) ? k : k - 136;
    int a = (m * kap) % 136;
    float s, c; sincosf((2.f*PI_F/136.f)*(float)a, &s, &c);
    float val;
    if (row < 128) val = (k < 136) ?  c : -s;
    else           val = (k < 136) ?  s :  c;
    split_bf(val, g_MI1h[i3], g_MI1l[i3]);
    return;
  }
  int i4 = i3 - 256*272;
  if (i4 < 128*144){
    int kap = i4 % 144, n = i4 / 144;
    int part = (kap >= 72);
    int v = kap - (part ? 72 : 0);
    float val = 0.f;
    if (v < 69){
      float mult = (v == 0 || v == 68) ? 1.f : 2.f;
      int a = ((n + 4) * v) % 136;
      float s, c; sincosf((2.f*PI_F/136.f)*(float)a, &s, &c);
      val = part ? (-mult * s) : (mult * c);
    }
    split_bf(val, g_MI2h[i4], g_MI2l[i4]);
  }
}

__global__ void k_H(const float* __restrict__ w, const float* __restrict__ bias){
  int idx = blockIdx.x*blockDim.x + threadIdx.x;
  if (idx >= 64*136*69) return;
  int kw = idx % 69; int t = idx / 69; int kh = t % 136; int c = t / 136;
  float beta = 1.f/(1.f + expf(9.f - bias[c])) + 1e-5f;

  float2 bh[5], bw[5];
  #pragma unroll
  for (int a = 0; a < 5; a++){
    int mh = ((kh*(a-2)) % 272 + 272) % 272;
    float2 th = g_tw[mh]; bh[a] = make_float2(th.x, -th.y);
    int mw = ((kw*(a-2)) % 272 + 272) % 272;
    float2 tw = g_tw[mw]; bw[a] = make_float2(tw.x, -tw.y);
  }
  float2 S0[5], S1[5];
  #pragma unroll
  for (int a = 0; a < 5; a++){
    float2 s0 = make_float2(0.f,0.f), s1 = make_float2(0.f,0.f);
    #pragma unroll
    for (int b = 0; b < 5; b++){
      float wv = w[c*25 + a*5 + b];
      float tx = wv*bw[b].x, ty = wv*bw[b].y;
      s0.x += tx; s0.y += ty;
      if (b & 1){ s1.x -= tx; s1.y -= ty; } else { s1.x += tx; s1.y += ty; }
    }
    S0[a] = s0; S1[a] = s1;
  }
  float2 tph = g_tw[kh];
  float2 ph = make_float2(tph.x, -tph.y);
  float2 tpw = g_tw[kw];
  float2 pw = make_float2(tpw.x, -tpw.y);

  float2 FB[4], G[4];
  float2 Asum = make_float2(0.f,0.f);
  float  invW = 0.f;
  #pragma unroll
  for (int p = 0; p < 2; p++){
    #pragma unroll
    for (int q = 0; q < 2; q++){
      int r = p*2+q;
      float2 fb = make_float2(0.f,0.f);
      #pragma unroll
      for (int a = 0; a < 5; a++){
        float2 S = q ? S1[a] : S0[a];
        float2 term = cmulf(bh[a], S);
        if (p && (a & 1)) { term.x = -term.x; term.y = -term.y; }
        fb.x += term.x; fb.y += term.y;
      }
      FB[r] = fb;
      float2 f1 = make_float2(1.f + (p ? -ph.x : ph.x), (p ? -ph.y : ph.y));
      float2 f2 = make_float2(1.f + (q ? -pw.x : pw.x), (q ? -pw.y : pw.y));
      float2 box = cmulf(f1, f2);
      float2 g = make_float2(fb.x + beta*box.x, -fb.y + beta*box.y);
      G[r] = g;
      float2 ag = cmulf(fb, g);
      Asum.x += ag.x; Asum.y += ag.y;
      invW += fb.x*fb.x + fb.y*fb.y;
    }
  }
  Asum.x *= 0.25f; Asum.y *= 0.25f; invW *= 0.25f;
  float dinv = 1.f/(invW + beta);
  float2 tt = make_float2(Asum.x*dinv, Asum.y*dinv);
  float invb = 1.f/beta;
  float2 Hm[4];
  #pragma unroll
  for (int r = 0; r < 4; r++){
    float2 cf = make_float2(FB[r].x, -FB[r].y);
    float2 ct = cmulf(cf, tt);
    Hm[r] = make_float2((G[r].x - ct.x)*invb, (G[r].y - ct.y)*invb);
  }
  const float scale = 1.f/73984.f;
  float2 twh = make_float2(ph.x, -ph.y);
  float2 tww = make_float2(pw.x, -pw.y);
  #pragma unroll
  for (int rh = 0; rh < 2; rh++){
    #pragma unroll
    for (int rw = 0; rw < 2; rw++){
      float2 s = make_float2(0.f,0.f);
      #pragma unroll
      for (int p = 0; p < 2; p++)
        #pragma unroll
        for (int q = 0; q < 2; q++){
          float sg = ((p*rh + q*rw) & 1) ? -1.f : 1.f;
          s.x += sg*Hm[p*2+q].x; s.y += sg*Hm[p*2+q].y;
        }
      float2 tw = make_float2(1.f, 0.f);
      if (rh) tw = twh;
      if (rw) tw = cmulf(tw, tww);
      float2 o = cmulf(s, tw);
      o.x *= scale; o.y *= scale;
      g_H[((c*4 + rh*2 + rw)*69 + kw)*136 + kh] = o;
    }
  }
}

// ===================== Z = Y .* H, split-bf16, K-major ======================
__global__ void k_Z(){
  int kw = blockIdx.x;             // [0,69)
  int b  = blockIdx.y;             // [0,256)
  int kh = threadIdx.x;
  if (kh >= 136) return;
  int c = b & 63;
  float yr = g_Yt[(b*138 + kw)*136 + kh];
  float yi = g_Yt[(b*138 + 69 + kw)*136 + kh];
  #pragma unroll
  for (int r = 0; r < 4; r++){
    float2 h = g_H[((c*4+r)*69 + kw)*136 + kh];
    float zr = yr*h.x - yi*h.y;
    float zi = yr*h.y + yi*h.x;
    int n = r*69 + kw;
    long base = (long)(b*276 + n)*272;
    split_bf(zr, g_Zh[base + kh],       g_Zl[base + kh]);
    split_bf(zi, g_Zh[base + 136 + kh], g_Zl[base + 136 + kh]);
  }
}

// ===================== FFMA2 GEMM stage 0 ===================================
// Tsp[(b*136+u)][half*128+j] = MB1 * x_b, output split bf16 K-major
__global__ __launch_bounds__(256, 2) void gemm0_k(const float* __restrict__ xin)
{
  constexpr int K = 128, TC = 16, BM = 128, BN = 128, NT = K/16;
  constexpr int NAQ = BM/64, NBQ = BN/64;

  __shared__ __align__(16) float As[2][16][BM];
  __shared__ __align__(16) float Bs[2][16][BN];

  const int z = blockIdx.z;
  const int tid = threadIdx.x;
  const int tc = tid % TC, tr = tid / TC;
  const int m0 = blockIdx.y*BM;

  auto fetchAq = [&](int gm, int gk)->float4{
    if (gm < 272) return *reinterpret_cast<const float4*>(g_MB1 + gm*128 + gk);
    return make_float4(0.f,0.f,0.f,0.f);
  };
  auto fetchBq = [&](int gk, int gn)->float4{
    return *reinterpret_cast<const float4*>(xin + z*16384 + gk*128 + gn);
  };

  float4 raq[NAQ], rbq[NBQ];
  auto loadAB = [&](int kk){
    #pragma unroll
    for (int i = 0; i < NAQ; i++){
      int e = tid + i*256;
      int m = e >> 2, kq = e & 3;
      raq[i] = fetchAq(m0 + m, kk + kq*4);
    }
    #pragma unroll
    for (int i = 0; i < NBQ; i++){
      int e = tid + i*256;
      int kb = e / (BN/4), nq = e % (BN/4);
      rbq[i] = fetchBq(kk + kb, nq*4);
    }
  };
  auto storeAB = [&](int buf){
    #pragma unroll
    for (int i = 0; i < NAQ; i++){
      int e = tid + i*256;
      int m = e >> 2, kq = e & 3;
      As[buf][kq*4+0][m] = raq[i].x;
      As[buf][kq*4+1][m] = raq[i].y;
      As[buf][kq*4+2][m] = raq[i].z;
      As[buf][kq*4+3][m] = raq[i].w;
    }
    #pragma unroll
    for (int i = 0; i < NBQ; i++){
      int e = tid + i*256;
      int kb = e / (BN/4), nq = e % (BN/4);
      *reinterpret_cast<float4*>(&Bs[buf][kb][nq*4]) = rbq[i];
    }
  };

  unsigned long long acc[4][8] = {};
  loadAB(0); storeAB(0); __syncthreads();

  #pragma unroll 1
  for (int t = 0; t < NT; t++){
    int buf = t & 1;
    if (t + 1 < NT) loadAB((t+1)*16);
    #pragma unroll
    for (int k = 0; k < 16; k++){
      ulonglong2 a01 = *reinterpret_cast<const ulonglong2*>(&As[buf][k][tr*8]);
      ulonglong2 a23 = *reinterpret_cast<const ulonglong2*>(&As[buf][k][tr*8+4]);
      unsigned long long ap[4] = {a01.x, a01.y, a23.x, a23.y};
      float4 b0 = *reinterpret_cast<const float4*>(&Bs[buf][k][tc*8]);
      float4 b1 = *reinterpret_cast<const float4*>(&Bs[buf][k][tc*8+4]);
      unsigned long long bd[8] = {dup2(b0.x),dup2(b0.y),dup2(b0.z),dup2(b0.w),
                                  dup2(b1.x),dup2(b1.y),dup2(b1.z),dup2(b1.w)};
      #pragma unroll
      for (int p = 0; p < 4; p++)
        #pragma unroll
        for (int j = 0; j < 8; j++)
          acc[p][j] = ffma2(ap[p], bd[j], acc[p][j]);
    }
    if (t + 1 < NT){ storeAB(buf ^ 1); __syncthreads(); }
  }

  union { unsigned long long u; float2 f; } pun;
  #pragma unroll
  for (int p = 0; p < 4; p++){
    #pragma unroll
    for (int e = 0; e < 2; e++){
      int gm = m0 + tr*8 + 2*p + e;
      if (gm >= 272) continue;
      int u = (gm < 136) ? gm : gm - 136;
      int half = (gm < 136) ? 0 : 128;
      __align__(16) __nv_bfloat16 hi[8], lo[8];
      #pragma unroll
      for (int j = 0; j < 8; j++){
        pun.u = acc[p][j];
        split_bf(e ? pun.f.y : pun.f.x, hi[j], lo[j]);
      }
      long off = (long)(z*136 + u)*256 + half + tc*8;
      *reinterpret_cast<uint4*>(g_Tbh + off) = *reinterpret_cast<uint4*>(hi);
      *reinterpret_cast<uint4*>(g_Tbl + off) = *reinterpret_cast<uint4*>(lo);
    }
  }
}

// ===================== HMMA split-bf16 GEMM, cp.async KC=32 pipeline ========
// STAGE 1: Yt = Tsp(34816x256) * MB2t(144x256)^T  -> g_Yt (fp32, transposed)
// STAGE 2: U(256x276) = MI1(256x272) * Z_b(276x272)^T -> g_UA split bf16
// STAGE 3: out = UA_z(128x144) * MI2(128x144)^T -> d_out interleaved
template<int STAGE>
__global__ __launch_bounds__(256) void mma_k(float* __restrict__ outp)
{
  constexpr int BN  = (STAGE==3) ? 128 : 96;
  constexpr int K   = (STAGE==1) ? 256 : (STAGE==2) ? 272 : 144;
  constexpr int KC  = 32;
  constexpr int NCH = (K + KC - 1)/KC;
  constexpr int SAB = 80;
  constexpr int NT4 = BN/32;
  constexpr int WN  = BN/4;
  constexpr int ABY = 128*SAB;
  constexpr int BBY = BN*SAB;
  constexpr int OAH = 0, OAL = ABY, OBH = 2*ABY, OBL = 2*ABY + BBY;
  constexpr int BUFB = 2*ABY + 2*BBY;

  extern __shared__ __align__(16) char smraw[];

  const int tid = threadIdx.x, lane = tid & 31, wid = tid >> 5;
  const int wm = wid & 1, wn = wid >> 1;

  int b = 0, n0 = 0, z = 0, mt = 0;
  const __nv_bfloat16 *Ahs, *Als, *Bhs, *Bls;
  if constexpr (STAGE==1){
    mt = blockIdx.y; n0 = blockIdx.x*96;
    Ahs = g_Tbh + (long)mt*128*256; Als = g_Tbl + (long)mt*128*256;
    Bhs = g_MB2th; Bls = g_MB2tl;
  } else if constexpr (STAGE==2){
    b = blockIdx.z; mt = blockIdx.y; n0 = blockIdx.x*96;
    Ahs = g_MI1h + mt*128*272; Als = g_MI1l + mt*128*272;
    Bhs = g_Zh + (long)b*276*272; Bls = g_Zl + (long)b*276*272;
  } else {
    z = blockIdx.x;
    Ahs = g_UAh + (long)z*128*144; Als = g_UAl + (long)z*128*144;
    Bhs = g_MI2h; Bls = g_MI2l;
  }

  auto issue = [&](int t, int buf){
    const int kk = t*KC;
    char* base = smraw + buf*BUFB;
    #pragma unroll
    for (int it = 0; it < 4; it++){
      int cid = tid + it*256;
      int hl = cid >> 9, rem = cid & 511;
      int row = rem >> 2, c16 = rem & 3;
      int gk = kk + c16*8;
      int sz = (gk + 8 <= K) ? 16 : 0;
      const __nv_bfloat16* src = (hl ? Als : Ahs) + (long)row*K + (sz ? gk : 0);
      uint32_t dst = smem_u32(base + (hl ? OAL : OAH) + row*SAB + c16*16);
      asm volatile("cp.async.ca.shared.global [%0], [%1], 16, %2;"
                   :: "r"(dst), "l"(src), "r"(sz));
    }
    constexpr int BCH = BN*8;
    #pragma unroll
    for (int it = 0; it < BCH/256; it++){
      int cid = tid + it*256;
      int hl = (cid >= BCH/2), rem = cid % (BCH/2);
      int row = rem >> 2, c16 = rem & 3;
      int gk = kk + c16*8;
      int grow = row;
      int sz = (gk + 8 <= K) ? 16 : 0;
      if constexpr (STAGE==1){
        grow = n0 + row;
        if (grow >= 144){ grow = 143; sz = 0; }
      }
      if constexpr (STAGE==2){
        grow = n0 + row;
        if (grow >= 276){ grow = 275; sz = 0; }
      }
      const __nv_bfloat16* src = (hl ? Bls : Bhs) + (long)grow*K + (sz ? gk : 0);
      uint32_t dst = smem_u32(base + (hl ? OBL : OBH) + row*SAB + c16*16);
      asm volatile("cp.async.ca.shared.global [%0], [%1], 16, %2;"
                   :: "r"(dst), "l"(src), "r"(sz));
    }
    asm volatile("cp.async.commit_group;" ::: "memory");
  };

  float acc[4][NT4][4];
  #pragma unroll
  for (int i = 0; i < 4; i++)
    #pragma unroll
    for (int j = 0; j < NT4; j++)
      #pragma unroll
      for (int q = 0; q < 4; q++) acc[i][j][q] = 0.f;

  issue(0, 0);

  #pragma unroll 1
  for (int t = 0; t < NCH; t++){
    const int buf = t & 1;
    if (t + 1 < NCH){
      issue(t + 1, buf ^ 1);
      asm volatile("cp.async.wait_group 1;" ::: "memory");
    } else {
      asm volatile("cp.async.wait_group 0;" ::: "memory");
    }
    __syncthreads();

    char* base = smraw + buf*BUFB;
    const int nsub = (K - t*KC >= KC) ? 2 : 1;
    #pragma unroll
    for (int sub = 0; sub < 2; sub++){
      if (sub >= nsub) break;
      const int tk = sub*16;
      uint32_t afh[4][4], afl[4][4];
      #pragma unroll
      for (int i = 0; i < 4; i++){
        int row = wm*64 + i*16 + (lane & 15);
        int col = tk + (lane >> 4)*8;
        ldsm_x4(afh[i][0], afh[i][1], afh[i][2], afh[i][3],
                smem_u32(base + OAH + row*SAB + col*2));
        ldsm_x4(afl[i][0], afl[i][1], afl[i][2], afl[i][3],
                smem_u32(base + OAL + row*SAB + col*2));
      }
      uint32_t bfh[NT4][2], bfl[NT4][2];
      if constexpr (NT4 == 4){
        #pragma unroll
        for (int j0 = 0; j0 < 4; j0 += 2){
          int q = lane >> 3;
          int row = wn*WN + (j0 + (q >> 1))*8 + (lane & 7);
          int col = tk + (q & 1)*8;
          ldsm_x4(bfh[j0][0], bfh[j0][1], bfh[j0+1][0], bfh[j0+1][1],
                  smem_u32(base + OBH + row*SAB + col*2));
          ldsm_x4(bfl[j0][0], bfl[j0][1], bfl[j0+1][0], bfl[j0+1][1],
                  smem_u32(base + OBL + row*SAB + col*2));
        }
      } else {
        {
          int q = lane >> 3;
          int row = wn*WN + (q >> 1)*8 + (lane & 7);
          int col = tk + (q & 1)*8;
          ldsm_x4(bfh[0][0], bfh[0][1], bfh[1][0], bfh[1][1],
                  smem_u32(base + OBH + row*SAB + col*2));
          ldsm_x4(bfl[0][0], bfl[0][1], bfl[1][0], bfl[1][1],
                  smem_u32(base + OBL + row*SAB + col*2));
        }
        {
          int l15 = lane & 15;
          int row = wn*WN + 16 + (l15 & 7);
          int col = tk + (l15 >> 3)*8;
          ldsm_x2(bfh[2][0], bfh[2][1], smem_u32(base + OBH + row*SAB + col*2));
          ldsm_x2(bfl[2][0], bfl[2][1], smem_u32(base + OBL + row*SAB + col*2));
        }
      }
      #pragma unroll
      for (int i = 0; i < 4; i++)
        #pragma unroll
        for (int j = 0; j < NT4; j++){
          mma_bf16(acc[i][j], afh[i], bfh[j]);
          mma_bf16(acc[i][j], afh[i], bfl[j]);
          mma_bf16(acc[i][j], afl[i], bfh[j]);
        }
    }
    __syncthreads();
  }

  // ---- coalesced epilogue via SMEM staging
  float* S = reinterpret_cast<float*>(smraw);
  const int g = lane >> 2, tig = lane & 3;
  constexpr int CG = (STAGE==3) ? 64 : 48;
  constexpr int NP = BN / CG;

  #pragma unroll 1
  for (int p = 0; p < NP; p++){
    if ((wn >> 1) == p){
      #pragma unroll
      for (int i = 0; i < 4; i++)
        #pragma unroll
        for (int j = 0; j < NT4; j++)
          #pragma unroll
          for (int h = 0; h < 2; h++)
            #pragma unroll
            for (int e = 0; e < 2; e++){
              int row = wm*64 + i*16 + g + h*8;
              int lc  = (wn & 1)*WN + j*8 + tig*2 + e;
              S[lc*129 + row] = acc[i][j][h*2 + e];
            }
    }
    __syncthreads();
    for (int idx = tid; idx < CG*128; idx += 256){
      if constexpr (STAGE==1){
        int m = idx & 127, cc = idx >> 7;     // m-fast: coalesced g_Yt stores
        int gn = n0 + p*CG + cc;
        if (gn < 138){
          int gmm = mt*128 + m;
          int bb = gmm / 136, uu = gmm - bb*136;
          g_Yt[((long)bb*138 + gn)*136 + uu] = S[cc*129 + m];
        }
      } else {
        int m = idx / CG, cc = idx % CG;
        float val = S[cc*129 + m];
        if constexpr (STAGE==2){
          int gc = n0 + p*CG + cc;
          if (gc < 276){
            int r = gc/69, v = gc - r*69;
            long dst = (long)((b*4 + r)*128 + m)*144 + mt*72 + v;
            split_bf(val, g_UAh[dst], g_UAl[dst]);
          }
        } else {
          int rr = z & 3, bb = z >> 2;
          int gc = p*CG + cc;
          outp[(long)bb*65536 + (2*m + (rr >> 1))*256 + 2*gc + (rr & 1)] = val;
        }
      }
    }
    __syncthreads();
  }
}

// ===================== launch ===============================================
extern "C" void kernel_launch(void* const* d_in, const int* in_sizes, int n_in,
                              void* d_out, int out_size)
{
  const float* x = (const float*)d_in[0];
  const float* w = (const float*)(n_in > 1 ? d_in[1] : d_in[0]);
  const float* bias = (const float*)(n_in > 2 ? d_in[2] : d_in[0]);
  for (int i = 0; i < n_in; i++){
    if (in_sizes[i] == 4*64*128*128) x = (const float*)d_in[i];
    else if (in_sizes[i] == 64*25)   w = (const float*)d_in[i];
    else if (in_sizes[i] == 64)      bias = (const float*)d_in[i];
  }
  float* out = (float*)d_out;

  constexpr int SM96  = 2*(2*128*80 + 2*96*80);    // 71680 (stages 1,2)
  constexpr int SM128 = 2*(2*128*80 + 2*128*80);   // 81920 (stage 3)
  cudaFuncSetAttribute(mma_k<1>, cudaFuncAttributeMaxDynamicSharedMemorySize, SM96);
  cudaFuncSetAttribute(mma_k<2>, cudaFuncAttributeMaxDynamicSharedMemorySize, SM96);
  cudaFuncSetAttribute(mma_k<3>, cudaFuncAttributeMaxDynamicSharedMemorySize, SM128);

  k_build<<<(160016+255)/256, 256>>>();            // #1
  k_H   <<<(64*136*69+255)/256, 256>>>(w, bias);   // #2
  gemm0_k<<<dim3(1,3,256), 256>>>(x);              // #3: Tsp (split bf16)
  mma_k<1><<<dim3(2,272,1), 256, SM96>>>(out);     // #4: Yt = Tsp * MB2t^T
  k_Z   <<<dim3(69,256), 160>>>();                 // #5: Z = Y .* H
  mma_k<2><<<dim3(3,2,256), 256, SM96>>>(out);     // #6: U -> g_UA (profiled)
  mma_k<3><<<dim3(1024,1,1), 256, SM128>>>(out);   // #7: out
}